// round 12
// baseline (speedup 1.0000x reference)
#include <cuda_runtime.h>
#include <math_constants.h>

#define NN 30000
#define EE 480000
#define ET (EE + NN)
#define BB 64
#define FIN 128
#define HID 64
#define ED 32
#define C1 256
#define NEG 0.2f
#define EPS 1e-5f

typedef unsigned long long ull;

// ------------------- scratch -------------------------------------------------
__device__ int      d_deg[NN];          // real in-degree
__device__ int      d_rowptr[NN + 1];
__device__ int      d_cursor[NN];
__device__ int      d_esrc[ET];

__device__ float    d_vs1[512];
__device__ float    d_vd1[512];
__device__ float    d_c1[ED * 4];
__device__ float    d_c2[ED];
__device__ float    d_als1[NN * 4];
__device__ float    d_ald1[NN * 4];
__device__ float    d_ecsum[NN * 4];    // per-dst sums of ea.c1
__device__ float    d_ec2sum[NN];
__device__ float    d_ec2[ET];          // CSR order, ea.c2 (real slots only)
__device__ float    d_alpha1[(size_t)ET * 4];   // CSR order (real slots only)
__device__ float    d_tmp[(size_t)NN * 512];
__device__ float    d_out1[(size_t)NN * C1];
__device__ float    d_colsum1[C1];
__device__ float    d_colsq1[C1];
__device__ float    d_xs2[(size_t)NN * HID];
__device__ float    d_als2[NN];
__device__ float    d_ald2[NN];
__device__ float    d_out2[(size_t)NN * HID];
__device__ float    d_colsum2[HID];
__device__ float    d_colsq2[HID];
__device__ float    d_gate[NN];

// ------------------- helpers -------------------------------------------------
__device__ __forceinline__ ull pack2(float lo, float hi) {
    ull r;
    asm("mov.b64 %0, {%1, %2};" : "=l"(r) : "f"(lo), "f"(hi));
    return r;
}
__device__ __forceinline__ void unpack2(ull v, float& lo, float& hi) {
    asm("mov.b64 {%0, %1}, %2;" : "=f"(lo), "=f"(hi) : "l"(v));
}
__device__ __forceinline__ void fma2(ull& acc, ull a, ull b) {
    asm("fma.rn.f32x2 %0, %1, %2, %0;" : "+l"(acc) : "l"(a), "l"(b));
}
__device__ __forceinline__ float lrelu(float a) { return a > 0.f ? a : NEG * a; }

// ------------------- init ------------------------------------------------------
__global__ void init0() {
    int i = blockIdx.x * blockDim.x + threadIdx.x;
    if (i < NN) d_deg[i] = 0;
}

// ------------------- CSR build --------------------------------------------------
__global__ void hist_kernel(const int* __restrict__ dst) {
    int e = blockIdx.x * blockDim.x + threadIdx.x;
    if (e < EE) atomicAdd(&d_deg[dst[e]], 1);
}

__global__ void scan_kernel() {
    __shared__ int wsum[32];
    const int PER = 30;
    int t = threadIdx.x;
    if (t < C1) { d_colsum1[t] = 0.f; d_colsq1[t] = 0.f; }
    if (t < HID) { d_colsum2[t] = 0.f; d_colsq2[t] = 0.f; }
    int base = t * PER;
    int vals[PER];
    int s = 0;
#pragma unroll
    for (int i = 0; i < PER; i++) {
        int idx = base + i;
        vals[i] = (idx < NN) ? (d_deg[idx] + 1) : 0;   // +1 self loop (last slot)
        if (idx < NN) {
            d_cursor[idx] = 0;
            d_ec2sum[idx] = 0.f;
            ((float4*)d_ecsum)[idx] = make_float4(0.f, 0.f, 0.f, 0.f);
        }
        s += vals[i];
    }
    int lane = t & 31, w = t >> 5;
    int x = s;
#pragma unroll
    for (int off = 1; off < 32; off <<= 1) {
        int y = __shfl_up_sync(0xFFFFFFFFu, x, off);
        if (lane >= off) x += y;
    }
    if (lane == 31) wsum[w] = x;
    __syncthreads();
    if (w == 0) {
        int y = wsum[lane];
#pragma unroll
        for (int off = 1; off < 32; off <<= 1) {
            int z = __shfl_up_sync(0xFFFFFFFFu, y, off);
            if (lane >= off) y += z;
        }
        wsum[lane] = y;
    }
    __syncthreads();
    int excl = x - s + (w > 0 ? wsum[w - 1] : 0);
    int run = excl;
#pragma unroll
    for (int i = 0; i < PER; i++) {
        int idx = base + i;
        if (idx < NN) d_rowptr[idx] = run;
        run += vals[i];
    }
    if (t == 0) d_rowptr[NN] = ET;
}

// -------------- precompute small vectors (warp per output; 672 warps) ---------------
__global__ void __launch_bounds__(256) prep_par(
    const float* __restrict__ W1, const float* __restrict__ as1,
    const float* __restrict__ ad1,
    const float* __restrict__ We1, const float* __restrict__ ae1,
    const float* __restrict__ We2, const float* __restrict__ ae2) {
    int gw = blockIdx.x * 8 + (threadIdx.x >> 5);   // global warp id
    int lane = threadIdx.x & 31;
    if (gw < 512) {
        // vs1/vd1[gw]: dot(W1[k, h*64: h*64+64], as1/ad1[h])
        int h = gw >> 7, k = gw & 127;
        const float* wrow = W1 + (size_t)k * C1 + h * HID;
        const float* arow = as1 + h * HID;
        const float* drow = ad1 + h * HID;
        float w0 = wrow[lane], w1 = wrow[lane + 32];
        float s = w0 * arow[lane] + w1 * arow[lane + 32];
        float dv = w0 * drow[lane] + w1 * drow[lane + 32];
#pragma unroll
        for (int off = 16; off >= 1; off >>= 1) {
            s += __shfl_xor_sync(0xFFFFFFFFu, s, off);
            dv += __shfl_xor_sync(0xFFFFFFFFu, dv, off);
        }
        if (lane == 0) { d_vs1[gw] = s; d_vd1[gw] = dv; }
    } else if (gw < 640) {
        int idx = gw - 512;           // c1 index: k*4+h
        int k = idx >> 2, h = idx & 3;
        const float* wrow = We1 + (size_t)k * C1 + h * HID;
        const float* arow = ae1 + h * HID;
        float s = wrow[lane] * arow[lane] + wrow[lane + 32] * arow[lane + 32];
#pragma unroll
        for (int off = 16; off >= 1; off >>= 1)
            s += __shfl_xor_sync(0xFFFFFFFFu, s, off);
        if (lane == 0) d_c1[idx] = s;
    } else if (gw < 672) {
        int k = gw - 640;             // c2 index
        const float* wrow = We2 + (size_t)k * HID;
        float s = wrow[lane] * ae2[lane] + wrow[lane + 32] * ae2[lane + 32];
#pragma unroll
        for (int off = 16; off >= 1; off >>= 1)
            s += __shfl_xor_sync(0xFFFFFFFFu, s, off);
        if (lane == 0) d_c2[k] = s;
    }
}

// ------------------- node logits (layer 1) ---------------------------------------
__global__ void logits1(const float* __restrict__ x) {
    int gw = (blockIdx.x * blockDim.x + threadIdx.x) >> 5;
    int lane = threadIdx.x & 31;
    if (gw >= NN) return;
    float4 xv = ((const float4*)x)[(size_t)gw * 32 + lane];
    float r0, r1, r2, r3, q0, q1, q2, q3;
    {
        float4 v;
        v = ((const float4*)d_vs1)[0 * 32 + lane]; r0 = xv.x*v.x + xv.y*v.y + xv.z*v.z + xv.w*v.w;
        v = ((const float4*)d_vs1)[1 * 32 + lane]; r1 = xv.x*v.x + xv.y*v.y + xv.z*v.z + xv.w*v.w;
        v = ((const float4*)d_vs1)[2 * 32 + lane]; r2 = xv.x*v.x + xv.y*v.y + xv.z*v.z + xv.w*v.w;
        v = ((const float4*)d_vs1)[3 * 32 + lane]; r3 = xv.x*v.x + xv.y*v.y + xv.z*v.z + xv.w*v.w;
        v = ((const float4*)d_vd1)[0 * 32 + lane]; q0 = xv.x*v.x + xv.y*v.y + xv.z*v.z + xv.w*v.w;
        v = ((const float4*)d_vd1)[1 * 32 + lane]; q1 = xv.x*v.x + xv.y*v.y + xv.z*v.z + xv.w*v.w;
        v = ((const float4*)d_vd1)[2 * 32 + lane]; q2 = xv.x*v.x + xv.y*v.y + xv.z*v.z + xv.w*v.w;
        v = ((const float4*)d_vd1)[3 * 32 + lane]; q3 = xv.x*v.x + xv.y*v.y + xv.z*v.z + xv.w*v.w;
    }
#pragma unroll
    for (int off = 16; off >= 1; off >>= 1) {
        r0 += __shfl_xor_sync(0xFFFFFFFFu, r0, off);
        r1 += __shfl_xor_sync(0xFFFFFFFFu, r1, off);
        r2 += __shfl_xor_sync(0xFFFFFFFFu, r2, off);
        r3 += __shfl_xor_sync(0xFFFFFFFFu, r3, off);
        q0 += __shfl_xor_sync(0xFFFFFFFFu, q0, off);
        q1 += __shfl_xor_sync(0xFFFFFFFFu, q1, off);
        q2 += __shfl_xor_sync(0xFFFFFFFFu, q2, off);
        q3 += __shfl_xor_sync(0xFFFFFFFFu, q3, off);
    }
    if (lane == 0) {
        d_als1[gw * 4 + 0] = r0; d_als1[gw * 4 + 1] = r1;
        d_als1[gw * 4 + 2] = r2; d_als1[gw * 4 + 3] = r3;
        d_ald1[gw * 4 + 0] = q0; d_ald1[gw * 4 + 1] = q1;
        d_ald1[gw * 4 + 2] = q2; d_ald1[gw * 4 + 3] = q3;
    }
}

// --------- edge alphas: CSR slot assignment + alpha + ec sums in ONE pass -----------
__global__ void edge_alpha1(const float* __restrict__ ea, const int* __restrict__ src,
                            const int* __restrict__ dst) {
    int e = blockIdx.x * blockDim.x + threadIdx.x;
    if (e >= EE) return;
    int s = src[e], d = dst[e];
    const float4* row = (const float4*)(ea + (size_t)e * ED);
    float ec0 = 0.f, ec1 = 0.f, ec2 = 0.f, ec3 = 0.f, e2 = 0.f;
#pragma unroll
    for (int q = 0; q < 8; q++) {
        float4 v = __ldg(row + q);
        int k = q * 4;
        ec0 += v.x * d_c1[(k+0)*4+0] + v.y * d_c1[(k+1)*4+0] + v.z * d_c1[(k+2)*4+0] + v.w * d_c1[(k+3)*4+0];
        ec1 += v.x * d_c1[(k+0)*4+1] + v.y * d_c1[(k+1)*4+1] + v.z * d_c1[(k+2)*4+1] + v.w * d_c1[(k+3)*4+1];
        ec2 += v.x * d_c1[(k+0)*4+2] + v.y * d_c1[(k+1)*4+2] + v.z * d_c1[(k+2)*4+2] + v.w * d_c1[(k+3)*4+2];
        ec3 += v.x * d_c1[(k+0)*4+3] + v.y * d_c1[(k+1)*4+3] + v.z * d_c1[(k+2)*4+3] + v.w * d_c1[(k+3)*4+3];
        e2  += v.x * d_c2[k+0] + v.y * d_c2[k+1] + v.z * d_c2[k+2] + v.w * d_c2[k+3];
    }
    int p = d_rowptr[d] + atomicAdd(&d_cursor[d], 1);
    d_esrc[p] = s;
    d_ec2[p] = e2;
    float4 a;
    a.x = lrelu(d_als1[s * 4 + 0] + d_ald1[d * 4 + 0] + ec0);
    a.y = lrelu(d_als1[s * 4 + 1] + d_ald1[d * 4 + 1] + ec1);
    a.z = lrelu(d_als1[s * 4 + 2] + d_ald1[d * 4 + 2] + ec2);
    a.w = lrelu(d_als1[s * 4 + 3] + d_ald1[d * 4 + 3] + ec3);
    *(float4*)&d_alpha1[(size_t)p * 4] = a;
    atomicAdd(&d_ecsum[d * 4 + 0], ec0);
    atomicAdd(&d_ecsum[d * 4 + 1], ec1);
    atomicAdd(&d_ecsum[d * 4 + 2], ec2);
    atomicAdd(&d_ecsum[d * 4 + 3], ec3);
    atomicAdd(&d_ec2sum[d], e2);
}

// ------------------- gather layer1: warp per node, self-loop inline -------------------
__global__ void __launch_bounds__(256) gather1w(const float* __restrict__ x) {
    int wid = threadIdx.x >> 5, lane = threadIdx.x & 31;
    int d = blockIdx.x * 8 + wid;   // NN % 8 == 0
    int r0 = d_rowptr[d], r1 = d_rowptr[d + 1];
    int LR = r1 - 1 - r0;           // real edges; slot r1-1 is self
    __shared__ __align__(16) float4 sex[8][32];
    __shared__ int ssrc[8][32];

    float inv = 1.0f / (float)(LR > 1 ? LR : 1);
    float4 selfa;
    selfa.x = lrelu(d_als1[d * 4 + 0] + d_ald1[d * 4 + 0] + d_ecsum[d * 4 + 0] * inv);
    selfa.y = lrelu(d_als1[d * 4 + 1] + d_ald1[d * 4 + 1] + d_ecsum[d * 4 + 1] * inv);
    selfa.z = lrelu(d_als1[d * 4 + 2] + d_ald1[d * 4 + 2] + d_ecsum[d * 4 + 2] * inv);
    selfa.w = lrelu(d_als1[d * 4 + 3] + d_ald1[d * 4 + 3] + d_ecsum[d * 4 + 3] * inv);

    // max per head (self included)
    float4 mx = selfa;
    for (int idx = lane; idx < LR; idx += 32) {
        float4 a = *(const float4*)&d_alpha1[(size_t)(r0 + idx) * 4];
        mx.x = fmaxf(mx.x, a.x); mx.y = fmaxf(mx.y, a.y);
        mx.z = fmaxf(mx.z, a.z); mx.w = fmaxf(mx.w, a.w);
    }
#pragma unroll
    for (int off = 16; off >= 1; off >>= 1) {
        mx.x = fmaxf(mx.x, __shfl_xor_sync(0xFFFFFFFFu, mx.x, off));
        mx.y = fmaxf(mx.y, __shfl_xor_sync(0xFFFFFFFFu, mx.y, off));
        mx.z = fmaxf(mx.z, __shfl_xor_sync(0xFFFFFFFFu, mx.z, off));
        mx.w = fmaxf(mx.w, __shfl_xor_sync(0xFFFFFFFFu, mx.w, off));
    }

    float4 a0 = make_float4(0, 0, 0, 0), a1 = a0, a2 = a0, a3 = a0;
    float4 lsum = make_float4(0, 0, 0, 0);
    const float4* x4 = (const float4*)x;
    for (int c0 = r0; c0 < r0 + LR; c0 += 32) {
        int m = min(32, r0 + LR - c0);
        __syncwarp();
        if (lane < m) {
            float4 a = *(const float4*)&d_alpha1[(size_t)(c0 + lane) * 4];
            float4 e;
            e.x = __expf(a.x - mx.x); e.y = __expf(a.y - mx.y);
            e.z = __expf(a.z - mx.z); e.w = __expf(a.w - mx.w);
            sex[wid][lane] = e;
            ssrc[wid][lane] = d_esrc[c0 + lane];
            lsum.x += e.x; lsum.y += e.y; lsum.z += e.z; lsum.w += e.w;
        }
        __syncwarp();
        for (int j = 0; j < m; j++) {
            float4 xv = x4[(size_t)ssrc[wid][j] * 32 + lane];
            float4 e = sex[wid][j];
            a0.x += e.x * xv.x; a0.y += e.x * xv.y; a0.z += e.x * xv.z; a0.w += e.x * xv.w;
            a1.x += e.y * xv.x; a1.y += e.y * xv.y; a1.z += e.y * xv.z; a1.w += e.y * xv.w;
            a2.x += e.z * xv.x; a2.y += e.z * xv.y; a2.z += e.z * xv.z; a2.w += e.z * xv.w;
            a3.x += e.w * xv.x; a3.y += e.w * xv.y; a3.z += e.w * xv.z; a3.w += e.w * xv.w;
        }
    }
    // self-loop contribution
    float4 es;
    es.x = __expf(selfa.x - mx.x); es.y = __expf(selfa.y - mx.y);
    es.z = __expf(selfa.z - mx.z); es.w = __expf(selfa.w - mx.w);
    {
        float4 xv = x4[(size_t)d * 32 + lane];
        a0.x += es.x * xv.x; a0.y += es.x * xv.y; a0.z += es.x * xv.z; a0.w += es.x * xv.w;
        a1.x += es.y * xv.x; a1.y += es.y * xv.y; a1.z += es.y * xv.z; a1.w += es.y * xv.w;
        a2.x += es.z * xv.x; a2.y += es.z * xv.y; a2.z += es.z * xv.z; a2.w += es.z * xv.w;
        a3.x += es.w * xv.x; a3.y += es.w * xv.y; a3.z += es.w * xv.z; a3.w += es.w * xv.w;
    }
#pragma unroll
    for (int off = 16; off >= 1; off >>= 1) {
        lsum.x += __shfl_xor_sync(0xFFFFFFFFu, lsum.x, off);
        lsum.y += __shfl_xor_sync(0xFFFFFFFFu, lsum.y, off);
        lsum.z += __shfl_xor_sync(0xFFFFFFFFu, lsum.z, off);
        lsum.w += __shfl_xor_sync(0xFFFFFFFFu, lsum.w, off);
    }
    lsum.x += es.x; lsum.y += es.y; lsum.z += es.z; lsum.w += es.w;
    float i0 = 1.0f / lsum.x, i1 = 1.0f / lsum.y, i2 = 1.0f / lsum.z, i3 = 1.0f / lsum.w;
    float4* tmp4 = (float4*)&d_tmp[(size_t)d * 512];
    tmp4[0 * 32 + lane] = make_float4(a0.x * i0, a0.y * i0, a0.z * i0, a0.w * i0);
    tmp4[1 * 32 + lane] = make_float4(a1.x * i1, a1.y * i1, a1.z * i1, a1.w * i1);
    tmp4[2 * 32 + lane] = make_float4(a2.x * i2, a2.y * i2, a2.z * i2, a2.w * i2);
    tmp4[3 * 32 + lane] = make_float4(a3.x * i3, a3.y * i3, a3.z * i3, a3.w * i3);
}

// ------------------- GEMM1: out1 = tmp(heads) @ W1 + b1, fused BN stats -------------
__global__ void __launch_bounds__(256) gemm1_stats(
    const float* __restrict__ A, const float* __restrict__ B,
    float* __restrict__ C, const float* __restrict__ bias) {
    const int BK = 16;
    __shared__ __align__(16) float As[BK][128 + 4];
    __shared__ __align__(16) float Bs[BK][64];
    __shared__ float reds[16][64];
    __shared__ float redq[16][64];
    int tid = threadIdx.x;
    int tx = tid & 15, ty = tid >> 4;
    int m0 = blockIdx.y * 128;
    const float* Ab = A + (size_t)blockIdx.x * 128;
    int bcol = blockIdx.x * 64;

    ull acc[4][4];
#pragma unroll
    for (int i = 0; i < 4; i++)
#pragma unroll
        for (int j = 0; j < 4; j++) acc[i][j] = 0ull;

    int ar = tid >> 1;
    int akb = (tid & 1) * 8;
    int gr_a = m0 + ar;
    int br = tid >> 4;
    int bc = (tid & 15) * 4;

    for (int k0 = 0; k0 < FIN; k0 += BK) {
        float4 a4a, a4b;
        if (gr_a < NN) {
            a4a = *(const float4*)&Ab[(size_t)gr_a * 512 + k0 + akb];
            a4b = *(const float4*)&Ab[(size_t)gr_a * 512 + k0 + akb + 4];
        } else {
            a4a = make_float4(0.f, 0.f, 0.f, 0.f);
            a4b = a4a;
        }
        As[akb + 0][ar] = a4a.x; As[akb + 1][ar] = a4a.y;
        As[akb + 2][ar] = a4a.z; As[akb + 3][ar] = a4a.w;
        As[akb + 4][ar] = a4b.x; As[akb + 5][ar] = a4b.y;
        As[akb + 6][ar] = a4b.z; As[akb + 7][ar] = a4b.w;
        *(float4*)&Bs[br][bc] = *(const float4*)&B[(size_t)(k0 + br) * C1 + bcol + bc];
        __syncthreads();
#pragma unroll
        for (int kk = 0; kk < BK; kk++) {
            ulonglong2 ap01 = *(const ulonglong2*)&As[kk][ty * 8];
            ulonglong2 ap23 = *(const ulonglong2*)&As[kk][ty * 8 + 4];
            float4 bq = *(const float4*)&Bs[kk][tx * 4];
            ull bb0 = pack2(bq.x, bq.x);
            ull bb1 = pack2(bq.y, bq.y);
            ull bb2 = pack2(bq.z, bq.z);
            ull bb3 = pack2(bq.w, bq.w);
            ull ap[4] = {ap01.x, ap01.y, ap23.x, ap23.y};
#pragma unroll
            for (int i = 0; i < 4; i++) {
                fma2(acc[i][0], ap[i], bb0);
                fma2(acc[i][1], ap[i], bb1);
                fma2(acc[i][2], ap[i], bb2);
                fma2(acc[i][3], ap[i], bb3);
            }
        }
        __syncthreads();
    }
    float4 bv = *(const float4*)&bias[bcol + tx * 4];
    float psum[4] = {0.f, 0.f, 0.f, 0.f};
    float psq[4]  = {0.f, 0.f, 0.f, 0.f};
#pragma unroll
    for (int i = 0; i < 4; i++) {
        float lo0, hi0, lo1, hi1, lo2, hi2, lo3, hi3;
        unpack2(acc[i][0], lo0, hi0);
        unpack2(acc[i][1], lo1, hi1);
        unpack2(acc[i][2], lo2, hi2);
        unpack2(acc[i][3], lo3, hi3);
        int r0 = m0 + ty * 8 + 2 * i;
        float y0 = lo0 + bv.x, y1 = lo1 + bv.y, y2 = lo2 + bv.z, y3 = lo3 + bv.w;
        float z0 = hi0 + bv.x, z1 = hi1 + bv.y, z2 = hi2 + bv.z, z3 = hi3 + bv.w;
        if (r0 < NN) {
            *(float4*)&C[(size_t)r0 * C1 + bcol + tx * 4] = make_float4(y0, y1, y2, y3);
            psum[0] += y0; psum[1] += y1; psum[2] += y2; psum[3] += y3;
            psq[0] += y0 * y0; psq[1] += y1 * y1; psq[2] += y2 * y2; psq[3] += y3 * y3;
        }
        if (r0 + 1 < NN) {
            *(float4*)&C[(size_t)(r0 + 1) * C1 + bcol + tx * 4] = make_float4(z0, z1, z2, z3);
            psum[0] += z0; psum[1] += z1; psum[2] += z2; psum[3] += z3;
            psq[0] += z0 * z0; psq[1] += z1 * z1; psq[2] += z2 * z2; psq[3] += z3 * z3;
        }
    }
#pragma unroll
    for (int c = 0; c < 4; c++) {
        reds[ty][tx * 4 + c] = psum[c];
        redq[ty][tx * 4 + c] = psq[c];
    }
    __syncthreads();
    if (tid < 64) {
        float s = 0.f, q = 0.f;
#pragma unroll
        for (int i = 0; i < 16; i++) { s += reds[i][tid]; q += redq[i][tid]; }
        atomicAdd(&d_colsum1[bcol + tid], s);
        atomicAdd(&d_colsq1[bcol + tid], q);
    }
}

// ------------------- GEMM2: xs2 = BNReLU(out1) @ W2, fused logits2 ------------------
__global__ void __launch_bounds__(256) gemm2_fused(
    const float* __restrict__ A, const float* __restrict__ B,
    float* __restrict__ C, const float* __restrict__ g1bn,
    const float* __restrict__ b1bn, const float* __restrict__ as2,
    const float* __restrict__ ad2) {
    const int BK = 16;
    __shared__ __align__(16) float As[BK][128 + 4];
    __shared__ __align__(16) float Bs[BK][64];
    __shared__ float sc[C1];
    __shared__ float sf[C1];
    int tid = threadIdx.x;
    int tx = tid & 15, ty = tid >> 4;
    int m0 = blockIdx.y * 128;

    {
        float mu = d_colsum1[tid] / (float)NN;
        float var = d_colsq1[tid] / (float)NN - mu * mu;
        float rs = rsqrtf(var + EPS) * g1bn[tid];
        sc[tid] = rs;
        sf[tid] = b1bn[tid] - mu * rs;
    }
    __syncthreads();

    ull acc[4][4];
#pragma unroll
    for (int i = 0; i < 4; i++)
#pragma unroll
        for (int j = 0; j < 4; j++) acc[i][j] = 0ull;

    int ar = tid >> 1;
    int akb = (tid & 1) * 8;
    int gr_a = m0 + ar;
    int br = tid >> 4;
    int bc = (tid & 15) * 4;

    for (int k0 = 0; k0 < C1; k0 += BK) {
        float4 a4a, a4b;
        if (gr_a < NN) {
            a4a = *(const float4*)&A[(size_t)gr_a * C1 + k0 + akb];
            a4b = *(const float4*)&A[(size_t)gr_a * C1 + k0 + akb + 4];
        } else {
            a4a = make_float4(0.f, 0.f, 0.f, 0.f);
            a4b = a4a;
        }
        int kb = k0 + akb;
        As[akb + 0][ar] = fmaxf(fmaf(a4a.x, sc[kb + 0], sf[kb + 0]), 0.f);
        As[akb + 1][ar] = fmaxf(fmaf(a4a.y, sc[kb + 1], sf[kb + 1]), 0.f);
        As[akb + 2][ar] = fmaxf(fmaf(a4a.z, sc[kb + 2], sf[kb + 2]), 0.f);
        As[akb + 3][ar] = fmaxf(fmaf(a4a.w, sc[kb + 3], sf[kb + 3]), 0.f);
        As[akb + 4][ar] = fmaxf(fmaf(a4b.x, sc[kb + 4], sf[kb + 4]), 0.f);
        As[akb + 5][ar] = fmaxf(fmaf(a4b.y, sc[kb + 5], sf[kb + 5]), 0.f);
        As[akb + 6][ar] = fmaxf(fmaf(a4b.z, sc[kb + 6], sf[kb + 6]), 0.f);
        As[akb + 7][ar] = fmaxf(fmaf(a4b.w, sc[kb + 7], sf[kb + 7]), 0.f);
        *(float4*)&Bs[br][bc] = *(const float4*)&B[(size_t)(k0 + br) * HID + bc];
        __syncthreads();
#pragma unroll
        for (int kk = 0; kk < BK; kk++) {
            ulonglong2 ap01 = *(const ulonglong2*)&As[kk][ty * 8];
            ulonglong2 ap23 = *(const ulonglong2*)&As[kk][ty * 8 + 4];
            float4 bq = *(const float4*)&Bs[kk][tx * 4];
            ull bb0 = pack2(bq.x, bq.x);
            ull bb1 = pack2(bq.y, bq.y);
            ull bb2 = pack2(bq.z, bq.z);
            ull bb3 = pack2(bq.w, bq.w);
            ull ap[4] = {ap01.x, ap01.y, ap23.x, ap23.y};
#pragma unroll
            for (int i = 0; i < 4; i++) {
                fma2(acc[i][0], ap[i], bb0);
                fma2(acc[i][1], ap[i], bb1);
                fma2(acc[i][2], ap[i], bb2);
                fma2(acc[i][3], ap[i], bb3);
            }
        }
        __syncthreads();
    }
    float4 av = *(const float4*)&as2[tx * 4];
    float4 dv = *(const float4*)&ad2[tx * 4];
    float ps8[8], pd8[8];
#pragma unroll
    for (int i = 0; i < 4; i++) {
        float lo0, hi0, lo1, hi1, lo2, hi2, lo3, hi3;
        unpack2(acc[i][0], lo0, hi0);
        unpack2(acc[i][1], lo1, hi1);
        unpack2(acc[i][2], lo2, hi2);
        unpack2(acc[i][3], lo3, hi3);
        int r0 = m0 + ty * 8 + 2 * i;
        if (r0 < NN)
            *(float4*)&C[(size_t)r0 * HID + tx * 4] = make_float4(lo0, lo1, lo2, lo3);
        if (r0 + 1 < NN)
            *(float4*)&C[(size_t)(r0 + 1) * HID + tx * 4] = make_float4(hi0, hi1, hi2, hi3);
        ps8[2 * i]     = lo0 * av.x + lo1 * av.y + lo2 * av.z + lo3 * av.w;
        ps8[2 * i + 1] = hi0 * av.x + hi1 * av.y + hi2 * av.z + hi3 * av.w;
        pd8[2 * i]     = lo0 * dv.x + lo1 * dv.y + lo2 * dv.z + lo3 * dv.w;
        pd8[2 * i + 1] = hi0 * dv.x + hi1 * dv.y + hi2 * dv.z + hi3 * dv.w;
    }
    float* red = &As[0][0];
    __syncthreads();
#pragma unroll
    for (int i = 0; i < 8; i++) red[(ty * 8 + i) * 16 + tx] = ps8[i];
    __syncthreads();
    if (tid < 128 && m0 + tid < NN) {
        float s = 0.f;
#pragma unroll
        for (int j = 0; j < 16; j++) s += red[tid * 16 + j];
        d_als2[m0 + tid] = s;
    }
    __syncthreads();
#pragma unroll
    for (int i = 0; i < 8; i++) red[(ty * 8 + i) * 16 + tx] = pd8[i];
    __syncthreads();
    if (tid < 128 && m0 + tid < NN) {
        float s = 0.f;
#pragma unroll
        for (int j = 0; j < 16; j++) s += red[tid * 16 + j];
        d_ald2[m0 + tid] = s;
    }
}

// ------- gather layer2: warp per node, self inline, fused BN2 stats ------------------
__global__ void __launch_bounds__(256) gather2w(const float* __restrict__ bias) {
    int wid = threadIdx.x >> 5, lane = threadIdx.x & 31;
    int d = blockIdx.x * 8 + wid;   // NN % 8 == 0, all warps active
    int r0 = d_rowptr[d], r1 = d_rowptr[d + 1];
    int LR = r1 - 1 - r0;
    __shared__ float sex[8][32];
    __shared__ int ssrc[8][32];
    __shared__ float s2v[8][64];
    float ald = d_ald2[d];
    float inv = 1.0f / (float)(LR > 1 ? LR : 1);
    float selfa = lrelu(d_als2[d] + ald + d_ec2sum[d] * inv);

    // pass 1: max
    float mx = selfa;
    for (int idx = lane; idx < LR; idx += 32) {
        int p = r0 + idx;
        float a = lrelu(d_als2[d_esrc[p]] + ald + d_ec2[p]);
        mx = fmaxf(mx, a);
    }
#pragma unroll
    for (int off = 16; off >= 1; off >>= 1)
        mx = fmaxf(mx, __shfl_xor_sync(0xFFFFFFFFu, mx, off));

    // pass 2: exp + accumulate
    float2 acc = make_float2(0.f, 0.f);
    float lsum = 0.f;
    const float2* x2 = (const float2*)d_xs2;
    for (int c0 = r0; c0 < r0 + LR; c0 += 32) {
        int m = min(32, r0 + LR - c0);
        __syncwarp();
        if (lane < m) {
            int p = c0 + lane;
            int s = d_esrc[p];
            float a = lrelu(d_als2[s] + ald + d_ec2[p]);
            float e = __expf(a - mx);
            sex[wid][lane] = e;
            ssrc[wid][lane] = s;
            lsum += e;
        }
        __syncwarp();
        for (int j = 0; j < m; j++) {
            float2 xv = x2[(size_t)ssrc[wid][j] * 32 + lane];
            float e = sex[wid][j];
            acc.x += e * xv.x;
            acc.y += e * xv.y;
        }
    }
    float es = __expf(selfa - mx);
    {
        float2 xv = x2[(size_t)d * 32 + lane];
        acc.x += es * xv.x;
        acc.y += es * xv.y;
    }
#pragma unroll
    for (int off = 16; off >= 1; off >>= 1)
        lsum += __shfl_xor_sync(0xFFFFFFFFu, lsum, off);
    lsum += es;
    float sinv = 1.0f / lsum;
    float2 bv = ((const float2*)bias)[lane];
    float y0 = acc.x * sinv + bv.x;
    float y1 = acc.y * sinv + bv.y;
    ((float2*)d_out2)[(size_t)d * 32 + lane] = make_float2(y0, y1);
    // fused BN2 stats
    s2v[wid][lane * 2]     = y0;
    s2v[wid][lane * 2 + 1] = y1;
    __syncthreads();
    int t = threadIdx.x;
    if (t < 64) {
        float s = 0.f, q = 0.f;
#pragma unroll
        for (int r = 0; r < 8; r++) {
            float v = s2v[r][t];
            s += v;
            q += v * v;
        }
        atomicAdd(&d_colsum2[t], s);
        atomicAdd(&d_colsq2[t], q);
    }
}

// ------------------- gate (applies BN2+ReLU in place) ---------------------------------
__global__ void gate_bn(const float* __restrict__ g2, const float* __restrict__ b2,
                        const float* __restrict__ Wg, const float* __restrict__ bg) {
    int n = (blockIdx.x * blockDim.x + threadIdx.x) >> 5;
    int lane = threadIdx.x & 31;
    if (n >= NN) return;
    int c0 = lane * 2, c1 = c0 + 1;
    float2 v = ((const float2*)d_out2)[(size_t)n * 32 + lane];
    float mu0 = d_colsum2[c0] / (float)NN;
    float var0 = d_colsq2[c0] / (float)NN - mu0 * mu0;
    float y0 = fmaxf((v.x - mu0) * rsqrtf(var0 + EPS) * __ldg(g2 + c0) + __ldg(b2 + c0), 0.f);
    float mu1 = d_colsum2[c1] / (float)NN;
    float var1 = d_colsq2[c1] / (float)NN - mu1 * mu1;
    float y1 = fmaxf((v.y - mu1) * rsqrtf(var1 + EPS) * __ldg(g2 + c1) + __ldg(b2 + c1), 0.f);
    ((float2*)d_out2)[(size_t)n * 32 + lane] = make_float2(y0, y1);
    float g = y0 * __ldg(Wg + c0) + y1 * __ldg(Wg + c1);
#pragma unroll
    for (int off = 16; off >= 1; off >>= 1)
        g += __shfl_xor_sync(0xFFFFFFFFu, g, off);
    if (lane == 0) d_gate[n] = g + bg[0];
}

// ------------------- pooling ------------------------------------------------------------
__device__ __forceinline__ int lbound(const int* a, int n, int v) {
    int lo = 0, hi = n;
    while (lo < hi) {
        int mid = (lo + hi) >> 1;
        if (a[mid] < v) lo = mid + 1; else hi = mid;
    }
    return lo;
}

__global__ void __launch_bounds__(64) pool_kernel(const int* __restrict__ batch,
                                                  float* __restrict__ out) {
    int b = blockIdx.x, t = threadIdx.x;
    __shared__ int slo, shi;
    __shared__ float red[64];
    __shared__ float sh_w[64];
    if (t == 0) { slo = lbound(batch, NN, b); shi = lbound(batch, NN, b + 1); }
    __syncthreads();
    int lo = slo, hi = shi;
    if (hi <= lo) { out[b * 64 + t] = 0.f; return; }
    float mx = -3.4e38f;
    for (int n = lo + t; n < hi; n += 64) mx = fmaxf(mx, d_gate[n]);
    red[t] = mx;
    __syncthreads();
    if (t == 0) {
        float m = red[0];
        for (int j = 1; j < 64; j++) m = fmaxf(m, red[j]);
        red[0] = m;
    }
    __syncthreads();
    float m = red[0];
    __syncthreads();
    float ts = 0.f;
    for (int n = lo + t; n < hi; n += 64) ts += __expf(d_gate[n] - m);
    red[t] = ts;
    __syncthreads();
    if (t == 0) {
        float s = 0.f;
        for (int j = 0; j < 64; j++) s += red[j];
        red[0] = s;
    }
    __syncthreads();
    float sinv = 1.0f / red[0];
    float acc = 0.f;
    for (int base = lo; base < hi; base += 64) {
        int mcnt = min(64, hi - base);
        __syncthreads();
        if (t < mcnt) sh_w[t] = __expf(d_gate[base + t] - m);
        __syncthreads();
        for (int j = 0; j < mcnt; j++)
            acc += sh_w[j] * d_out2[(size_t)(base + j) * 64 + t];
    }
    out[b * 64 + t] = acc * sinv;
}

// ------------------- launch ----------------------------------------------------------------
static inline int gdiv(long long a, int b) { return (int)((a + b - 1) / b); }

extern "C" void kernel_launch(void* const* d_in, const int* in_sizes, int n_in,
                              void* d_out, int out_size) {
    const float* x     = (const float*)d_in[0];
    const float* ea    = (const float*)d_in[1];
    const int*   ei    = (const int*)d_in[2];
    const int*   batch = (const int*)d_in[3];
    const float* W1    = (const float*)d_in[4];
    const float* We1   = (const float*)d_in[5];
    const float* as1   = (const float*)d_in[6];
    const float* ad1   = (const float*)d_in[7];
    const float* ae1   = (const float*)d_in[8];
    const float* b1    = (const float*)d_in[9];
    const float* g1    = (const float*)d_in[10];
    const float* bb1   = (const float*)d_in[11];
    const float* W2    = (const float*)d_in[12];
    const float* We2   = (const float*)d_in[13];
    const float* as2   = (const float*)d_in[14];
    const float* ad2   = (const float*)d_in[15];
    const float* ae2   = (const float*)d_in[16];
    const float* b2    = (const float*)d_in[17];
    const float* g2    = (const float*)d_in[18];
    const float* bb2   = (const float*)d_in[19];
    const float* Wg    = (const float*)d_in[20];
    const float* bg    = (const float*)d_in[21];
    float* out = (float*)d_out;

    const int* src = ei;
    const int* dst = ei + EE;

    float* p_tmp;  cudaGetSymbolAddress((void**)&p_tmp, d_tmp);
    float* p_out1; cudaGetSymbolAddress((void**)&p_out1, d_out1);
    float* p_xs2;  cudaGetSymbolAddress((void**)&p_xs2, d_xs2);

    init0<<<gdiv(NN, 256), 256>>>();
    hist_kernel<<<gdiv(EE, 256), 256>>>(dst);
    scan_kernel<<<1, 1024>>>();
    prep_par<<<84, 256>>>(W1, as1, ad1, We1, ae1, We2, ae2);
    logits1<<<gdiv((long long)NN * 32, 256), 256>>>(x);
    edge_alpha1<<<gdiv(EE, 256), 256>>>(ea, src, dst);
    gather1w<<<gdiv(NN, 8), 256>>>(x);
    {
        dim3 g(4, gdiv(NN, 128));
        gemm1_stats<<<g, 256>>>(p_tmp, W1, p_out1, b1);
    }
    {
        dim3 g(1, gdiv(NN, 128));
        gemm2_fused<<<g, 256>>>(p_out1, W2, p_xs2, g1, bb1, as2, ad2);
    }
    gather2w<<<gdiv(NN, 8), 256>>>(b2);
    gate_bn<<<gdiv((long long)NN * 32, 256), 256>>>(g2, bb2, Wg, bg);
    pool_kernel<<<BB, 64>>>(batch, out);
}

// round 13
// speedup vs baseline: 1.1746x; 1.1746x over previous
#include <cuda_runtime.h>
#include <math_constants.h>

#define NN 30000
#define EE 480000
#define ET (EE + NN)
#define BB 64
#define FIN 128
#define HID 64
#define ED 32
#define C1 256
#define NEG 0.2f
#define EPS 1e-5f

typedef unsigned long long ull;

// ------------------- scratch -------------------------------------------------
__device__ int      d_deg[NN];          // real in-degree
__device__ int      d_rowptr[NN + 1];
__device__ int      d_cursor[NN];
__device__ int      d_esrc[ET];

__device__ float    d_vs1[512];
__device__ float    d_vd1[512];
__device__ float    d_c1[ED * 4];
__device__ float    d_c2[ED];
__device__ float    d_als1[NN * 4];
__device__ float    d_ald1[NN * 4];
__device__ float    d_ecsum[NN * 4];    // per-dst sums of ea.c1
__device__ float    d_ec2sum[NN];
__device__ float    d_ec2[ET];          // CSR order, ea.c2 (real slots only)
__device__ float    d_alpha1[(size_t)ET * 4];   // CSR order (real slots only)
__device__ float    d_tmp[(size_t)NN * 512];
__device__ float    d_out1[(size_t)NN * C1];
__device__ float    d_colsum1[C1];
__device__ float    d_colsq1[C1];
__device__ float    d_xs2[(size_t)NN * HID];
__device__ float    d_als2[NN];
__device__ float    d_ald2[NN];
__device__ float    d_out2[(size_t)NN * HID];
__device__ float    d_colsum2[HID];
__device__ float    d_colsq2[HID];
__device__ float    d_gate[NN];

// ------------------- helpers -------------------------------------------------
__device__ __forceinline__ ull pack2(float lo, float hi) {
    ull r;
    asm("mov.b64 %0, {%1, %2};" : "=l"(r) : "f"(lo), "f"(hi));
    return r;
}
__device__ __forceinline__ void unpack2(ull v, float& lo, float& hi) {
    asm("mov.b64 {%0, %1}, %2;" : "=f"(lo), "=f"(hi) : "l"(v));
}
__device__ __forceinline__ void fma2(ull& acc, ull a, ull b) {
    asm("fma.rn.f32x2 %0, %1, %2, %0;" : "+l"(acc) : "l"(a), "l"(b));
}
__device__ __forceinline__ float lrelu(float a) { return a > 0.f ? a : NEG * a; }

// ------------------- init (grid-wide) ------------------------------------------
__global__ void init0() {
    int i = blockIdx.x * blockDim.x + threadIdx.x;
    if (i < NN * 4) d_ecsum[i] = 0.f;
    if (i < NN) { d_deg[i] = 0; d_cursor[i] = 0; d_ec2sum[i] = 0.f; }
}

// ------------------- CSR build --------------------------------------------------
__global__ void hist_kernel(const int* __restrict__ dst) {
    int e = blockIdx.x * blockDim.x + threadIdx.x;
    if (e < EE) atomicAdd(&d_deg[dst[e]], 1);
}

__global__ void scan_kernel() {
    __shared__ int wsum[32];
    const int PER = 30;
    int t = threadIdx.x;
    if (t < C1) { d_colsum1[t] = 0.f; d_colsq1[t] = 0.f; }
    if (t < HID) { d_colsum2[t] = 0.f; d_colsq2[t] = 0.f; }
    int base = t * PER;
    int vals[PER];
    int s = 0;
#pragma unroll
    for (int i = 0; i < PER; i++) {
        int idx = base + i;
        vals[i] = (idx < NN) ? (d_deg[idx] + 1) : 0;   // +1 self loop (last slot)
        s += vals[i];
    }
    int lane = t & 31, w = t >> 5;
    int x = s;
#pragma unroll
    for (int off = 1; off < 32; off <<= 1) {
        int y = __shfl_up_sync(0xFFFFFFFFu, x, off);
        if (lane >= off) x += y;
    }
    if (lane == 31) wsum[w] = x;
    __syncthreads();
    if (w == 0) {
        int y = wsum[lane];
#pragma unroll
        for (int off = 1; off < 32; off <<= 1) {
            int z = __shfl_up_sync(0xFFFFFFFFu, y, off);
            if (lane >= off) y += z;
        }
        wsum[lane] = y;
    }
    __syncthreads();
    int excl = x - s + (w > 0 ? wsum[w - 1] : 0);
    int run = excl;
#pragma unroll
    for (int i = 0; i < PER; i++) {
        int idx = base + i;
        if (idx < NN) d_rowptr[idx] = run;
        run += vals[i];
    }
    if (t == 0) d_rowptr[NN] = ET;
}

// -------------- precompute small vectors (warp per output; 672 warps) ---------------
__global__ void __launch_bounds__(256) prep_par(
    const float* __restrict__ W1, const float* __restrict__ as1,
    const float* __restrict__ ad1,
    const float* __restrict__ We1, const float* __restrict__ ae1,
    const float* __restrict__ We2, const float* __restrict__ ae2) {
    int gw = blockIdx.x * 8 + (threadIdx.x >> 5);   // global warp id
    int lane = threadIdx.x & 31;
    if (gw < 512) {
        int h = gw >> 7, k = gw & 127;
        const float* wrow = W1 + (size_t)k * C1 + h * HID;
        const float* arow = as1 + h * HID;
        const float* drow = ad1 + h * HID;
        float w0 = wrow[lane], w1 = wrow[lane + 32];
        float s = w0 * arow[lane] + w1 * arow[lane + 32];
        float dv = w0 * drow[lane] + w1 * drow[lane + 32];
#pragma unroll
        for (int off = 16; off >= 1; off >>= 1) {
            s += __shfl_xor_sync(0xFFFFFFFFu, s, off);
            dv += __shfl_xor_sync(0xFFFFFFFFu, dv, off);
        }
        if (lane == 0) { d_vs1[gw] = s; d_vd1[gw] = dv; }
    } else if (gw < 640) {
        int idx = gw - 512;
        int k = idx >> 2, h = idx & 3;
        const float* wrow = We1 + (size_t)k * C1 + h * HID;
        const float* arow = ae1 + h * HID;
        float s = wrow[lane] * arow[lane] + wrow[lane + 32] * arow[lane + 32];
#pragma unroll
        for (int off = 16; off >= 1; off >>= 1)
            s += __shfl_xor_sync(0xFFFFFFFFu, s, off);
        if (lane == 0) d_c1[idx] = s;
    } else if (gw < 672) {
        int k = gw - 640;
        const float* wrow = We2 + (size_t)k * HID;
        float s = wrow[lane] * ae2[lane] + wrow[lane + 32] * ae2[lane + 32];
#pragma unroll
        for (int off = 16; off >= 1; off >>= 1)
            s += __shfl_xor_sync(0xFFFFFFFFu, s, off);
        if (lane == 0) d_c2[k] = s;
    }
}

// ------------------- node logits (layer 1) ---------------------------------------
__global__ void logits1(const float* __restrict__ x) {
    int gw = (blockIdx.x * blockDim.x + threadIdx.x) >> 5;
    int lane = threadIdx.x & 31;
    if (gw >= NN) return;
    float4 xv = ((const float4*)x)[(size_t)gw * 32 + lane];
    float r0, r1, r2, r3, q0, q1, q2, q3;
    {
        float4 v;
        v = ((const float4*)d_vs1)[0 * 32 + lane]; r0 = xv.x*v.x + xv.y*v.y + xv.z*v.z + xv.w*v.w;
        v = ((const float4*)d_vs1)[1 * 32 + lane]; r1 = xv.x*v.x + xv.y*v.y + xv.z*v.z + xv.w*v.w;
        v = ((const float4*)d_vs1)[2 * 32 + lane]; r2 = xv.x*v.x + xv.y*v.y + xv.z*v.z + xv.w*v.w;
        v = ((const float4*)d_vs1)[3 * 32 + lane]; r3 = xv.x*v.x + xv.y*v.y + xv.z*v.z + xv.w*v.w;
        v = ((const float4*)d_vd1)[0 * 32 + lane]; q0 = xv.x*v.x + xv.y*v.y + xv.z*v.z + xv.w*v.w;
        v = ((const float4*)d_vd1)[1 * 32 + lane]; q1 = xv.x*v.x + xv.y*v.y + xv.z*v.z + xv.w*v.w;
        v = ((const float4*)d_vd1)[2 * 32 + lane]; q2 = xv.x*v.x + xv.y*v.y + xv.z*v.z + xv.w*v.w;
        v = ((const float4*)d_vd1)[3 * 32 + lane]; q3 = xv.x*v.x + xv.y*v.y + xv.z*v.z + xv.w*v.w;
    }
#pragma unroll
    for (int off = 16; off >= 1; off >>= 1) {
        r0 += __shfl_xor_sync(0xFFFFFFFFu, r0, off);
        r1 += __shfl_xor_sync(0xFFFFFFFFu, r1, off);
        r2 += __shfl_xor_sync(0xFFFFFFFFu, r2, off);
        r3 += __shfl_xor_sync(0xFFFFFFFFu, r3, off);
        q0 += __shfl_xor_sync(0xFFFFFFFFu, q0, off);
        q1 += __shfl_xor_sync(0xFFFFFFFFu, q1, off);
        q2 += __shfl_xor_sync(0xFFFFFFFFu, q2, off);
        q3 += __shfl_xor_sync(0xFFFFFFFFu, q3, off);
    }
    if (lane == 0) {
        d_als1[gw * 4 + 0] = r0; d_als1[gw * 4 + 1] = r1;
        d_als1[gw * 4 + 2] = r2; d_als1[gw * 4 + 3] = r3;
        d_ald1[gw * 4 + 0] = q0; d_ald1[gw * 4 + 1] = q1;
        d_ald1[gw * 4 + 2] = q2; d_ald1[gw * 4 + 3] = q3;
    }
}

// --------- edge alphas: CSR slot assignment + alpha + ec sums in ONE pass -----------
__global__ void edge_alpha1(const float* __restrict__ ea, const int* __restrict__ src,
                            const int* __restrict__ dst) {
    int e = blockIdx.x * blockDim.x + threadIdx.x;
    if (e >= EE) return;
    int s = src[e], d = dst[e];
    const float4* row = (const float4*)(ea + (size_t)e * ED);
    float ec0 = 0.f, ec1 = 0.f, ec2 = 0.f, ec3 = 0.f, e2 = 0.f;
#pragma unroll
    for (int q = 0; q < 8; q++) {
        float4 v = __ldg(row + q);
        int k = q * 4;
        ec0 += v.x * d_c1[(k+0)*4+0] + v.y * d_c1[(k+1)*4+0] + v.z * d_c1[(k+2)*4+0] + v.w * d_c1[(k+3)*4+0];
        ec1 += v.x * d_c1[(k+0)*4+1] + v.y * d_c1[(k+1)*4+1] + v.z * d_c1[(k+2)*4+1] + v.w * d_c1[(k+3)*4+1];
        ec2 += v.x * d_c1[(k+0)*4+2] + v.y * d_c1[(k+1)*4+2] + v.z * d_c1[(k+2)*4+2] + v.w * d_c1[(k+3)*4+2];
        ec3 += v.x * d_c1[(k+0)*4+3] + v.y * d_c1[(k+1)*4+3] + v.z * d_c1[(k+2)*4+3] + v.w * d_c1[(k+3)*4+3];
        e2  += v.x * d_c2[k+0] + v.y * d_c2[k+1] + v.z * d_c2[k+2] + v.w * d_c2[k+3];
    }
    int p = d_rowptr[d] + atomicAdd(&d_cursor[d], 1);
    d_esrc[p] = s;
    d_ec2[p] = e2;
    float4 a;
    a.x = lrelu(d_als1[s * 4 + 0] + d_ald1[d * 4 + 0] + ec0);
    a.y = lrelu(d_als1[s * 4 + 1] + d_ald1[d * 4 + 1] + ec1);
    a.z = lrelu(d_als1[s * 4 + 2] + d_ald1[d * 4 + 2] + ec2);
    a.w = lrelu(d_als1[s * 4 + 3] + d_ald1[d * 4 + 3] + ec3);
    *(float4*)&d_alpha1[(size_t)p * 4] = a;
    atomicAdd(&d_ecsum[d * 4 + 0], ec0);
    atomicAdd(&d_ecsum[d * 4 + 1], ec1);
    atomicAdd(&d_ecsum[d * 4 + 2], ec2);
    atomicAdd(&d_ecsum[d * 4 + 3], ec3);
    atomicAdd(&d_ec2sum[d], e2);
}

// ------------------- gather layer1: warp per node, self-loop inline -------------------
__global__ void __launch_bounds__(256) gather1w(const float* __restrict__ x) {
    int wid = threadIdx.x >> 5, lane = threadIdx.x & 31;
    int d = blockIdx.x * 8 + wid;   // NN % 8 == 0
    int r0 = d_rowptr[d], r1 = d_rowptr[d + 1];
    int LR = r1 - 1 - r0;           // real edges; slot r1-1 is self
    __shared__ __align__(16) float4 sex[8][32];
    __shared__ int ssrc[8][32];

    float inv = 1.0f / (float)(LR > 1 ? LR : 1);
    float4 selfa;
    selfa.x = lrelu(d_als1[d * 4 + 0] + d_ald1[d * 4 + 0] + d_ecsum[d * 4 + 0] * inv);
    selfa.y = lrelu(d_als1[d * 4 + 1] + d_ald1[d * 4 + 1] + d_ecsum[d * 4 + 1] * inv);
    selfa.z = lrelu(d_als1[d * 4 + 2] + d_ald1[d * 4 + 2] + d_ecsum[d * 4 + 2] * inv);
    selfa.w = lrelu(d_als1[d * 4 + 3] + d_ald1[d * 4 + 3] + d_ecsum[d * 4 + 3] * inv);

    // max per head (self included)
    float4 mx = selfa;
    for (int idx = lane; idx < LR; idx += 32) {
        float4 a = *(const float4*)&d_alpha1[(size_t)(r0 + idx) * 4];
        mx.x = fmaxf(mx.x, a.x); mx.y = fmaxf(mx.y, a.y);
        mx.z = fmaxf(mx.z, a.z); mx.w = fmaxf(mx.w, a.w);
    }
#pragma unroll
    for (int off = 16; off >= 1; off >>= 1) {
        mx.x = fmaxf(mx.x, __shfl_xor_sync(0xFFFFFFFFu, mx.x, off));
        mx.y = fmaxf(mx.y, __shfl_xor_sync(0xFFFFFFFFu, mx.y, off));
        mx.z = fmaxf(mx.z, __shfl_xor_sync(0xFFFFFFFFu, mx.z, off));
        mx.w = fmaxf(mx.w, __shfl_xor_sync(0xFFFFFFFFu, mx.w, off));
    }

    float4 a0 = make_float4(0, 0, 0, 0), a1 = a0, a2 = a0, a3 = a0;
    float4 lsum = make_float4(0, 0, 0, 0);
    const float4* x4 = (const float4*)x;
    for (int c0 = r0; c0 < r0 + LR; c0 += 32) {
        int m = min(32, r0 + LR - c0);
        __syncwarp();
        if (lane < m) {
            float4 a = *(const float4*)&d_alpha1[(size_t)(c0 + lane) * 4];
            float4 e;
            e.x = __expf(a.x - mx.x); e.y = __expf(a.y - mx.y);
            e.z = __expf(a.z - mx.z); e.w = __expf(a.w - mx.w);
            sex[wid][lane] = e;
            ssrc[wid][lane] = d_esrc[c0 + lane];
            lsum.x += e.x; lsum.y += e.y; lsum.z += e.z; lsum.w += e.w;
        }
        __syncwarp();
        for (int j = 0; j < m; j++) {
            float4 xv = x4[(size_t)ssrc[wid][j] * 32 + lane];
            float4 e = sex[wid][j];
            a0.x += e.x * xv.x; a0.y += e.x * xv.y; a0.z += e.x * xv.z; a0.w += e.x * xv.w;
            a1.x += e.y * xv.x; a1.y += e.y * xv.y; a1.z += e.y * xv.z; a1.w += e.y * xv.w;
            a2.x += e.z * xv.x; a2.y += e.z * xv.y; a2.z += e.z * xv.z; a2.w += e.z * xv.w;
            a3.x += e.w * xv.x; a3.y += e.w * xv.y; a3.z += e.w * xv.z; a3.w += e.w * xv.w;
        }
    }
    // self-loop contribution
    float4 es;
    es.x = __expf(selfa.x - mx.x); es.y = __expf(selfa.y - mx.y);
    es.z = __expf(selfa.z - mx.z); es.w = __expf(selfa.w - mx.w);
    {
        float4 xv = x4[(size_t)d * 32 + lane];
        a0.x += es.x * xv.x; a0.y += es.x * xv.y; a0.z += es.x * xv.z; a0.w += es.x * xv.w;
        a1.x += es.y * xv.x; a1.y += es.y * xv.y; a1.z += es.y * xv.z; a1.w += es.y * xv.w;
        a2.x += es.z * xv.x; a2.y += es.z * xv.y; a2.z += es.z * xv.z; a2.w += es.z * xv.w;
        a3.x += es.w * xv.x; a3.y += es.w * xv.y; a3.z += es.w * xv.z; a3.w += es.w * xv.w;
    }
#pragma unroll
    for (int off = 16; off >= 1; off >>= 1) {
        lsum.x += __shfl_xor_sync(0xFFFFFFFFu, lsum.x, off);
        lsum.y += __shfl_xor_sync(0xFFFFFFFFu, lsum.y, off);
        lsum.z += __shfl_xor_sync(0xFFFFFFFFu, lsum.z, off);
        lsum.w += __shfl_xor_sync(0xFFFFFFFFu, lsum.w, off);
    }
    lsum.x += es.x; lsum.y += es.y; lsum.z += es.z; lsum.w += es.w;
    float i0 = 1.0f / lsum.x, i1 = 1.0f / lsum.y, i2 = 1.0f / lsum.z, i3 = 1.0f / lsum.w;
    float4* tmp4 = (float4*)&d_tmp[(size_t)d * 512];
    tmp4[0 * 32 + lane] = make_float4(a0.x * i0, a0.y * i0, a0.z * i0, a0.w * i0);
    tmp4[1 * 32 + lane] = make_float4(a1.x * i1, a1.y * i1, a1.z * i1, a1.w * i1);
    tmp4[2 * 32 + lane] = make_float4(a2.x * i2, a2.y * i2, a2.z * i2, a2.w * i2);
    tmp4[3 * 32 + lane] = make_float4(a3.x * i3, a3.y * i3, a3.z * i3, a3.w * i3);
}

// ------------------- GEMM1: out1 = tmp(heads) @ W1 + b1, fused BN stats -------------
__global__ void __launch_bounds__(256) gemm1_stats(
    const float* __restrict__ A, const float* __restrict__ B,
    float* __restrict__ C, const float* __restrict__ bias) {
    const int BK = 16;
    __shared__ __align__(16) float As[BK][128 + 4];
    __shared__ __align__(16) float Bs[BK][64];
    __shared__ float reds[16][64];
    __shared__ float redq[16][64];
    int tid = threadIdx.x;
    int tx = tid & 15, ty = tid >> 4;
    int m0 = blockIdx.y * 128;
    const float* Ab = A + (size_t)blockIdx.x * 128;
    int bcol = blockIdx.x * 64;

    ull acc[4][4];
#pragma unroll
    for (int i = 0; i < 4; i++)
#pragma unroll
        for (int j = 0; j < 4; j++) acc[i][j] = 0ull;

    int ar = tid >> 1;
    int akb = (tid & 1) * 8;
    int gr_a = m0 + ar;
    int br = tid >> 4;
    int bc = (tid & 15) * 4;

    for (int k0 = 0; k0 < FIN; k0 += BK) {
        float4 a4a, a4b;
        if (gr_a < NN) {
            a4a = *(const float4*)&Ab[(size_t)gr_a * 512 + k0 + akb];
            a4b = *(const float4*)&Ab[(size_t)gr_a * 512 + k0 + akb + 4];
        } else {
            a4a = make_float4(0.f, 0.f, 0.f, 0.f);
            a4b = a4a;
        }
        As[akb + 0][ar] = a4a.x; As[akb + 1][ar] = a4a.y;
        As[akb + 2][ar] = a4a.z; As[akb + 3][ar] = a4a.w;
        As[akb + 4][ar] = a4b.x; As[akb + 5][ar] = a4b.y;
        As[akb + 6][ar] = a4b.z; As[akb + 7][ar] = a4b.w;
        *(float4*)&Bs[br][bc] = *(const float4*)&B[(size_t)(k0 + br) * C1 + bcol + bc];
        __syncthreads();
#pragma unroll
        for (int kk = 0; kk < BK; kk++) {
            ulonglong2 ap01 = *(const ulonglong2*)&As[kk][ty * 8];
            ulonglong2 ap23 = *(const ulonglong2*)&As[kk][ty * 8 + 4];
            float4 bq = *(const float4*)&Bs[kk][tx * 4];
            ull bb0 = pack2(bq.x, bq.x);
            ull bb1 = pack2(bq.y, bq.y);
            ull bb2 = pack2(bq.z, bq.z);
            ull bb3 = pack2(bq.w, bq.w);
            ull ap[4] = {ap01.x, ap01.y, ap23.x, ap23.y};
#pragma unroll
            for (int i = 0; i < 4; i++) {
                fma2(acc[i][0], ap[i], bb0);
                fma2(acc[i][1], ap[i], bb1);
                fma2(acc[i][2], ap[i], bb2);
                fma2(acc[i][3], ap[i], bb3);
            }
        }
        __syncthreads();
    }
    float4 bv = *(const float4*)&bias[bcol + tx * 4];
    float psum[4] = {0.f, 0.f, 0.f, 0.f};
    float psq[4]  = {0.f, 0.f, 0.f, 0.f};
#pragma unroll
    for (int i = 0; i < 4; i++) {
        float lo0, hi0, lo1, hi1, lo2, hi2, lo3, hi3;
        unpack2(acc[i][0], lo0, hi0);
        unpack2(acc[i][1], lo1, hi1);
        unpack2(acc[i][2], lo2, hi2);
        unpack2(acc[i][3], lo3, hi3);
        int r0 = m0 + ty * 8 + 2 * i;
        float y0 = lo0 + bv.x, y1 = lo1 + bv.y, y2 = lo2 + bv.z, y3 = lo3 + bv.w;
        float z0 = hi0 + bv.x, z1 = hi1 + bv.y, z2 = hi2 + bv.z, z3 = hi3 + bv.w;
        if (r0 < NN) {
            *(float4*)&C[(size_t)r0 * C1 + bcol + tx * 4] = make_float4(y0, y1, y2, y3);
            psum[0] += y0; psum[1] += y1; psum[2] += y2; psum[3] += y3;
            psq[0] += y0 * y0; psq[1] += y1 * y1; psq[2] += y2 * y2; psq[3] += y3 * y3;
        }
        if (r0 + 1 < NN) {
            *(float4*)&C[(size_t)(r0 + 1) * C1 + bcol + tx * 4] = make_float4(z0, z1, z2, z3);
            psum[0] += z0; psum[1] += z1; psum[2] += z2; psum[3] += z3;
            psq[0] += z0 * z0; psq[1] += z1 * z1; psq[2] += z2 * z2; psq[3] += z3 * z3;
        }
    }
#pragma unroll
    for (int c = 0; c < 4; c++) {
        reds[ty][tx * 4 + c] = psum[c];
        redq[ty][tx * 4 + c] = psq[c];
    }
    __syncthreads();
    if (tid < 64) {
        float s = 0.f, q = 0.f;
#pragma unroll
        for (int i = 0; i < 16; i++) { s += reds[i][tid]; q += redq[i][tid]; }
        atomicAdd(&d_colsum1[bcol + tid], s);
        atomicAdd(&d_colsq1[bcol + tid], q);
    }
}

// ------------------- GEMM2: xs2 = BNReLU(out1) @ W2, fused logits2 ------------------
__global__ void __launch_bounds__(256) gemm2_fused(
    const float* __restrict__ A, const float* __restrict__ B,
    float* __restrict__ C, const float* __restrict__ g1bn,
    const float* __restrict__ b1bn, const float* __restrict__ as2,
    const float* __restrict__ ad2) {
    const int BK = 16;
    __shared__ __align__(16) float As[BK][128 + 4];
    __shared__ __align__(16) float Bs[BK][64];
    __shared__ float sc[C1];
    __shared__ float sf[C1];
    int tid = threadIdx.x;
    int tx = tid & 15, ty = tid >> 4;
    int m0 = blockIdx.y * 128;

    {
        float mu = d_colsum1[tid] / (float)NN;
        float var = d_colsq1[tid] / (float)NN - mu * mu;
        float rs = rsqrtf(var + EPS) * g1bn[tid];
        sc[tid] = rs;
        sf[tid] = b1bn[tid] - mu * rs;
    }
    __syncthreads();

    ull acc[4][4];
#pragma unroll
    for (int i = 0; i < 4; i++)
#pragma unroll
        for (int j = 0; j < 4; j++) acc[i][j] = 0ull;

    int ar = tid >> 1;
    int akb = (tid & 1) * 8;
    int gr_a = m0 + ar;
    int br = tid >> 4;
    int bc = (tid & 15) * 4;

    for (int k0 = 0; k0 < C1; k0 += BK) {
        float4 a4a, a4b;
        if (gr_a < NN) {
            a4a = *(const float4*)&A[(size_t)gr_a * C1 + k0 + akb];
            a4b = *(const float4*)&A[(size_t)gr_a * C1 + k0 + akb + 4];
        } else {
            a4a = make_float4(0.f, 0.f, 0.f, 0.f);
            a4b = a4a;
        }
        int kb = k0 + akb;
        As[akb + 0][ar] = fmaxf(fmaf(a4a.x, sc[kb + 0], sf[kb + 0]), 0.f);
        As[akb + 1][ar] = fmaxf(fmaf(a4a.y, sc[kb + 1], sf[kb + 1]), 0.f);
        As[akb + 2][ar] = fmaxf(fmaf(a4a.z, sc[kb + 2], sf[kb + 2]), 0.f);
        As[akb + 3][ar] = fmaxf(fmaf(a4a.w, sc[kb + 3], sf[kb + 3]), 0.f);
        As[akb + 4][ar] = fmaxf(fmaf(a4b.x, sc[kb + 4], sf[kb + 4]), 0.f);
        As[akb + 5][ar] = fmaxf(fmaf(a4b.y, sc[kb + 5], sf[kb + 5]), 0.f);
        As[akb + 6][ar] = fmaxf(fmaf(a4b.z, sc[kb + 6], sf[kb + 6]), 0.f);
        As[akb + 7][ar] = fmaxf(fmaf(a4b.w, sc[kb + 7], sf[kb + 7]), 0.f);
        *(float4*)&Bs[br][bc] = *(const float4*)&B[(size_t)(k0 + br) * HID + bc];
        __syncthreads();
#pragma unroll
        for (int kk = 0; kk < BK; kk++) {
            ulonglong2 ap01 = *(const ulonglong2*)&As[kk][ty * 8];
            ulonglong2 ap23 = *(const ulonglong2*)&As[kk][ty * 8 + 4];
            float4 bq = *(const float4*)&Bs[kk][tx * 4];
            ull bb0 = pack2(bq.x, bq.x);
            ull bb1 = pack2(bq.y, bq.y);
            ull bb2 = pack2(bq.z, bq.z);
            ull bb3 = pack2(bq.w, bq.w);
            ull ap[4] = {ap01.x, ap01.y, ap23.x, ap23.y};
#pragma unroll
            for (int i = 0; i < 4; i++) {
                fma2(acc[i][0], ap[i], bb0);
                fma2(acc[i][1], ap[i], bb1);
                fma2(acc[i][2], ap[i], bb2);
                fma2(acc[i][3], ap[i], bb3);
            }
        }
        __syncthreads();
    }
    float4 av = *(const float4*)&as2[tx * 4];
    float4 dv = *(const float4*)&ad2[tx * 4];
    float ps8[8], pd8[8];
#pragma unroll
    for (int i = 0; i < 4; i++) {
        float lo0, hi0, lo1, hi1, lo2, hi2, lo3, hi3;
        unpack2(acc[i][0], lo0, hi0);
        unpack2(acc[i][1], lo1, hi1);
        unpack2(acc[i][2], lo2, hi2);
        unpack2(acc[i][3], lo3, hi3);
        int r0 = m0 + ty * 8 + 2 * i;
        if (r0 < NN)
            *(float4*)&C[(size_t)r0 * HID + tx * 4] = make_float4(lo0, lo1, lo2, lo3);
        if (r0 + 1 < NN)
            *(float4*)&C[(size_t)(r0 + 1) * HID + tx * 4] = make_float4(hi0, hi1, hi2, hi3);
        ps8[2 * i]     = lo0 * av.x + lo1 * av.y + lo2 * av.z + lo3 * av.w;
        ps8[2 * i + 1] = hi0 * av.x + hi1 * av.y + hi2 * av.z + hi3 * av.w;
        pd8[2 * i]     = lo0 * dv.x + lo1 * dv.y + lo2 * dv.z + lo3 * dv.w;
        pd8[2 * i + 1] = hi0 * dv.x + hi1 * dv.y + hi2 * dv.z + hi3 * dv.w;
    }
    float* red = &As[0][0];
    __syncthreads();
#pragma unroll
    for (int i = 0; i < 8; i++) red[(ty * 8 + i) * 16 + tx] = ps8[i];
    __syncthreads();
    if (tid < 128 && m0 + tid < NN) {
        float s = 0.f;
#pragma unroll
        for (int j = 0; j < 16; j++) s += red[tid * 16 + j];
        d_als2[m0 + tid] = s;
    }
    __syncthreads();
#pragma unroll
    for (int i = 0; i < 8; i++) red[(ty * 8 + i) * 16 + tx] = pd8[i];
    __syncthreads();
    if (tid < 128 && m0 + tid < NN) {
        float s = 0.f;
#pragma unroll
        for (int j = 0; j < 16; j++) s += red[tid * 16 + j];
        d_ald2[m0 + tid] = s;
    }
}

// ------- gather layer2: warp per node, self inline, fused BN2 stats ------------------
__global__ void __launch_bounds__(256) gather2w(const float* __restrict__ bias) {
    int wid = threadIdx.x >> 5, lane = threadIdx.x & 31;
    int d = blockIdx.x * 8 + wid;   // NN % 8 == 0, all warps active
    int r0 = d_rowptr[d], r1 = d_rowptr[d + 1];
    int LR = r1 - 1 - r0;
    __shared__ float sex[8][32];
    __shared__ int ssrc[8][32];
    __shared__ float s2v[8][64];
    float ald = d_ald2[d];
    float inv = 1.0f / (float)(LR > 1 ? LR : 1);
    float selfa = lrelu(d_als2[d] + ald + d_ec2sum[d] * inv);

    // pass 1: max
    float mx = selfa;
    for (int idx = lane; idx < LR; idx += 32) {
        int p = r0 + idx;
        float a = lrelu(d_als2[d_esrc[p]] + ald + d_ec2[p]);
        mx = fmaxf(mx, a);
    }
#pragma unroll
    for (int off = 16; off >= 1; off >>= 1)
        mx = fmaxf(mx, __shfl_xor_sync(0xFFFFFFFFu, mx, off));

    // pass 2: exp + accumulate
    float2 acc = make_float2(0.f, 0.f);
    float lsum = 0.f;
    const float2* x2 = (const float2*)d_xs2;
    for (int c0 = r0; c0 < r0 + LR; c0 += 32) {
        int m = min(32, r0 + LR - c0);
        __syncwarp();
        if (lane < m) {
            int p = c0 + lane;
            int s = d_esrc[p];
            float a = lrelu(d_als2[s] + ald + d_ec2[p]);
            float e = __expf(a - mx);
            sex[wid][lane] = e;
            ssrc[wid][lane] = s;
            lsum += e;
        }
        __syncwarp();
        for (int j = 0; j < m; j++) {
            float2 xv = x2[(size_t)ssrc[wid][j] * 32 + lane];
            float e = sex[wid][j];
            acc.x += e * xv.x;
            acc.y += e * xv.y;
        }
    }
    float es = __expf(selfa - mx);
    {
        float2 xv = x2[(size_t)d * 32 + lane];
        acc.x += es * xv.x;
        acc.y += es * xv.y;
    }
#pragma unroll
    for (int off = 16; off >= 1; off >>= 1)
        lsum += __shfl_xor_sync(0xFFFFFFFFu, lsum, off);
    lsum += es;
    float sinv = 1.0f / lsum;
    float2 bv = ((const float2*)bias)[lane];
    float y0 = acc.x * sinv + bv.x;
    float y1 = acc.y * sinv + bv.y;
    ((float2*)d_out2)[(size_t)d * 32 + lane] = make_float2(y0, y1);
    // fused BN2 stats
    s2v[wid][lane * 2]     = y0;
    s2v[wid][lane * 2 + 1] = y1;
    __syncthreads();
    int t = threadIdx.x;
    if (t < 64) {
        float s = 0.f, q = 0.f;
#pragma unroll
        for (int r = 0; r < 8; r++) {
            float v = s2v[r][t];
            s += v;
            q += v * v;
        }
        atomicAdd(&d_colsum2[t], s);
        atomicAdd(&d_colsq2[t], q);
    }
}

// ------------------- gate (applies BN2+ReLU in place) ---------------------------------
__global__ void gate_bn(const float* __restrict__ g2, const float* __restrict__ b2,
                        const float* __restrict__ Wg, const float* __restrict__ bg) {
    int n = (blockIdx.x * blockDim.x + threadIdx.x) >> 5;
    int lane = threadIdx.x & 31;
    if (n >= NN) return;
    int c0 = lane * 2, c1 = c0 + 1;
    float2 v = ((const float2*)d_out2)[(size_t)n * 32 + lane];
    float mu0 = d_colsum2[c0] / (float)NN;
    float var0 = d_colsq2[c0] / (float)NN - mu0 * mu0;
    float y0 = fmaxf((v.x - mu0) * rsqrtf(var0 + EPS) * __ldg(g2 + c0) + __ldg(b2 + c0), 0.f);
    float mu1 = d_colsum2[c1] / (float)NN;
    float var1 = d_colsq2[c1] / (float)NN - mu1 * mu1;
    float y1 = fmaxf((v.y - mu1) * rsqrtf(var1 + EPS) * __ldg(g2 + c1) + __ldg(b2 + c1), 0.f);
    ((float2*)d_out2)[(size_t)n * 32 + lane] = make_float2(y0, y1);
    float g = y0 * __ldg(Wg + c0) + y1 * __ldg(Wg + c1);
#pragma unroll
    for (int off = 16; off >= 1; off >>= 1)
        g += __shfl_xor_sync(0xFFFFFFFFu, g, off);
    if (lane == 0) d_gate[n] = g + bg[0];
}

// ------------------- pooling ------------------------------------------------------------
__device__ __forceinline__ int lbound(const int* a, int n, int v) {
    int lo = 0, hi = n;
    while (lo < hi) {
        int mid = (lo + hi) >> 1;
        if (a[mid] < v) lo = mid + 1; else hi = mid;
    }
    return lo;
}

__global__ void __launch_bounds__(64) pool_kernel(const int* __restrict__ batch,
                                                  float* __restrict__ out) {
    int b = blockIdx.x, t = threadIdx.x;
    __shared__ int slo, shi;
    __shared__ float red[64];
    __shared__ float sh_w[64];
    if (t == 0) { slo = lbound(batch, NN, b); shi = lbound(batch, NN, b + 1); }
    __syncthreads();
    int lo = slo, hi = shi;
    if (hi <= lo) { out[b * 64 + t] = 0.f; return; }
    float mx = -3.4e38f;
    for (int n = lo + t; n < hi; n += 64) mx = fmaxf(mx, d_gate[n]);
    red[t] = mx;
    __syncthreads();
    if (t == 0) {
        float m = red[0];
        for (int j = 1; j < 64; j++) m = fmaxf(m, red[j]);
        red[0] = m;
    }
    __syncthreads();
    float m = red[0];
    __syncthreads();
    float ts = 0.f;
    for (int n = lo + t; n < hi; n += 64) ts += __expf(d_gate[n] - m);
    red[t] = ts;
    __syncthreads();
    if (t == 0) {
        float s = 0.f;
        for (int j = 0; j < 64; j++) s += red[j];
        red[0] = s;
    }
    __syncthreads();
    float sinv = 1.0f / red[0];
    float acc = 0.f;
    for (int base = lo; base < hi; base += 64) {
        int mcnt = min(64, hi - base);
        __syncthreads();
        if (t < mcnt) sh_w[t] = __expf(d_gate[base + t] - m);
        __syncthreads();
        for (int j = 0; j < mcnt; j++)
            acc += sh_w[j] * d_out2[(size_t)(base + j) * 64 + t];
    }
    out[b * 64 + t] = acc * sinv;
}

// ------------------- launch ----------------------------------------------------------------
static inline int gdiv(long long a, int b) { return (int)((a + b - 1) / b); }

extern "C" void kernel_launch(void* const* d_in, const int* in_sizes, int n_in,
                              void* d_out, int out_size) {
    const float* x     = (const float*)d_in[0];
    const float* ea    = (const float*)d_in[1];
    const int*   ei    = (const int*)d_in[2];
    const int*   batch = (const int*)d_in[3];
    const float* W1    = (const float*)d_in[4];
    const float* We1   = (const float*)d_in[5];
    const float* as1   = (const float*)d_in[6];
    const float* ad1   = (const float*)d_in[7];
    const float* ae1   = (const float*)d_in[8];
    const float* b1    = (const float*)d_in[9];
    const float* g1    = (const float*)d_in[10];
    const float* bb1   = (const float*)d_in[11];
    const float* W2    = (const float*)d_in[12];
    const float* We2   = (const float*)d_in[13];
    const float* as2   = (const float*)d_in[14];
    const float* ad2   = (const float*)d_in[15];
    const float* ae2   = (const float*)d_in[16];
    const float* b2    = (const float*)d_in[17];
    const float* g2    = (const float*)d_in[18];
    const float* bb2   = (const float*)d_in[19];
    const float* Wg    = (const float*)d_in[20];
    const float* bg    = (const float*)d_in[21];
    float* out = (float*)d_out;

    const int* src = ei;
    const int* dst = ei + EE;

    float* p_tmp;  cudaGetSymbolAddress((void**)&p_tmp, d_tmp);
    float* p_out1; cudaGetSymbolAddress((void**)&p_out1, d_out1);
    float* p_xs2;  cudaGetSymbolAddress((void**)&p_xs2, d_xs2);

    init0<<<gdiv(NN * 4, 256), 256>>>();
    hist_kernel<<<gdiv(EE, 256), 256>>>(dst);
    scan_kernel<<<1, 1024>>>();
    prep_par<<<84, 256>>>(W1, as1, ad1, We1, ae1, We2, ae2);
    logits1<<<gdiv((long long)NN * 32, 256), 256>>>(x);
    edge_alpha1<<<gdiv(EE, 256), 256>>>(ea, src, dst);
    gather1w<<<gdiv(NN, 8), 256>>>(x);
    {
        dim3 g(4, gdiv(NN, 128));
        gemm1_stats<<<g, 256>>>(p_tmp, W1, p_out1, b1);
    }
    {
        dim3 g(1, gdiv(NN, 128));
        gemm2_fused<<<g, 256>>>(p_out1, W2, p_xs2, g1, bb1, as2, ad2);
    }
    gather2w<<<gdiv(NN, 8), 256>>>(b2);
    gate_bn<<<gdiv((long long)NN * 32, 256), 256>>>(g2, bb2, Wg, bg);
    pool_kernel<<<BB, 64>>>(batch, out);
}

// round 14
// speedup vs baseline: 1.2115x; 1.0315x over previous
#include <cuda_runtime.h>
#include <math_constants.h>

#define NN 30000
#define EE 480000
#define ET (EE + NN)
#define BB 64
#define FIN 128
#define HID 64
#define ED 32
#define C1 256
#define NEG 0.2f
#define EPS 1e-5f

typedef unsigned long long ull;

// ------------------- scratch -------------------------------------------------
__device__ int      d_deg[NN];          // real in-degree
__device__ int      d_rowptr[NN + 1];
__device__ int      d_cursor[NN];
__device__ int      d_esrc[ET];

__device__ float    d_vs1[512];
__device__ float    d_vd1[512];
__device__ float    d_c1[ED * 4];
__device__ float    d_c2[ED];
__device__ float    d_als1[NN * 4];
__device__ float    d_ald1[NN * 4];
__device__ float    d_ecsum[NN * 4];    // per-dst sums of ea.c1
__device__ float    d_ec2sum[NN];
__device__ float    d_ec2[ET];          // CSR order, ea.c2 (real slots only)
__device__ float    d_alpha1[(size_t)ET * 4];   // CSR order (real slots only)
__device__ float    d_tmp[(size_t)NN * 512];
__device__ float    d_out1[(size_t)NN * C1];
__device__ float    d_colsum1[C1];
__device__ float    d_colsq1[C1];
__device__ float    d_xs2[(size_t)NN * HID];
__device__ float    d_als2[NN];
__device__ float    d_ald2[NN];
__device__ float    d_out2[(size_t)NN * HID];
__device__ float    d_colsum2[HID];
__device__ float    d_colsq2[HID];
__device__ float    d_gate[NN];

// ------------------- helpers -------------------------------------------------
__device__ __forceinline__ ull pack2(float lo, float hi) {
    ull r;
    asm("mov.b64 %0, {%1, %2};" : "=l"(r) : "f"(lo), "f"(hi));
    return r;
}
__device__ __forceinline__ void unpack2(ull v, float& lo, float& hi) {
    asm("mov.b64 {%0, %1}, %2;" : "=f"(lo), "=f"(hi) : "l"(v));
}
__device__ __forceinline__ void fma2(ull& acc, ull a, ull b) {
    asm("fma.rn.f32x2 %0, %1, %2, %0;" : "+l"(acc) : "l"(a), "l"(b));
}
__device__ __forceinline__ float lrelu(float a) { return a > 0.f ? a : NEG * a; }

// ------------------- init (grid-wide) ------------------------------------------
__global__ void init0() {
    int i = blockIdx.x * blockDim.x + threadIdx.x;
    if (i < NN * 4) d_ecsum[i] = 0.f;
    if (i < NN) { d_deg[i] = 0; d_cursor[i] = 0; d_ec2sum[i] = 0.f; }
}

// ------------------- CSR build --------------------------------------------------
__global__ void hist_kernel(const int* __restrict__ dst) {
    int e = blockIdx.x * blockDim.x + threadIdx.x;
    if (e < EE) atomicAdd(&d_deg[dst[e]], 1);
}

__global__ void scan_kernel() {
    __shared__ int wsum[32];
    const int PER = 30;
    int t = threadIdx.x;
    if (t < C1) { d_colsum1[t] = 0.f; d_colsq1[t] = 0.f; }
    if (t < HID) { d_colsum2[t] = 0.f; d_colsq2[t] = 0.f; }
    int base = t * PER;
    int vals[PER];
    int s = 0;
#pragma unroll
    for (int i = 0; i < PER; i++) {
        int idx = base + i;
        vals[i] = (idx < NN) ? (d_deg[idx] + 1) : 0;   // +1 self loop (last slot)
        s += vals[i];
    }
    int lane = t & 31, w = t >> 5;
    int x = s;
#pragma unroll
    for (int off = 1; off < 32; off <<= 1) {
        int y = __shfl_up_sync(0xFFFFFFFFu, x, off);
        if (lane >= off) x += y;
    }
    if (lane == 31) wsum[w] = x;
    __syncthreads();
    if (w == 0) {
        int y = wsum[lane];
#pragma unroll
        for (int off = 1; off < 32; off <<= 1) {
            int z = __shfl_up_sync(0xFFFFFFFFu, y, off);
            if (lane >= off) y += z;
        }
        wsum[lane] = y;
    }
    __syncthreads();
    int excl = x - s + (w > 0 ? wsum[w - 1] : 0);
    int run = excl;
#pragma unroll
    for (int i = 0; i < PER; i++) {
        int idx = base + i;
        if (idx < NN) d_rowptr[idx] = run;
        run += vals[i];
    }
    if (t == 0) d_rowptr[NN] = ET;
}

// -------------- precompute small vectors (warp per output; 672 warps) ---------------
__global__ void __launch_bounds__(256) prep_par(
    const float* __restrict__ W1, const float* __restrict__ as1,
    const float* __restrict__ ad1,
    const float* __restrict__ We1, const float* __restrict__ ae1,
    const float* __restrict__ We2, const float* __restrict__ ae2) {
    int gw = blockIdx.x * 8 + (threadIdx.x >> 5);   // global warp id
    int lane = threadIdx.x & 31;
    if (gw < 512) {
        int h = gw >> 7, k = gw & 127;
        const float* wrow = W1 + (size_t)k * C1 + h * HID;
        const float* arow = as1 + h * HID;
        const float* drow = ad1 + h * HID;
        float w0 = wrow[lane], w1 = wrow[lane + 32];
        float s = w0 * arow[lane] + w1 * arow[lane + 32];
        float dv = w0 * drow[lane] + w1 * drow[lane + 32];
#pragma unroll
        for (int off = 16; off >= 1; off >>= 1) {
            s += __shfl_xor_sync(0xFFFFFFFFu, s, off);
            dv += __shfl_xor_sync(0xFFFFFFFFu, dv, off);
        }
        if (lane == 0) { d_vs1[gw] = s; d_vd1[gw] = dv; }
    } else if (gw < 640) {
        int idx = gw - 512;
        int k = idx >> 2, h = idx & 3;
        const float* wrow = We1 + (size_t)k * C1 + h * HID;
        const float* arow = ae1 + h * HID;
        float s = wrow[lane] * arow[lane] + wrow[lane + 32] * arow[lane + 32];
#pragma unroll
        for (int off = 16; off >= 1; off >>= 1)
            s += __shfl_xor_sync(0xFFFFFFFFu, s, off);
        if (lane == 0) d_c1[idx] = s;
    } else if (gw < 672) {
        int k = gw - 640;
        const float* wrow = We2 + (size_t)k * HID;
        float s = wrow[lane] * ae2[lane] + wrow[lane + 32] * ae2[lane + 32];
#pragma unroll
        for (int off = 16; off >= 1; off >>= 1)
            s += __shfl_xor_sync(0xFFFFFFFFu, s, off);
        if (lane == 0) d_c2[k] = s;
    }
}

// ------------------- node logits (layer 1) ---------------------------------------
__global__ void logits1(const float* __restrict__ x) {
    int gw = (blockIdx.x * blockDim.x + threadIdx.x) >> 5;
    int lane = threadIdx.x & 31;
    if (gw >= NN) return;
    float4 xv = ((const float4*)x)[(size_t)gw * 32 + lane];
    float r0, r1, r2, r3, q0, q1, q2, q3;
    {
        float4 v;
        v = ((const float4*)d_vs1)[0 * 32 + lane]; r0 = xv.x*v.x + xv.y*v.y + xv.z*v.z + xv.w*v.w;
        v = ((const float4*)d_vs1)[1 * 32 + lane]; r1 = xv.x*v.x + xv.y*v.y + xv.z*v.z + xv.w*v.w;
        v = ((const float4*)d_vs1)[2 * 32 + lane]; r2 = xv.x*v.x + xv.y*v.y + xv.z*v.z + xv.w*v.w;
        v = ((const float4*)d_vs1)[3 * 32 + lane]; r3 = xv.x*v.x + xv.y*v.y + xv.z*v.z + xv.w*v.w;
        v = ((const float4*)d_vd1)[0 * 32 + lane]; q0 = xv.x*v.x + xv.y*v.y + xv.z*v.z + xv.w*v.w;
        v = ((const float4*)d_vd1)[1 * 32 + lane]; q1 = xv.x*v.x + xv.y*v.y + xv.z*v.z + xv.w*v.w;
        v = ((const float4*)d_vd1)[2 * 32 + lane]; q2 = xv.x*v.x + xv.y*v.y + xv.z*v.z + xv.w*v.w;
        v = ((const float4*)d_vd1)[3 * 32 + lane]; q3 = xv.x*v.x + xv.y*v.y + xv.z*v.z + xv.w*v.w;
    }
#pragma unroll
    for (int off = 16; off >= 1; off >>= 1) {
        r0 += __shfl_xor_sync(0xFFFFFFFFu, r0, off);
        r1 += __shfl_xor_sync(0xFFFFFFFFu, r1, off);
        r2 += __shfl_xor_sync(0xFFFFFFFFu, r2, off);
        r3 += __shfl_xor_sync(0xFFFFFFFFu, r3, off);
        q0 += __shfl_xor_sync(0xFFFFFFFFu, q0, off);
        q1 += __shfl_xor_sync(0xFFFFFFFFu, q1, off);
        q2 += __shfl_xor_sync(0xFFFFFFFFu, q2, off);
        q3 += __shfl_xor_sync(0xFFFFFFFFu, q3, off);
    }
    if (lane == 0) {
        d_als1[gw * 4 + 0] = r0; d_als1[gw * 4 + 1] = r1;
        d_als1[gw * 4 + 2] = r2; d_als1[gw * 4 + 3] = r3;
        d_ald1[gw * 4 + 0] = q0; d_ald1[gw * 4 + 1] = q1;
        d_ald1[gw * 4 + 2] = q2; d_ald1[gw * 4 + 3] = q3;
    }
}

// --------- edge alphas: CSR slot assignment + alpha + ec sums in ONE pass -----------
__global__ void edge_alpha1(const float* __restrict__ ea, const int* __restrict__ src,
                            const int* __restrict__ dst) {
    int e = blockIdx.x * blockDim.x + threadIdx.x;
    if (e >= EE) return;
    int s = src[e], d = dst[e];
    const float4* row = (const float4*)(ea + (size_t)e * ED);
    float ec0 = 0.f, ec1 = 0.f, ec2 = 0.f, ec3 = 0.f, e2 = 0.f;
#pragma unroll
    for (int q = 0; q < 8; q++) {
        float4 v = __ldg(row + q);
        int k = q * 4;
        ec0 += v.x * d_c1[(k+0)*4+0] + v.y * d_c1[(k+1)*4+0] + v.z * d_c1[(k+2)*4+0] + v.w * d_c1[(k+3)*4+0];
        ec1 += v.x * d_c1[(k+0)*4+1] + v.y * d_c1[(k+1)*4+1] + v.z * d_c1[(k+2)*4+1] + v.w * d_c1[(k+3)*4+1];
        ec2 += v.x * d_c1[(k+0)*4+2] + v.y * d_c1[(k+1)*4+2] + v.z * d_c1[(k+2)*4+2] + v.w * d_c1[(k+3)*4+2];
        ec3 += v.x * d_c1[(k+0)*4+3] + v.y * d_c1[(k+1)*4+3] + v.z * d_c1[(k+2)*4+3] + v.w * d_c1[(k+3)*4+3];
        e2  += v.x * d_c2[k+0] + v.y * d_c2[k+1] + v.z * d_c2[k+2] + v.w * d_c2[k+3];
    }
    int p = d_rowptr[d] + atomicAdd(&d_cursor[d], 1);
    d_esrc[p] = s;
    d_ec2[p] = e2;
    float4 a;
    a.x = lrelu(d_als1[s * 4 + 0] + d_ald1[d * 4 + 0] + ec0);
    a.y = lrelu(d_als1[s * 4 + 1] + d_ald1[d * 4 + 1] + ec1);
    a.z = lrelu(d_als1[s * 4 + 2] + d_ald1[d * 4 + 2] + ec2);
    a.w = lrelu(d_als1[s * 4 + 3] + d_ald1[d * 4 + 3] + ec3);
    *(float4*)&d_alpha1[(size_t)p * 4] = a;
    atomicAdd(&d_ecsum[d * 4 + 0], ec0);
    atomicAdd(&d_ecsum[d * 4 + 1], ec1);
    atomicAdd(&d_ecsum[d * 4 + 2], ec2);
    atomicAdd(&d_ecsum[d * 4 + 3], ec3);
    atomicAdd(&d_ec2sum[d], e2);
}

// --------- gather layer1: warp per node, unshifted softmax (single pass) -------------
__global__ void __launch_bounds__(256) gather1w(const float* __restrict__ x) {
    int wid = threadIdx.x >> 5, lane = threadIdx.x & 31;
    int d = blockIdx.x * 8 + wid;   // NN % 8 == 0
    int r0 = d_rowptr[d], r1 = d_rowptr[d + 1];
    int LR = r1 - 1 - r0;           // real edges; slot r1-1 is self
    __shared__ __align__(16) float4 sex[8][32];
    __shared__ int ssrc[8][32];

    float inv = 1.0f / (float)(LR > 1 ? LR : 1);
    float4 es;
    es.x = __expf(lrelu(d_als1[d * 4 + 0] + d_ald1[d * 4 + 0] + d_ecsum[d * 4 + 0] * inv));
    es.y = __expf(lrelu(d_als1[d * 4 + 1] + d_ald1[d * 4 + 1] + d_ecsum[d * 4 + 1] * inv));
    es.z = __expf(lrelu(d_als1[d * 4 + 2] + d_ald1[d * 4 + 2] + d_ecsum[d * 4 + 2] * inv));
    es.w = __expf(lrelu(d_als1[d * 4 + 3] + d_ald1[d * 4 + 3] + d_ecsum[d * 4 + 3] * inv));

    float4 a0 = make_float4(0, 0, 0, 0), a1 = a0, a2 = a0, a3 = a0;
    float4 lsum = make_float4(0, 0, 0, 0);
    const float4* x4 = (const float4*)x;
    for (int c0 = r0; c0 < r0 + LR; c0 += 32) {
        int m = min(32, r0 + LR - c0);
        __syncwarp();
        if (lane < m) {
            float4 a = *(const float4*)&d_alpha1[(size_t)(c0 + lane) * 4];
            float4 e;
            e.x = __expf(a.x); e.y = __expf(a.y);
            e.z = __expf(a.z); e.w = __expf(a.w);
            sex[wid][lane] = e;
            ssrc[wid][lane] = d_esrc[c0 + lane];
            lsum.x += e.x; lsum.y += e.y; lsum.z += e.z; lsum.w += e.w;
        }
        __syncwarp();
        for (int j = 0; j < m; j++) {
            float4 xv = x4[(size_t)ssrc[wid][j] * 32 + lane];
            float4 e = sex[wid][j];
            a0.x += e.x * xv.x; a0.y += e.x * xv.y; a0.z += e.x * xv.z; a0.w += e.x * xv.w;
            a1.x += e.y * xv.x; a1.y += e.y * xv.y; a1.z += e.y * xv.z; a1.w += e.y * xv.w;
            a2.x += e.z * xv.x; a2.y += e.z * xv.y; a2.z += e.z * xv.z; a2.w += e.z * xv.w;
            a3.x += e.w * xv.x; a3.y += e.w * xv.y; a3.z += e.w * xv.z; a3.w += e.w * xv.w;
        }
    }
    // self-loop contribution
    {
        float4 xv = x4[(size_t)d * 32 + lane];
        a0.x += es.x * xv.x; a0.y += es.x * xv.y; a0.z += es.x * xv.z; a0.w += es.x * xv.w;
        a1.x += es.y * xv.x; a1.y += es.y * xv.y; a1.z += es.y * xv.z; a1.w += es.y * xv.w;
        a2.x += es.z * xv.x; a2.y += es.z * xv.y; a2.z += es.z * xv.z; a2.w += es.z * xv.w;
        a3.x += es.w * xv.x; a3.y += es.w * xv.y; a3.z += es.w * xv.z; a3.w += es.w * xv.w;
    }
#pragma unroll
    for (int off = 16; off >= 1; off >>= 1) {
        lsum.x += __shfl_xor_sync(0xFFFFFFFFu, lsum.x, off);
        lsum.y += __shfl_xor_sync(0xFFFFFFFFu, lsum.y, off);
        lsum.z += __shfl_xor_sync(0xFFFFFFFFu, lsum.z, off);
        lsum.w += __shfl_xor_sync(0xFFFFFFFFu, lsum.w, off);
    }
    lsum.x += es.x; lsum.y += es.y; lsum.z += es.z; lsum.w += es.w;
    float i0 = 1.0f / lsum.x, i1 = 1.0f / lsum.y, i2 = 1.0f / lsum.z, i3 = 1.0f / lsum.w;
    float4* tmp4 = (float4*)&d_tmp[(size_t)d * 512];
    tmp4[0 * 32 + lane] = make_float4(a0.x * i0, a0.y * i0, a0.z * i0, a0.w * i0);
    tmp4[1 * 32 + lane] = make_float4(a1.x * i1, a1.y * i1, a1.z * i1, a1.w * i1);
    tmp4[2 * 32 + lane] = make_float4(a2.x * i2, a2.y * i2, a2.z * i2, a2.w * i2);
    tmp4[3 * 32 + lane] = make_float4(a3.x * i3, a3.y * i3, a3.z * i3, a3.w * i3);
}

// ------------------- GEMM1: out1 = tmp(heads) @ W1 + b1, fused BN stats -------------
__global__ void __launch_bounds__(256) gemm1_stats(
    const float* __restrict__ A, const float* __restrict__ B,
    float* __restrict__ C, const float* __restrict__ bias) {
    const int BK = 16;
    __shared__ __align__(16) float As[BK][128 + 4];
    __shared__ __align__(16) float Bs[BK][64];
    __shared__ float reds[16][64];
    __shared__ float redq[16][64];
    int tid = threadIdx.x;
    int tx = tid & 15, ty = tid >> 4;
    int m0 = blockIdx.y * 128;
    const float* Ab = A + (size_t)blockIdx.x * 128;
    int bcol = blockIdx.x * 64;

    ull acc[4][4];
#pragma unroll
    for (int i = 0; i < 4; i++)
#pragma unroll
        for (int j = 0; j < 4; j++) acc[i][j] = 0ull;

    int ar = tid >> 1;
    int akb = (tid & 1) * 8;
    int gr_a = m0 + ar;
    int br = tid >> 4;
    int bc = (tid & 15) * 4;

    for (int k0 = 0; k0 < FIN; k0 += BK) {
        float4 a4a, a4b;
        if (gr_a < NN) {
            a4a = *(const float4*)&Ab[(size_t)gr_a * 512 + k0 + akb];
            a4b = *(const float4*)&Ab[(size_t)gr_a * 512 + k0 + akb + 4];
        } else {
            a4a = make_float4(0.f, 0.f, 0.f, 0.f);
            a4b = a4a;
        }
        As[akb + 0][ar] = a4a.x; As[akb + 1][ar] = a4a.y;
        As[akb + 2][ar] = a4a.z; As[akb + 3][ar] = a4a.w;
        As[akb + 4][ar] = a4b.x; As[akb + 5][ar] = a4b.y;
        As[akb + 6][ar] = a4b.z; As[akb + 7][ar] = a4b.w;
        *(float4*)&Bs[br][bc] = *(const float4*)&B[(size_t)(k0 + br) * C1 + bcol + bc];
        __syncthreads();
#pragma unroll
        for (int kk = 0; kk < BK; kk++) {
            ulonglong2 ap01 = *(const ulonglong2*)&As[kk][ty * 8];
            ulonglong2 ap23 = *(const ulonglong2*)&As[kk][ty * 8 + 4];
            float4 bq = *(const float4*)&Bs[kk][tx * 4];
            ull bb0 = pack2(bq.x, bq.x);
            ull bb1 = pack2(bq.y, bq.y);
            ull bb2 = pack2(bq.z, bq.z);
            ull bb3 = pack2(bq.w, bq.w);
            ull ap[4] = {ap01.x, ap01.y, ap23.x, ap23.y};
#pragma unroll
            for (int i = 0; i < 4; i++) {
                fma2(acc[i][0], ap[i], bb0);
                fma2(acc[i][1], ap[i], bb1);
                fma2(acc[i][2], ap[i], bb2);
                fma2(acc[i][3], ap[i], bb3);
            }
        }
        __syncthreads();
    }
    float4 bv = *(const float4*)&bias[bcol + tx * 4];
    float psum[4] = {0.f, 0.f, 0.f, 0.f};
    float psq[4]  = {0.f, 0.f, 0.f, 0.f};
#pragma unroll
    for (int i = 0; i < 4; i++) {
        float lo0, hi0, lo1, hi1, lo2, hi2, lo3, hi3;
        unpack2(acc[i][0], lo0, hi0);
        unpack2(acc[i][1], lo1, hi1);
        unpack2(acc[i][2], lo2, hi2);
        unpack2(acc[i][3], lo3, hi3);
        int r0 = m0 + ty * 8 + 2 * i;
        float y0 = lo0 + bv.x, y1 = lo1 + bv.y, y2 = lo2 + bv.z, y3 = lo3 + bv.w;
        float z0 = hi0 + bv.x, z1 = hi1 + bv.y, z2 = hi2 + bv.z, z3 = hi3 + bv.w;
        if (r0 < NN) {
            *(float4*)&C[(size_t)r0 * C1 + bcol + tx * 4] = make_float4(y0, y1, y2, y3);
            psum[0] += y0; psum[1] += y1; psum[2] += y2; psum[3] += y3;
            psq[0] += y0 * y0; psq[1] += y1 * y1; psq[2] += y2 * y2; psq[3] += y3 * y3;
        }
        if (r0 + 1 < NN) {
            *(float4*)&C[(size_t)(r0 + 1) * C1 + bcol + tx * 4] = make_float4(z0, z1, z2, z3);
            psum[0] += z0; psum[1] += z1; psum[2] += z2; psum[3] += z3;
            psq[0] += z0 * z0; psq[1] += z1 * z1; psq[2] += z2 * z2; psq[3] += z3 * z3;
        }
    }
#pragma unroll
    for (int c = 0; c < 4; c++) {
        reds[ty][tx * 4 + c] = psum[c];
        redq[ty][tx * 4 + c] = psq[c];
    }
    __syncthreads();
    if (tid < 64) {
        float s = 0.f, q = 0.f;
#pragma unroll
        for (int i = 0; i < 16; i++) { s += reds[i][tid]; q += redq[i][tid]; }
        atomicAdd(&d_colsum1[bcol + tid], s);
        atomicAdd(&d_colsq1[bcol + tid], q);
    }
}

// ------------------- GEMM2: xs2 = BNReLU(out1) @ W2, fused logits2 ------------------
__global__ void __launch_bounds__(256) gemm2_fused(
    const float* __restrict__ A, const float* __restrict__ B,
    float* __restrict__ C, const float* __restrict__ g1bn,
    const float* __restrict__ b1bn, const float* __restrict__ as2,
    const float* __restrict__ ad2) {
    const int BK = 16;
    __shared__ __align__(16) float As[BK][128 + 4];
    __shared__ __align__(16) float Bs[BK][64];
    __shared__ float sc[C1];
    __shared__ float sf[C1];
    int tid = threadIdx.x;
    int tx = tid & 15, ty = tid >> 4;
    int m0 = blockIdx.y * 128;

    {
        float mu = d_colsum1[tid] / (float)NN;
        float var = d_colsq1[tid] / (float)NN - mu * mu;
        float rs = rsqrtf(var + EPS) * g1bn[tid];
        sc[tid] = rs;
        sf[tid] = b1bn[tid] - mu * rs;
    }
    __syncthreads();

    ull acc[4][4];
#pragma unroll
    for (int i = 0; i < 4; i++)
#pragma unroll
        for (int j = 0; j < 4; j++) acc[i][j] = 0ull;

    int ar = tid >> 1;
    int akb = (tid & 1) * 8;
    int gr_a = m0 + ar;
    int br = tid >> 4;
    int bc = (tid & 15) * 4;

    for (int k0 = 0; k0 < C1; k0 += BK) {
        float4 a4a, a4b;
        if (gr_a < NN) {
            a4a = *(const float4*)&A[(size_t)gr_a * C1 + k0 + akb];
            a4b = *(const float4*)&A[(size_t)gr_a * C1 + k0 + akb + 4];
        } else {
            a4a = make_float4(0.f, 0.f, 0.f, 0.f);
            a4b = a4a;
        }
        int kb = k0 + akb;
        As[akb + 0][ar] = fmaxf(fmaf(a4a.x, sc[kb + 0], sf[kb + 0]), 0.f);
        As[akb + 1][ar] = fmaxf(fmaf(a4a.y, sc[kb + 1], sf[kb + 1]), 0.f);
        As[akb + 2][ar] = fmaxf(fmaf(a4a.z, sc[kb + 2], sf[kb + 2]), 0.f);
        As[akb + 3][ar] = fmaxf(fmaf(a4a.w, sc[kb + 3], sf[kb + 3]), 0.f);
        As[akb + 4][ar] = fmaxf(fmaf(a4b.x, sc[kb + 4], sf[kb + 4]), 0.f);
        As[akb + 5][ar] = fmaxf(fmaf(a4b.y, sc[kb + 5], sf[kb + 5]), 0.f);
        As[akb + 6][ar] = fmaxf(fmaf(a4b.z, sc[kb + 6], sf[kb + 6]), 0.f);
        As[akb + 7][ar] = fmaxf(fmaf(a4b.w, sc[kb + 7], sf[kb + 7]), 0.f);
        *(float4*)&Bs[br][bc] = *(const float4*)&B[(size_t)(k0 + br) * HID + bc];
        __syncthreads();
#pragma unroll
        for (int kk = 0; kk < BK; kk++) {
            ulonglong2 ap01 = *(const ulonglong2*)&As[kk][ty * 8];
            ulonglong2 ap23 = *(const ulonglong2*)&As[kk][ty * 8 + 4];
            float4 bq = *(const float4*)&Bs[kk][tx * 4];
            ull bb0 = pack2(bq.x, bq.x);
            ull bb1 = pack2(bq.y, bq.y);
            ull bb2 = pack2(bq.z, bq.z);
            ull bb3 = pack2(bq.w, bq.w);
            ull ap[4] = {ap01.x, ap01.y, ap23.x, ap23.y};
#pragma unroll
            for (int i = 0; i < 4; i++) {
                fma2(acc[i][0], ap[i], bb0);
                fma2(acc[i][1], ap[i], bb1);
                fma2(acc[i][2], ap[i], bb2);
                fma2(acc[i][3], ap[i], bb3);
            }
        }
        __syncthreads();
    }
    float4 av = *(const float4*)&as2[tx * 4];
    float4 dv = *(const float4*)&ad2[tx * 4];
    float ps8[8], pd8[8];
#pragma unroll
    for (int i = 0; i < 4; i++) {
        float lo0, hi0, lo1, hi1, lo2, hi2, lo3, hi3;
        unpack2(acc[i][0], lo0, hi0);
        unpack2(acc[i][1], lo1, hi1);
        unpack2(acc[i][2], lo2, hi2);
        unpack2(acc[i][3], lo3, hi3);
        int r0 = m0 + ty * 8 + 2 * i;
        if (r0 < NN)
            *(float4*)&C[(size_t)r0 * HID + tx * 4] = make_float4(lo0, lo1, lo2, lo3);
        if (r0 + 1 < NN)
            *(float4*)&C[(size_t)(r0 + 1) * HID + tx * 4] = make_float4(hi0, hi1, hi2, hi3);
        ps8[2 * i]     = lo0 * av.x + lo1 * av.y + lo2 * av.z + lo3 * av.w;
        ps8[2 * i + 1] = hi0 * av.x + hi1 * av.y + hi2 * av.z + hi3 * av.w;
        pd8[2 * i]     = lo0 * dv.x + lo1 * dv.y + lo2 * dv.z + lo3 * dv.w;
        pd8[2 * i + 1] = hi0 * dv.x + hi1 * dv.y + hi2 * dv.z + hi3 * dv.w;
    }
    float* red = &As[0][0];
    __syncthreads();
#pragma unroll
    for (int i = 0; i < 8; i++) red[(ty * 8 + i) * 16 + tx] = ps8[i];
    __syncthreads();
    if (tid < 128 && m0 + tid < NN) {
        float s = 0.f;
#pragma unroll
        for (int j = 0; j < 16; j++) s += red[tid * 16 + j];
        d_als2[m0 + tid] = s;
    }
    __syncthreads();
#pragma unroll
    for (int i = 0; i < 8; i++) red[(ty * 8 + i) * 16 + tx] = pd8[i];
    __syncthreads();
    if (tid < 128 && m0 + tid < NN) {
        float s = 0.f;
#pragma unroll
        for (int j = 0; j < 16; j++) s += red[tid * 16 + j];
        d_ald2[m0 + tid] = s;
    }
}

// ------- gather layer2: warp per node, single pass, fused BN2 stats ------------------
__global__ void __launch_bounds__(256) gather2w(const float* __restrict__ bias) {
    int wid = threadIdx.x >> 5, lane = threadIdx.x & 31;
    int d = blockIdx.x * 8 + wid;   // NN % 8 == 0, all warps active
    int r0 = d_rowptr[d], r1 = d_rowptr[d + 1];
    int LR = r1 - 1 - r0;
    __shared__ float sex[8][32];
    __shared__ int ssrc[8][32];
    __shared__ float s2v[8][64];
    float ald = d_ald2[d];
    float inv = 1.0f / (float)(LR > 1 ? LR : 1);
    float es = __expf(lrelu(d_als2[d] + ald + d_ec2sum[d] * inv));

    float2 acc = make_float2(0.f, 0.f);
    float lsum = 0.f;
    const float2* x2 = (const float2*)d_xs2;
    for (int c0 = r0; c0 < r0 + LR; c0 += 32) {
        int m = min(32, r0 + LR - c0);
        __syncwarp();
        if (lane < m) {
            int p = c0 + lane;
            int s = d_esrc[p];
            float e = __expf(lrelu(d_als2[s] + ald + d_ec2[p]));
            sex[wid][lane] = e;
            ssrc[wid][lane] = s;
            lsum += e;
        }
        __syncwarp();
        for (int j = 0; j < m; j++) {
            float2 xv = x2[(size_t)ssrc[wid][j] * 32 + lane];
            float e = sex[wid][j];
            acc.x += e * xv.x;
            acc.y += e * xv.y;
        }
    }
    {
        float2 xv = x2[(size_t)d * 32 + lane];
        acc.x += es * xv.x;
        acc.y += es * xv.y;
    }
#pragma unroll
    for (int off = 16; off >= 1; off >>= 1)
        lsum += __shfl_xor_sync(0xFFFFFFFFu, lsum, off);
    lsum += es;
    float sinv = 1.0f / lsum;
    float2 bv = ((const float2*)bias)[lane];
    float y0 = acc.x * sinv + bv.x;
    float y1 = acc.y * sinv + bv.y;
    ((float2*)d_out2)[(size_t)d * 32 + lane] = make_float2(y0, y1);
    // fused BN2 stats
    s2v[wid][lane * 2]     = y0;
    s2v[wid][lane * 2 + 1] = y1;
    __syncthreads();
    int t = threadIdx.x;
    if (t < 64) {
        float s = 0.f, q = 0.f;
#pragma unroll
        for (int r = 0; r < 8; r++) {
            float v = s2v[r][t];
            s += v;
            q += v * v;
        }
        atomicAdd(&d_colsum2[t], s);
        atomicAdd(&d_colsq2[t], q);
    }
}

// ------------------- gate (applies BN2+ReLU in place) ---------------------------------
__global__ void gate_bn(const float* __restrict__ g2, const float* __restrict__ b2,
                        const float* __restrict__ Wg, const float* __restrict__ bg) {
    int n = (blockIdx.x * blockDim.x + threadIdx.x) >> 5;
    int lane = threadIdx.x & 31;
    if (n >= NN) return;
    int c0 = lane * 2, c1 = c0 + 1;
    float2 v = ((const float2*)d_out2)[(size_t)n * 32 + lane];
    float mu0 = d_colsum2[c0] / (float)NN;
    float var0 = d_colsq2[c0] / (float)NN - mu0 * mu0;
    float y0 = fmaxf((v.x - mu0) * rsqrtf(var0 + EPS) * __ldg(g2 + c0) + __ldg(b2 + c0), 0.f);
    float mu1 = d_colsum2[c1] / (float)NN;
    float var1 = d_colsq2[c1] / (float)NN - mu1 * mu1;
    float y1 = fmaxf((v.y - mu1) * rsqrtf(var1 + EPS) * __ldg(g2 + c1) + __ldg(b2 + c1), 0.f);
    ((float2*)d_out2)[(size_t)n * 32 + lane] = make_float2(y0, y1);
    float g = y0 * __ldg(Wg + c0) + y1 * __ldg(Wg + c1);
#pragma unroll
    for (int off = 16; off >= 1; off >>= 1)
        g += __shfl_xor_sync(0xFFFFFFFFu, g, off);
    if (lane == 0) d_gate[n] = g + bg[0];
}

// ------------------- pooling (256 threads; unshifted softmax) ---------------------------
__device__ __forceinline__ int lbound(const int* a, int n, int v) {
    int lo = 0, hi = n;
    while (lo < hi) {
        int mid = (lo + hi) >> 1;
        if (a[mid] < v) lo = mid + 1; else hi = mid;
    }
    return lo;
}

__global__ void __launch_bounds__(256) pool_kernel(const int* __restrict__ batch,
                                                   float* __restrict__ out) {
    int b = blockIdx.x, t = threadIdx.x;
    int c = t & 63, sub = t >> 6;   // 4 subgroups of 64 channels
    __shared__ int slo, shi;
    __shared__ float red[256];
    __shared__ float sh_w[64];
    __shared__ float facc[4][64];
    if (t == 0) { slo = lbound(batch, NN, b); shi = lbound(batch, NN, b + 1); }
    __syncthreads();
    int lo = slo, hi = shi;
    if (hi <= lo) { if (t < 64) out[b * 64 + c] = 0.f; return; }
    // sum of exp (unshifted; gate values O(1))
    float ts = 0.f;
    for (int n = lo + t; n < hi; n += 256) ts += __expf(d_gate[n]);
    red[t] = ts;
    __syncthreads();
#pragma unroll
    for (int off = 128; off >= 1; off >>= 1) {
        if (t < off) red[t] += red[t + off];
        __syncthreads();
    }
    float sinv = 1.0f / red[0];
    // weighted accumulate, 4 nodes in flight
    float acc = 0.f;
    for (int base = lo; base < hi; base += 64) {
        int mcnt = min(64, hi - base);
        __syncthreads();
        if (t < mcnt) sh_w[t] = __expf(d_gate[base + t]);
        __syncthreads();
        for (int j = sub; j < mcnt; j += 4)
            acc += sh_w[j] * d_out2[(size_t)(base + j) * 64 + c];
    }
    facc[sub][c] = acc;
    __syncthreads();
    if (t < 64) {
        float v = facc[0][t] + facc[1][t] + facc[2][t] + facc[3][t];
        out[b * 64 + t] = v * sinv;
    }
}

// ------------------- launch ----------------------------------------------------------------
static inline int gdiv(long long a, int b) { return (int)((a + b - 1) / b); }

extern "C" void kernel_launch(void* const* d_in, const int* in_sizes, int n_in,
                              void* d_out, int out_size) {
    const float* x     = (const float*)d_in[0];
    const float* ea    = (const float*)d_in[1];
    const int*   ei    = (const int*)d_in[2];
    const int*   batch = (const int*)d_in[3];
    const float* W1    = (const float*)d_in[4];
    const float* We1   = (const float*)d_in[5];
    const float* as1   = (const float*)d_in[6];
    const float* ad1   = (const float*)d_in[7];
    const float* ae1   = (const float*)d_in[8];
    const float* b1    = (const float*)d_in[9];
    const float* g1    = (const float*)d_in[10];
    const float* bb1   = (const float*)d_in[11];
    const float* W2    = (const float*)d_in[12];
    const float* We2   = (const float*)d_in[13];
    const float* as2   = (const float*)d_in[14];
    const float* ad2   = (const float*)d_in[15];
    const float* ae2   = (const float*)d_in[16];
    const float* b2    = (const float*)d_in[17];
    const float* g2    = (const float*)d_in[18];
    const float* bb2   = (const float*)d_in[19];
    const float* Wg    = (const float*)d_in[20];
    const float* bg    = (const float*)d_in[21];
    float* out = (float*)d_out;

    const int* src = ei;
    const int* dst = ei + EE;

    float* p_tmp;  cudaGetSymbolAddress((void**)&p_tmp, d_tmp);
    float* p_out1; cudaGetSymbolAddress((void**)&p_out1, d_out1);
    float* p_xs2;  cudaGetSymbolAddress((void**)&p_xs2, d_xs2);

    init0<<<gdiv(NN * 4, 256), 256>>>();
    hist_kernel<<<gdiv(EE, 256), 256>>>(dst);
    scan_kernel<<<1, 1024>>>();
    prep_par<<<84, 256>>>(W1, as1, ad1, We1, ae1, We2, ae2);
    logits1<<<gdiv((long long)NN * 32, 256), 256>>>(x);
    edge_alpha1<<<gdiv(EE, 256), 256>>>(ea, src, dst);
    gather1w<<<gdiv(NN, 8), 256>>>(x);
    {
        dim3 g(4, gdiv(NN, 128));
        gemm1_stats<<<g, 256>>>(p_tmp, W1, p_out1, b1);
    }
    {
        dim3 g(1, gdiv(NN, 128));
        gemm2_fused<<<g, 256>>>(p_out1, W2, p_xs2, g1, bb1, as2, ad2);
    }
    gather2w<<<gdiv(NN, 8), 256>>>(b2);
    gate_bn<<<gdiv((long long)NN * 32, 256), 256>>>(g2, bb2, Wg, bg);
    pool_kernel<<<BB, 256>>>(batch, out);
}

// round 15
// speedup vs baseline: 1.2277x; 1.0133x over previous
#include <cuda_runtime.h>
#include <math_constants.h>

#define NN 30000
#define EE 480000
#define ET (EE + NN)
#define BB 64
#define FIN 128
#define HID 64
#define ED 32
#define C1 256
#define NEG 0.2f
#define EPS 1e-5f

typedef unsigned long long ull;

// ------------------- scratch -------------------------------------------------
__device__ int      d_deg[NN];          // real in-degree
__device__ int      d_rowptr[NN + 1];
__device__ int      d_cursor[NN];
__device__ int      d_esrc[ET];

__device__ float    d_vs1[512];
__device__ float    d_vd1[512];
__device__ float    d_c1[ED * 4];
__device__ float    d_c2[ED];
__device__ float    d_als1[NN * 4];
__device__ float    d_ald1[NN * 4];
__device__ float    d_ecsum[NN * 4];    // per-dst sums of ea.c1
__device__ float    d_ec2sum[NN];
__device__ float    d_ec2[ET];          // CSR order, ea.c2 (real slots only)
__device__ float    d_alpha1[(size_t)ET * 4];   // CSR order: exp(lrelu(alpha))
__device__ float    d_tmp[(size_t)NN * 512];
__device__ float    d_out1[(size_t)NN * C1];
__device__ float    d_colsum1[C1];
__device__ float    d_colsq1[C1];
__device__ float    d_xs2[(size_t)NN * HID];
__device__ float    d_als2[NN];
__device__ float    d_ald2[NN];
__device__ float    d_out2[(size_t)NN * HID];
__device__ float    d_colsum2[HID];
__device__ float    d_colsq2[HID];
__device__ float    d_gate[NN];

// ------------------- helpers -------------------------------------------------
__device__ __forceinline__ ull pack2(float lo, float hi) {
    ull r;
    asm("mov.b64 %0, {%1, %2};" : "=l"(r) : "f"(lo), "f"(hi));
    return r;
}
__device__ __forceinline__ void unpack2(ull v, float& lo, float& hi) {
    asm("mov.b64 {%0, %1}, %2;" : "=f"(lo), "=f"(hi) : "l"(v));
}
__device__ __forceinline__ void fma2(ull& acc, ull a, ull b) {
    asm("fma.rn.f32x2 %0, %1, %2, %0;" : "+l"(acc) : "l"(a), "l"(b));
}
__device__ __forceinline__ float lrelu(float a) { return a > 0.f ? a : NEG * a; }

// ------------------- init (grid-wide) ------------------------------------------
__global__ void init0() {
    int i = blockIdx.x * blockDim.x + threadIdx.x;
    if (i < NN * 4) d_ecsum[i] = 0.f;
    if (i < NN) { d_deg[i] = 0; d_cursor[i] = 0; d_ec2sum[i] = 0.f; }
}

// ------------------- CSR build --------------------------------------------------
__global__ void hist_kernel(const int* __restrict__ dst) {
    int e = blockIdx.x * blockDim.x + threadIdx.x;
    if (e < EE) atomicAdd(&d_deg[dst[e]], 1);
}

__global__ void scan_kernel() {
    __shared__ int wsum[32];
    const int PER = 30;
    int t = threadIdx.x;
    if (t < C1) { d_colsum1[t] = 0.f; d_colsq1[t] = 0.f; }
    if (t < HID) { d_colsum2[t] = 0.f; d_colsq2[t] = 0.f; }
    int base = t * PER;
    int vals[PER];
    int s = 0;
#pragma unroll
    for (int i = 0; i < PER; i++) {
        int idx = base + i;
        vals[i] = (idx < NN) ? (d_deg[idx] + 1) : 0;   // +1 self loop (last slot)
        s += vals[i];
    }
    int lane = t & 31, w = t >> 5;
    int x = s;
#pragma unroll
    for (int off = 1; off < 32; off <<= 1) {
        int y = __shfl_up_sync(0xFFFFFFFFu, x, off);
        if (lane >= off) x += y;
    }
    if (lane == 31) wsum[w] = x;
    __syncthreads();
    if (w == 0) {
        int y = wsum[lane];
#pragma unroll
        for (int off = 1; off < 32; off <<= 1) {
            int z = __shfl_up_sync(0xFFFFFFFFu, y, off);
            if (lane >= off) y += z;
        }
        wsum[lane] = y;
    }
    __syncthreads();
    int excl = x - s + (w > 0 ? wsum[w - 1] : 0);
    int run = excl;
#pragma unroll
    for (int i = 0; i < PER; i++) {
        int idx = base + i;
        if (idx < NN) d_rowptr[idx] = run;
        run += vals[i];
    }
    if (t == 0) d_rowptr[NN] = ET;
}

// -------------- precompute small vectors (warp per output; 672 warps) ---------------
__global__ void __launch_bounds__(256) prep_par(
    const float* __restrict__ W1, const float* __restrict__ as1,
    const float* __restrict__ ad1,
    const float* __restrict__ We1, const float* __restrict__ ae1,
    const float* __restrict__ We2, const float* __restrict__ ae2) {
    int gw = blockIdx.x * 8 + (threadIdx.x >> 5);   // global warp id
    int lane = threadIdx.x & 31;
    if (gw < 512) {
        int h = gw >> 7, k = gw & 127;
        const float* wrow = W1 + (size_t)k * C1 + h * HID;
        const float* arow = as1 + h * HID;
        const float* drow = ad1 + h * HID;
        float w0 = wrow[lane], w1 = wrow[lane + 32];
        float s = w0 * arow[lane] + w1 * arow[lane + 32];
        float dv = w0 * drow[lane] + w1 * drow[lane + 32];
#pragma unroll
        for (int off = 16; off >= 1; off >>= 1) {
            s += __shfl_xor_sync(0xFFFFFFFFu, s, off);
            dv += __shfl_xor_sync(0xFFFFFFFFu, dv, off);
        }
        if (lane == 0) { d_vs1[gw] = s; d_vd1[gw] = dv; }
    } else if (gw < 640) {
        int idx = gw - 512;
        int k = idx >> 2, h = idx & 3;
        const float* wrow = We1 + (size_t)k * C1 + h * HID;
        const float* arow = ae1 + h * HID;
        float s = wrow[lane] * arow[lane] + wrow[lane + 32] * arow[lane + 32];
#pragma unroll
        for (int off = 16; off >= 1; off >>= 1)
            s += __shfl_xor_sync(0xFFFFFFFFu, s, off);
        if (lane == 0) d_c1[idx] = s;
    } else if (gw < 672) {
        int k = gw - 640;
        const float* wrow = We2 + (size_t)k * HID;
        float s = wrow[lane] * ae2[lane] + wrow[lane + 32] * ae2[lane + 32];
#pragma unroll
        for (int off = 16; off >= 1; off >>= 1)
            s += __shfl_xor_sync(0xFFFFFFFFu, s, off);
        if (lane == 0) d_c2[k] = s;
    }
}

// ------------------- node logits (layer 1) ---------------------------------------
__global__ void logits1(const float* __restrict__ x) {
    int gw = (blockIdx.x * blockDim.x + threadIdx.x) >> 5;
    int lane = threadIdx.x & 31;
    if (gw >= NN) return;
    float4 xv = ((const float4*)x)[(size_t)gw * 32 + lane];
    float r0, r1, r2, r3, q0, q1, q2, q3;
    {
        float4 v;
        v = ((const float4*)d_vs1)[0 * 32 + lane]; r0 = xv.x*v.x + xv.y*v.y + xv.z*v.z + xv.w*v.w;
        v = ((const float4*)d_vs1)[1 * 32 + lane]; r1 = xv.x*v.x + xv.y*v.y + xv.z*v.z + xv.w*v.w;
        v = ((const float4*)d_vs1)[2 * 32 + lane]; r2 = xv.x*v.x + xv.y*v.y + xv.z*v.z + xv.w*v.w;
        v = ((const float4*)d_vs1)[3 * 32 + lane]; r3 = xv.x*v.x + xv.y*v.y + xv.z*v.z + xv.w*v.w;
        v = ((const float4*)d_vd1)[0 * 32 + lane]; q0 = xv.x*v.x + xv.y*v.y + xv.z*v.z + xv.w*v.w;
        v = ((const float4*)d_vd1)[1 * 32 + lane]; q1 = xv.x*v.x + xv.y*v.y + xv.z*v.z + xv.w*v.w;
        v = ((const float4*)d_vd1)[2 * 32 + lane]; q2 = xv.x*v.x + xv.y*v.y + xv.z*v.z + xv.w*v.w;
        v = ((const float4*)d_vd1)[3 * 32 + lane]; q3 = xv.x*v.x + xv.y*v.y + xv.z*v.z + xv.w*v.w;
    }
#pragma unroll
    for (int off = 16; off >= 1; off >>= 1) {
        r0 += __shfl_xor_sync(0xFFFFFFFFu, r0, off);
        r1 += __shfl_xor_sync(0xFFFFFFFFu, r1, off);
        r2 += __shfl_xor_sync(0xFFFFFFFFu, r2, off);
        r3 += __shfl_xor_sync(0xFFFFFFFFu, r3, off);
        q0 += __shfl_xor_sync(0xFFFFFFFFu, q0, off);
        q1 += __shfl_xor_sync(0xFFFFFFFFu, q1, off);
        q2 += __shfl_xor_sync(0xFFFFFFFFu, q2, off);
        q3 += __shfl_xor_sync(0xFFFFFFFFu, q3, off);
    }
    if (lane == 0) {
        d_als1[gw * 4 + 0] = r0; d_als1[gw * 4 + 1] = r1;
        d_als1[gw * 4 + 2] = r2; d_als1[gw * 4 + 3] = r3;
        d_ald1[gw * 4 + 0] = q0; d_ald1[gw * 4 + 1] = q1;
        d_ald1[gw * 4 + 2] = q2; d_ald1[gw * 4 + 3] = q3;
    }
}

// --------- edge alphas: slot assign + exp(lrelu(alpha)) + ec sums in ONE pass --------
__global__ void edge_alpha1(const float* __restrict__ ea, const int* __restrict__ src,
                            const int* __restrict__ dst) {
    int e = blockIdx.x * blockDim.x + threadIdx.x;
    if (e >= EE) return;
    int s = src[e], d = dst[e];
    const float4* row = (const float4*)(ea + (size_t)e * ED);
    float ec0 = 0.f, ec1 = 0.f, ec2 = 0.f, ec3 = 0.f, e2 = 0.f;
#pragma unroll
    for (int q = 0; q < 8; q++) {
        float4 v = __ldg(row + q);
        int k = q * 4;
        ec0 += v.x * d_c1[(k+0)*4+0] + v.y * d_c1[(k+1)*4+0] + v.z * d_c1[(k+2)*4+0] + v.w * d_c1[(k+3)*4+0];
        ec1 += v.x * d_c1[(k+0)*4+1] + v.y * d_c1[(k+1)*4+1] + v.z * d_c1[(k+2)*4+1] + v.w * d_c1[(k+3)*4+1];
        ec2 += v.x * d_c1[(k+0)*4+2] + v.y * d_c1[(k+1)*4+2] + v.z * d_c1[(k+2)*4+2] + v.w * d_c1[(k+3)*4+2];
        ec3 += v.x * d_c1[(k+0)*4+3] + v.y * d_c1[(k+1)*4+3] + v.z * d_c1[(k+2)*4+3] + v.w * d_c1[(k+3)*4+3];
        e2  += v.x * d_c2[k+0] + v.y * d_c2[k+1] + v.z * d_c2[k+2] + v.w * d_c2[k+3];
    }
    int p = d_rowptr[d] + atomicAdd(&d_cursor[d], 1);
    d_esrc[p] = s;
    d_ec2[p] = e2;
    float4 a;
    a.x = __expf(lrelu(d_als1[s * 4 + 0] + d_ald1[d * 4 + 0] + ec0));
    a.y = __expf(lrelu(d_als1[s * 4 + 1] + d_ald1[d * 4 + 1] + ec1));
    a.z = __expf(lrelu(d_als1[s * 4 + 2] + d_ald1[d * 4 + 2] + ec2));
    a.w = __expf(lrelu(d_als1[s * 4 + 3] + d_ald1[d * 4 + 3] + ec3));
    *(float4*)&d_alpha1[(size_t)p * 4] = a;
    atomicAdd(&d_ecsum[d * 4 + 0], ec0);
    atomicAdd(&d_ecsum[d * 4 + 1], ec1);
    atomicAdd(&d_ecsum[d * 4 + 2], ec2);
    atomicAdd(&d_ecsum[d * 4 + 3], ec3);
    atomicAdd(&d_ec2sum[d], e2);
}

// --------- gather layer1: warp per node, 2x unrolled inner (MLP=2) -------------------
__global__ void __launch_bounds__(256) gather1w(const float* __restrict__ x) {
    int wid = threadIdx.x >> 5, lane = threadIdx.x & 31;
    int d = blockIdx.x * 8 + wid;   // NN % 8 == 0
    int r0 = d_rowptr[d], r1 = d_rowptr[d + 1];
    int LR = r1 - 1 - r0;           // real edges; slot r1-1 is self
    __shared__ __align__(16) float4 sex[8][32];
    __shared__ int ssrc[8][32];

    float inv = 1.0f / (float)(LR > 1 ? LR : 1);
    float4 es;
    es.x = __expf(lrelu(d_als1[d * 4 + 0] + d_ald1[d * 4 + 0] + d_ecsum[d * 4 + 0] * inv));
    es.y = __expf(lrelu(d_als1[d * 4 + 1] + d_ald1[d * 4 + 1] + d_ecsum[d * 4 + 1] * inv));
    es.z = __expf(lrelu(d_als1[d * 4 + 2] + d_ald1[d * 4 + 2] + d_ecsum[d * 4 + 2] * inv));
    es.w = __expf(lrelu(d_als1[d * 4 + 3] + d_ald1[d * 4 + 3] + d_ecsum[d * 4 + 3] * inv));

    float4 a0 = make_float4(0, 0, 0, 0), a1 = a0, a2 = a0, a3 = a0;
    float4 lsum = make_float4(0, 0, 0, 0);
    const float4* x4 = (const float4*)x;
    for (int c0 = r0; c0 < r0 + LR; c0 += 32) {
        int m = min(32, r0 + LR - c0);
        __syncwarp();
        if (lane < m) {
            float4 e = *(const float4*)&d_alpha1[(size_t)(c0 + lane) * 4];  // exp'd
            sex[wid][lane] = e;
            ssrc[wid][lane] = d_esrc[c0 + lane];
            lsum.x += e.x; lsum.y += e.y; lsum.z += e.z; lsum.w += e.w;
        }
        __syncwarp();
        int j = 0;
        for (; j + 2 <= m; j += 2) {
            float4 xv0 = x4[(size_t)ssrc[wid][j] * 32 + lane];
            float4 xv1 = x4[(size_t)ssrc[wid][j + 1] * 32 + lane];
            float4 e0 = sex[wid][j];
            float4 e1 = sex[wid][j + 1];
            a0.x += e0.x * xv0.x; a0.y += e0.x * xv0.y; a0.z += e0.x * xv0.z; a0.w += e0.x * xv0.w;
            a1.x += e0.y * xv0.x; a1.y += e0.y * xv0.y; a1.z += e0.y * xv0.z; a1.w += e0.y * xv0.w;
            a2.x += e0.z * xv0.x; a2.y += e0.z * xv0.y; a2.z += e0.z * xv0.z; a2.w += e0.z * xv0.w;
            a3.x += e0.w * xv0.x; a3.y += e0.w * xv0.y; a3.z += e0.w * xv0.z; a3.w += e0.w * xv0.w;
            a0.x += e1.x * xv1.x; a0.y += e1.x * xv1.y; a0.z += e1.x * xv1.z; a0.w += e1.x * xv1.w;
            a1.x += e1.y * xv1.x; a1.y += e1.y * xv1.y; a1.z += e1.y * xv1.z; a1.w += e1.y * xv1.w;
            a2.x += e1.z * xv1.x; a2.y += e1.z * xv1.y; a2.z += e1.z * xv1.z; a2.w += e1.z * xv1.w;
            a3.x += e1.w * xv1.x; a3.y += e1.w * xv1.y; a3.z += e1.w * xv1.z; a3.w += e1.w * xv1.w;
        }
        if (j < m) {
            float4 xv = x4[(size_t)ssrc[wid][j] * 32 + lane];
            float4 e = sex[wid][j];
            a0.x += e.x * xv.x; a0.y += e.x * xv.y; a0.z += e.x * xv.z; a0.w += e.x * xv.w;
            a1.x += e.y * xv.x; a1.y += e.y * xv.y; a1.z += e.y * xv.z; a1.w += e.y * xv.w;
            a2.x += e.z * xv.x; a2.y += e.z * xv.y; a2.z += e.z * xv.z; a2.w += e.z * xv.w;
            a3.x += e.w * xv.x; a3.y += e.w * xv.y; a3.z += e.w * xv.z; a3.w += e.w * xv.w;
        }
    }
    // self-loop contribution
    {
        float4 xv = x4[(size_t)d * 32 + lane];
        a0.x += es.x * xv.x; a0.y += es.x * xv.y; a0.z += es.x * xv.z; a0.w += es.x * xv.w;
        a1.x += es.y * xv.x; a1.y += es.y * xv.y; a1.z += es.y * xv.z; a1.w += es.y * xv.w;
        a2.x += es.z * xv.x; a2.y += es.z * xv.y; a2.z += es.z * xv.z; a2.w += es.z * xv.w;
        a3.x += es.w * xv.x; a3.y += es.w * xv.y; a3.z += es.w * xv.z; a3.w += es.w * xv.w;
    }
#pragma unroll
    for (int off = 16; off >= 1; off >>= 1) {
        lsum.x += __shfl_xor_sync(0xFFFFFFFFu, lsum.x, off);
        lsum.y += __shfl_xor_sync(0xFFFFFFFFu, lsum.y, off);
        lsum.z += __shfl_xor_sync(0xFFFFFFFFu, lsum.z, off);
        lsum.w += __shfl_xor_sync(0xFFFFFFFFu, lsum.w, off);
    }
    lsum.x += es.x; lsum.y += es.y; lsum.z += es.z; lsum.w += es.w;
    float i0 = 1.0f / lsum.x, i1 = 1.0f / lsum.y, i2 = 1.0f / lsum.z, i3 = 1.0f / lsum.w;
    float4* tmp4 = (float4*)&d_tmp[(size_t)d * 512];
    tmp4[0 * 32 + lane] = make_float4(a0.x * i0, a0.y * i0, a0.z * i0, a0.w * i0);
    tmp4[1 * 32 + lane] = make_float4(a1.x * i1, a1.y * i1, a1.z * i1, a1.w * i1);
    tmp4[2 * 32 + lane] = make_float4(a2.x * i2, a2.y * i2, a2.z * i2, a2.w * i2);
    tmp4[3 * 32 + lane] = make_float4(a3.x * i3, a3.y * i3, a3.z * i3, a3.w * i3);
}

// ------------------- GEMM1: out1 = tmp(heads) @ W1 + b1, fused BN stats -------------
__global__ void __launch_bounds__(256) gemm1_stats(
    const float* __restrict__ A, const float* __restrict__ B,
    float* __restrict__ C, const float* __restrict__ bias) {
    const int BK = 16;
    __shared__ __align__(16) float As[BK][128 + 4];
    __shared__ __align__(16) float Bs[BK][64];
    __shared__ float reds[16][64];
    __shared__ float redq[16][64];
    int tid = threadIdx.x;
    int tx = tid & 15, ty = tid >> 4;
    int m0 = blockIdx.y * 128;
    const float* Ab = A + (size_t)blockIdx.x * 128;
    int bcol = blockIdx.x * 64;

    ull acc[4][4];
#pragma unroll
    for (int i = 0; i < 4; i++)
#pragma unroll
        for (int j = 0; j < 4; j++) acc[i][j] = 0ull;

    int ar = tid >> 1;
    int akb = (tid & 1) * 8;
    int gr_a = m0 + ar;
    int br = tid >> 4;
    int bc = (tid & 15) * 4;

    for (int k0 = 0; k0 < FIN; k0 += BK) {
        float4 a4a, a4b;
        if (gr_a < NN) {
            a4a = *(const float4*)&Ab[(size_t)gr_a * 512 + k0 + akb];
            a4b = *(const float4*)&Ab[(size_t)gr_a * 512 + k0 + akb + 4];
        } else {
            a4a = make_float4(0.f, 0.f, 0.f, 0.f);
            a4b = a4a;
        }
        As[akb + 0][ar] = a4a.x; As[akb + 1][ar] = a4a.y;
        As[akb + 2][ar] = a4a.z; As[akb + 3][ar] = a4a.w;
        As[akb + 4][ar] = a4b.x; As[akb + 5][ar] = a4b.y;
        As[akb + 6][ar] = a4b.z; As[akb + 7][ar] = a4b.w;
        *(float4*)&Bs[br][bc] = *(const float4*)&B[(size_t)(k0 + br) * C1 + bcol + bc];
        __syncthreads();
#pragma unroll
        for (int kk = 0; kk < BK; kk++) {
            ulonglong2 ap01 = *(const ulonglong2*)&As[kk][ty * 8];
            ulonglong2 ap23 = *(const ulonglong2*)&As[kk][ty * 8 + 4];
            float4 bq = *(const float4*)&Bs[kk][tx * 4];
            ull bb0 = pack2(bq.x, bq.x);
            ull bb1 = pack2(bq.y, bq.y);
            ull bb2 = pack2(bq.z, bq.z);
            ull bb3 = pack2(bq.w, bq.w);
            ull ap[4] = {ap01.x, ap01.y, ap23.x, ap23.y};
#pragma unroll
            for (int i = 0; i < 4; i++) {
                fma2(acc[i][0], ap[i], bb0);
                fma2(acc[i][1], ap[i], bb1);
                fma2(acc[i][2], ap[i], bb2);
                fma2(acc[i][3], ap[i], bb3);
            }
        }
        __syncthreads();
    }
    float4 bv = *(const float4*)&bias[bcol + tx * 4];
    float psum[4] = {0.f, 0.f, 0.f, 0.f};
    float psq[4]  = {0.f, 0.f, 0.f, 0.f};
#pragma unroll
    for (int i = 0; i < 4; i++) {
        float lo0, hi0, lo1, hi1, lo2, hi2, lo3, hi3;
        unpack2(acc[i][0], lo0, hi0);
        unpack2(acc[i][1], lo1, hi1);
        unpack2(acc[i][2], lo2, hi2);
        unpack2(acc[i][3], lo3, hi3);
        int r0 = m0 + ty * 8 + 2 * i;
        float y0 = lo0 + bv.x, y1 = lo1 + bv.y, y2 = lo2 + bv.z, y3 = lo3 + bv.w;
        float z0 = hi0 + bv.x, z1 = hi1 + bv.y, z2 = hi2 + bv.z, z3 = hi3 + bv.w;
        if (r0 < NN) {
            *(float4*)&C[(size_t)r0 * C1 + bcol + tx * 4] = make_float4(y0, y1, y2, y3);
            psum[0] += y0; psum[1] += y1; psum[2] += y2; psum[3] += y3;
            psq[0] += y0 * y0; psq[1] += y1 * y1; psq[2] += y2 * y2; psq[3] += y3 * y3;
        }
        if (r0 + 1 < NN) {
            *(float4*)&C[(size_t)(r0 + 1) * C1 + bcol + tx * 4] = make_float4(z0, z1, z2, z3);
            psum[0] += z0; psum[1] += z1; psum[2] += z2; psum[3] += z3;
            psq[0] += z0 * z0; psq[1] += z1 * z1; psq[2] += z2 * z2; psq[3] += z3 * z3;
        }
    }
#pragma unroll
    for (int c = 0; c < 4; c++) {
        reds[ty][tx * 4 + c] = psum[c];
        redq[ty][tx * 4 + c] = psq[c];
    }
    __syncthreads();
    if (tid < 64) {
        float s = 0.f, q = 0.f;
#pragma unroll
        for (int i = 0; i < 16; i++) { s += reds[i][tid]; q += redq[i][tid]; }
        atomicAdd(&d_colsum1[bcol + tid], s);
        atomicAdd(&d_colsq1[bcol + tid], q);
    }
}

// ------------------- GEMM2: xs2 = BNReLU(out1) @ W2, fused logits2 ------------------
__global__ void __launch_bounds__(256) gemm2_fused(
    const float* __restrict__ A, const float* __restrict__ B,
    float* __restrict__ C, const float* __restrict__ g1bn,
    const float* __restrict__ b1bn, const float* __restrict__ as2,
    const float* __restrict__ ad2) {
    const int BK = 16;
    __shared__ __align__(16) float As[BK][128 + 4];
    __shared__ __align__(16) float Bs[BK][64];
    __shared__ float sc[C1];
    __shared__ float sf[C1];
    int tid = threadIdx.x;
    int tx = tid & 15, ty = tid >> 4;
    int m0 = blockIdx.y * 128;

    {
        float mu = d_colsum1[tid] / (float)NN;
        float var = d_colsq1[tid] / (float)NN - mu * mu;
        float rs = rsqrtf(var + EPS) * g1bn[tid];
        sc[tid] = rs;
        sf[tid] = b1bn[tid] - mu * rs;
    }
    __syncthreads();

    ull acc[4][4];
#pragma unroll
    for (int i = 0; i < 4; i++)
#pragma unroll
        for (int j = 0; j < 4; j++) acc[i][j] = 0ull;

    int ar = tid >> 1;
    int akb = (tid & 1) * 8;
    int gr_a = m0 + ar;
    int br = tid >> 4;
    int bc = (tid & 15) * 4;

    for (int k0 = 0; k0 < C1; k0 += BK) {
        float4 a4a, a4b;
        if (gr_a < NN) {
            a4a = *(const float4*)&A[(size_t)gr_a * C1 + k0 + akb];
            a4b = *(const float4*)&A[(size_t)gr_a * C1 + k0 + akb + 4];
        } else {
            a4a = make_float4(0.f, 0.f, 0.f, 0.f);
            a4b = a4a;
        }
        int kb = k0 + akb;
        As[akb + 0][ar] = fmaxf(fmaf(a4a.x, sc[kb + 0], sf[kb + 0]), 0.f);
        As[akb + 1][ar] = fmaxf(fmaf(a4a.y, sc[kb + 1], sf[kb + 1]), 0.f);
        As[akb + 2][ar] = fmaxf(fmaf(a4a.z, sc[kb + 2], sf[kb + 2]), 0.f);
        As[akb + 3][ar] = fmaxf(fmaf(a4a.w, sc[kb + 3], sf[kb + 3]), 0.f);
        As[akb + 4][ar] = fmaxf(fmaf(a4b.x, sc[kb + 4], sf[kb + 4]), 0.f);
        As[akb + 5][ar] = fmaxf(fmaf(a4b.y, sc[kb + 5], sf[kb + 5]), 0.f);
        As[akb + 6][ar] = fmaxf(fmaf(a4b.z, sc[kb + 6], sf[kb + 6]), 0.f);
        As[akb + 7][ar] = fmaxf(fmaf(a4b.w, sc[kb + 7], sf[kb + 7]), 0.f);
        *(float4*)&Bs[br][bc] = *(const float4*)&B[(size_t)(k0 + br) * HID + bc];
        __syncthreads();
#pragma unroll
        for (int kk = 0; kk < BK; kk++) {
            ulonglong2 ap01 = *(const ulonglong2*)&As[kk][ty * 8];
            ulonglong2 ap23 = *(const ulonglong2*)&As[kk][ty * 8 + 4];
            float4 bq = *(const float4*)&Bs[kk][tx * 4];
            ull bb0 = pack2(bq.x, bq.x);
            ull bb1 = pack2(bq.y, bq.y);
            ull bb2 = pack2(bq.z, bq.z);
            ull bb3 = pack2(bq.w, bq.w);
            ull ap[4] = {ap01.x, ap01.y, ap23.x, ap23.y};
#pragma unroll
            for (int i = 0; i < 4; i++) {
                fma2(acc[i][0], ap[i], bb0);
                fma2(acc[i][1], ap[i], bb1);
                fma2(acc[i][2], ap[i], bb2);
                fma2(acc[i][3], ap[i], bb3);
            }
        }
        __syncthreads();
    }
    float4 av = *(const float4*)&as2[tx * 4];
    float4 dv = *(const float4*)&ad2[tx * 4];
    float ps8[8], pd8[8];
#pragma unroll
    for (int i = 0; i < 4; i++) {
        float lo0, hi0, lo1, hi1, lo2, hi2, lo3, hi3;
        unpack2(acc[i][0], lo0, hi0);
        unpack2(acc[i][1], lo1, hi1);
        unpack2(acc[i][2], lo2, hi2);
        unpack2(acc[i][3], lo3, hi3);
        int r0 = m0 + ty * 8 + 2 * i;
        if (r0 < NN)
            *(float4*)&C[(size_t)r0 * HID + tx * 4] = make_float4(lo0, lo1, lo2, lo3);
        if (r0 + 1 < NN)
            *(float4*)&C[(size_t)(r0 + 1) * HID + tx * 4] = make_float4(hi0, hi1, hi2, hi3);
        ps8[2 * i]     = lo0 * av.x + lo1 * av.y + lo2 * av.z + lo3 * av.w;
        ps8[2 * i + 1] = hi0 * av.x + hi1 * av.y + hi2 * av.z + hi3 * av.w;
        pd8[2 * i]     = lo0 * dv.x + lo1 * dv.y + lo2 * dv.z + lo3 * dv.w;
        pd8[2 * i + 1] = hi0 * dv.x + hi1 * dv.y + hi2 * dv.z + hi3 * dv.w;
    }
    float* red = &As[0][0];
    __syncthreads();
#pragma unroll
    for (int i = 0; i < 8; i++) red[(ty * 8 + i) * 16 + tx] = ps8[i];
    __syncthreads();
    if (tid < 128 && m0 + tid < NN) {
        float s = 0.f;
#pragma unroll
        for (int j = 0; j < 16; j++) s += red[tid * 16 + j];
        d_als2[m0 + tid] = s;
    }
    __syncthreads();
#pragma unroll
    for (int i = 0; i < 8; i++) red[(ty * 8 + i) * 16 + tx] = pd8[i];
    __syncthreads();
    if (tid < 128 && m0 + tid < NN) {
        float s = 0.f;
#pragma unroll
        for (int j = 0; j < 16; j++) s += red[tid * 16 + j];
        d_ald2[m0 + tid] = s;
    }
}

// ------- gather layer2: warp per node, 2x unrolled, fused BN2 stats ------------------
__global__ void __launch_bounds__(256) gather2w(const float* __restrict__ bias) {
    int wid = threadIdx.x >> 5, lane = threadIdx.x & 31;
    int d = blockIdx.x * 8 + wid;   // NN % 8 == 0, all warps active
    int r0 = d_rowptr[d], r1 = d_rowptr[d + 1];
    int LR = r1 - 1 - r0;
    __shared__ float sex[8][32];
    __shared__ int ssrc[8][32];
    __shared__ float s2v[8][64];
    float ald = d_ald2[d];
    float inv = 1.0f / (float)(LR > 1 ? LR : 1);
    float es = __expf(lrelu(d_als2[d] + ald + d_ec2sum[d] * inv));

    float2 acc = make_float2(0.f, 0.f);
    float lsum = 0.f;
    const float2* x2 = (const float2*)d_xs2;
    for (int c0 = r0; c0 < r0 + LR; c0 += 32) {
        int m = min(32, r0 + LR - c0);
        __syncwarp();
        if (lane < m) {
            int p = c0 + lane;
            int s = d_esrc[p];
            float e = __expf(lrelu(d_als2[s] + ald + d_ec2[p]));
            sex[wid][lane] = e;
            ssrc[wid][lane] = s;
            lsum += e;
        }
        __syncwarp();
        int j = 0;
        for (; j + 2 <= m; j += 2) {
            float2 xv0 = x2[(size_t)ssrc[wid][j] * 32 + lane];
            float2 xv1 = x2[(size_t)ssrc[wid][j + 1] * 32 + lane];
            float e0 = sex[wid][j];
            float e1 = sex[wid][j + 1];
            acc.x += e0 * xv0.x; acc.y += e0 * xv0.y;
            acc.x += e1 * xv1.x; acc.y += e1 * xv1.y;
        }
        if (j < m) {
            float2 xv = x2[(size_t)ssrc[wid][j] * 32 + lane];
            float e = sex[wid][j];
            acc.x += e * xv.x;
            acc.y += e * xv.y;
        }
    }
    {
        float2 xv = x2[(size_t)d * 32 + lane];
        acc.x += es * xv.x;
        acc.y += es * xv.y;
    }
#pragma unroll
    for (int off = 16; off >= 1; off >>= 1)
        lsum += __shfl_xor_sync(0xFFFFFFFFu, lsum, off);
    lsum += es;
    float sinv = 1.0f / lsum;
    float2 bv = ((const float2*)bias)[lane];
    float y0 = acc.x * sinv + bv.x;
    float y1 = acc.y * sinv + bv.y;
    ((float2*)d_out2)[(size_t)d * 32 + lane] = make_float2(y0, y1);
    // fused BN2 stats
    s2v[wid][lane * 2]     = y0;
    s2v[wid][lane * 2 + 1] = y1;
    __syncthreads();
    int t = threadIdx.x;
    if (t < 64) {
        float s = 0.f, q = 0.f;
#pragma unroll
        for (int r = 0; r < 8; r++) {
            float v = s2v[r][t];
            s += v;
            q += v * v;
        }
        atomicAdd(&d_colsum2[t], s);
        atomicAdd(&d_colsq2[t], q);
    }
}

// ------------------- gate (applies BN2+ReLU in place) ---------------------------------
__global__ void gate_bn(const float* __restrict__ g2, const float* __restrict__ b2,
                        const float* __restrict__ Wg, const float* __restrict__ bg) {
    int n = (blockIdx.x * blockDim.x + threadIdx.x) >> 5;
    int lane = threadIdx.x & 31;
    if (n >= NN) return;
    int c0 = lane * 2, c1 = c0 + 1;
    float2 v = ((const float2*)d_out2)[(size_t)n * 32 + lane];
    float mu0 = d_colsum2[c0] / (float)NN;
    float var0 = d_colsq2[c0] / (float)NN - mu0 * mu0;
    float y0 = fmaxf((v.x - mu0) * rsqrtf(var0 + EPS) * __ldg(g2 + c0) + __ldg(b2 + c0), 0.f);
    float mu1 = d_colsum2[c1] / (float)NN;
    float var1 = d_colsq2[c1] / (float)NN - mu1 * mu1;
    float y1 = fmaxf((v.y - mu1) * rsqrtf(var1 + EPS) * __ldg(g2 + c1) + __ldg(b2 + c1), 0.f);
    ((float2*)d_out2)[(size_t)n * 32 + lane] = make_float2(y0, y1);
    float g = y0 * __ldg(Wg + c0) + y1 * __ldg(Wg + c1);
#pragma unroll
    for (int off = 16; off >= 1; off >>= 1)
        g += __shfl_xor_sync(0xFFFFFFFFu, g, off);
    if (lane == 0) d_gate[n] = g + bg[0];
}

// ------------------- pooling (256 threads; unshifted softmax) ---------------------------
__device__ __forceinline__ int lbound(const int* a, int n, int v) {
    int lo = 0, hi = n;
    while (lo < hi) {
        int mid = (lo + hi) >> 1;
        if (a[mid] < v) lo = mid + 1; else hi = mid;
    }
    return lo;
}

__global__ void __launch_bounds__(256) pool_kernel(const int* __restrict__ batch,
                                                   float* __restrict__ out) {
    int b = blockIdx.x, t = threadIdx.x;
    int c = t & 63, sub = t >> 6;   // 4 subgroups of 64 channels
    __shared__ int slo, shi;
    __shared__ float red[256];
    __shared__ float sh_w[64];
    __shared__ float facc[4][64];
    if (t == 0) { slo = lbound(batch, NN, b); shi = lbound(batch, NN, b + 1); }
    __syncthreads();
    int lo = slo, hi = shi;
    if (hi <= lo) { if (t < 64) out[b * 64 + c] = 0.f; return; }
    float ts = 0.f;
    for (int n = lo + t; n < hi; n += 256) ts += __expf(d_gate[n]);
    red[t] = ts;
    __syncthreads();
#pragma unroll
    for (int off = 128; off >= 1; off >>= 1) {
        if (t < off) red[t] += red[t + off];
        __syncthreads();
    }
    float sinv = 1.0f / red[0];
    float acc = 0.f;
    for (int base = lo; base < hi; base += 64) {
        int mcnt = min(64, hi - base);
        __syncthreads();
        if (t < mcnt) sh_w[t] = __expf(d_gate[base + t]);
        __syncthreads();
        for (int j = sub; j < mcnt; j += 4)
            acc += sh_w[j] * d_out2[(size_t)(base + j) * 64 + c];
    }
    facc[sub][c] = acc;
    __syncthreads();
    if (t < 64) {
        float v = facc[0][t] + facc[1][t] + facc[2][t] + facc[3][t];
        out[b * 64 + t] = v * sinv;
    }
}

// ------------------- launch ----------------------------------------------------------------
static inline int gdiv(long long a, int b) { return (int)((a + b - 1) / b); }

extern "C" void kernel_launch(void* const* d_in, const int* in_sizes, int n_in,
                              void* d_out, int out_size) {
    const float* x     = (const float*)d_in[0];
    const float* ea    = (const float*)d_in[1];
    const int*   ei    = (const int*)d_in[2];
    const int*   batch = (const int*)d_in[3];
    const float* W1    = (const float*)d_in[4];
    const float* We1   = (const float*)d_in[5];
    const float* as1   = (const float*)d_in[6];
    const float* ad1   = (const float*)d_in[7];
    const float* ae1   = (const float*)d_in[8];
    const float* b1    = (const float*)d_in[9];
    const float* g1    = (const float*)d_in[10];
    const float* bb1   = (const float*)d_in[11];
    const float* W2    = (const float*)d_in[12];
    const float* We2   = (const float*)d_in[13];
    const float* as2   = (const float*)d_in[14];
    const float* ad2   = (const float*)d_in[15];
    const float* ae2   = (const float*)d_in[16];
    const float* b2    = (const float*)d_in[17];
    const float* g2    = (const float*)d_in[18];
    const float* bb2   = (const float*)d_in[19];
    const float* Wg    = (const float*)d_in[20];
    const float* bg    = (const float*)d_in[21];
    float* out = (float*)d_out;

    const int* src = ei;
    const int* dst = ei + EE;

    float* p_tmp;  cudaGetSymbolAddress((void**)&p_tmp, d_tmp);
    float* p_out1; cudaGetSymbolAddress((void**)&p_out1, d_out1);
    float* p_xs2;  cudaGetSymbolAddress((void**)&p_xs2, d_xs2);

    init0<<<gdiv(NN * 4, 256), 256>>>();
    hist_kernel<<<gdiv(EE, 256), 256>>>(dst);
    scan_kernel<<<1, 1024>>>();
    prep_par<<<84, 256>>>(W1, as1, ad1, We1, ae1, We2, ae2);
    logits1<<<gdiv((long long)NN * 32, 256), 256>>>(x);
    edge_alpha1<<<gdiv(EE, 256), 256>>>(ea, src, dst);
    gather1w<<<gdiv(NN, 8), 256>>>(x);
    {
        dim3 g(4, gdiv(NN, 128));
        gemm1_stats<<<g, 256>>>(p_tmp, W1, p_out1, b1);
    }
    {
        dim3 g(1, gdiv(NN, 128));
        gemm2_fused<<<g, 256>>>(p_out1, W2, p_xs2, g1, bb1, as2, ad2);
    }
    gather2w<<<gdiv(NN, 8), 256>>>(b2);
    gate_bn<<<gdiv((long long)NN * 32, 256), 256>>>(g2, bb2, Wg, bg);
    pool_kernel<<<BB, 256>>>(batch, out);
}

// round 16
// speedup vs baseline: 1.2552x; 1.0224x over previous
#include <cuda_runtime.h>
#include <math_constants.h>

#define NN 30000
#define EE 480000
#define ET (EE + NN)
#define BB 64
#define FIN 128
#define HID 64
#define ED 32
#define C1 256
#define NEG 0.2f
#define EPS 1e-5f

typedef unsigned long long ull;

// ------------------- scratch -------------------------------------------------
__device__ int      d_deg[NN];
__device__ int      d_rowptr[NN + 1];
__device__ int      d_cursor[NN];
// per-edge record: [2p] = exp'd alpha (4 heads); [2p+1] = (src_bits, ec2, 0, 0)
__device__ float4   d_edge[(size_t)ET * 2];

__device__ float    d_vs1[512];
__device__ float    d_vd1[512];
__device__ float    d_c1[ED * 4];
__device__ float    d_c2[ED];
__device__ float    d_als1[NN * 4];
__device__ float    d_ald1[NN * 4];
__device__ float    d_ecsum[NN * 4];
__device__ float    d_ec2sum[NN];
__device__ float    d_tmp[(size_t)NN * 512];
__device__ float    d_out1[(size_t)NN * C1];
__device__ float    d_colsum1[C1];
__device__ float    d_colsq1[C1];
__device__ float    d_xs2[(size_t)NN * HID];
__device__ float    d_als2[NN];
__device__ float    d_ald2[NN];
__device__ float    d_out2[(size_t)NN * HID];
__device__ float    d_colsum2[HID];
__device__ float    d_colsq2[HID];
__device__ float    d_gate[NN];

// ------------------- helpers -------------------------------------------------
__device__ __forceinline__ ull pack2(float lo, float hi) {
    ull r;
    asm("mov.b64 %0, {%1, %2};" : "=l"(r) : "f"(lo), "f"(hi));
    return r;
}
__device__ __forceinline__ void unpack2(ull v, float& lo, float& hi) {
    asm("mov.b64 {%0, %1}, %2;" : "=f"(lo), "=f"(hi) : "l"(v));
}
__device__ __forceinline__ void fma2(ull& acc, ull a, ull b) {
    asm("fma.rn.f32x2 %0, %1, %2, %0;" : "+l"(acc) : "l"(a), "l"(b));
}
__device__ __forceinline__ float lrelu(float a) { return a > 0.f ? a : NEG * a; }

// ---------- merged: init (blocks >= 84) + prep small vectors (blocks < 84) ---------
__global__ void __launch_bounds__(256) init_prep(
    const float* __restrict__ W1, const float* __restrict__ as1,
    const float* __restrict__ ad1,
    const float* __restrict__ We1, const float* __restrict__ ae1,
    const float* __restrict__ We2, const float* __restrict__ ae2) {
    if (blockIdx.x >= 84) {
        int i = (blockIdx.x - 84) * 256 + threadIdx.x;
        if (i < NN * 4) d_ecsum[i] = 0.f;
        if (i < NN) { d_deg[i] = 0; d_cursor[i] = 0; d_ec2sum[i] = 0.f; }
        return;
    }
    int gw = blockIdx.x * 8 + (threadIdx.x >> 5);
    int lane = threadIdx.x & 31;
    if (gw < 512) {
        int h = gw >> 7, k = gw & 127;
        const float* wrow = W1 + (size_t)k * C1 + h * HID;
        const float* arow = as1 + h * HID;
        const float* drow = ad1 + h * HID;
        float w0 = wrow[lane], w1 = wrow[lane + 32];
        float s = w0 * arow[lane] + w1 * arow[lane + 32];
        float dv = w0 * drow[lane] + w1 * drow[lane + 32];
#pragma unroll
        for (int off = 16; off >= 1; off >>= 1) {
            s += __shfl_xor_sync(0xFFFFFFFFu, s, off);
            dv += __shfl_xor_sync(0xFFFFFFFFu, dv, off);
        }
        if (lane == 0) { d_vs1[gw] = s; d_vd1[gw] = dv; }
    } else if (gw < 640) {
        int idx = gw - 512;
        int k = idx >> 2, h = idx & 3;
        const float* wrow = We1 + (size_t)k * C1 + h * HID;
        const float* arow = ae1 + h * HID;
        float s = wrow[lane] * arow[lane] + wrow[lane + 32] * arow[lane + 32];
#pragma unroll
        for (int off = 16; off >= 1; off >>= 1)
            s += __shfl_xor_sync(0xFFFFFFFFu, s, off);
        if (lane == 0) d_c1[idx] = s;
    } else if (gw < 672) {
        int k = gw - 640;
        const float* wrow = We2 + (size_t)k * HID;
        float s = wrow[lane] * ae2[lane] + wrow[lane + 32] * ae2[lane + 32];
#pragma unroll
        for (int off = 16; off >= 1; off >>= 1)
            s += __shfl_xor_sync(0xFFFFFFFFu, s, off);
        if (lane == 0) d_c2[k] = s;
    }
}

// ---------- merged: degree histogram (first HB blocks) + node logits1 -----------------
#define HBLK ((EE + 255) / 256)
__global__ void __launch_bounds__(256) hist_logits(const int* __restrict__ dst,
                                                   const float* __restrict__ x) {
    if (blockIdx.x < HBLK) {
        int e = blockIdx.x * 256 + threadIdx.x;
        if (e < EE) atomicAdd(&d_deg[dst[e]], 1);
        return;
    }
    int gw = (blockIdx.x - HBLK) * 8 + (threadIdx.x >> 5);
    int lane = threadIdx.x & 31;
    if (gw >= NN) return;
    float4 xv = ((const float4*)x)[(size_t)gw * 32 + lane];
    float r0, r1, r2, r3, q0, q1, q2, q3;
    {
        float4 v;
        v = ((const float4*)d_vs1)[0 * 32 + lane]; r0 = xv.x*v.x + xv.y*v.y + xv.z*v.z + xv.w*v.w;
        v = ((const float4*)d_vs1)[1 * 32 + lane]; r1 = xv.x*v.x + xv.y*v.y + xv.z*v.z + xv.w*v.w;
        v = ((const float4*)d_vs1)[2 * 32 + lane]; r2 = xv.x*v.x + xv.y*v.y + xv.z*v.z + xv.w*v.w;
        v = ((const float4*)d_vs1)[3 * 32 + lane]; r3 = xv.x*v.x + xv.y*v.y + xv.z*v.z + xv.w*v.w;
        v = ((const float4*)d_vd1)[0 * 32 + lane]; q0 = xv.x*v.x + xv.y*v.y + xv.z*v.z + xv.w*v.w;
        v = ((const float4*)d_vd1)[1 * 32 + lane]; q1 = xv.x*v.x + xv.y*v.y + xv.z*v.z + xv.w*v.w;
        v = ((const float4*)d_vd1)[2 * 32 + lane]; q2 = xv.x*v.x + xv.y*v.y + xv.z*v.z + xv.w*v.w;
        v = ((const float4*)d_vd1)[3 * 32 + lane]; q3 = xv.x*v.x + xv.y*v.y + xv.z*v.z + xv.w*v.w;
    }
#pragma unroll
    for (int off = 16; off >= 1; off >>= 1) {
        r0 += __shfl_xor_sync(0xFFFFFFFFu, r0, off);
        r1 += __shfl_xor_sync(0xFFFFFFFFu, r1, off);
        r2 += __shfl_xor_sync(0xFFFFFFFFu, r2, off);
        r3 += __shfl_xor_sync(0xFFFFFFFFu, r3, off);
        q0 += __shfl_xor_sync(0xFFFFFFFFu, q0, off);
        q1 += __shfl_xor_sync(0xFFFFFFFFu, q1, off);
        q2 += __shfl_xor_sync(0xFFFFFFFFu, q2, off);
        q3 += __shfl_xor_sync(0xFFFFFFFFu, q3, off);
    }
    if (lane == 0) {
        d_als1[gw * 4 + 0] = r0; d_als1[gw * 4 + 1] = r1;
        d_als1[gw * 4 + 2] = r2; d_als1[gw * 4 + 3] = r3;
        d_ald1[gw * 4 + 0] = q0; d_ald1[gw * 4 + 1] = q1;
        d_ald1[gw * 4 + 2] = q2; d_ald1[gw * 4 + 3] = q3;
    }
}

// ------------------- rowptr scan ---------------------------------------------------
__global__ void scan_kernel() {
    __shared__ int wsum[32];
    const int PER = 30;
    int t = threadIdx.x;
    if (t < C1) { d_colsum1[t] = 0.f; d_colsq1[t] = 0.f; }
    if (t < HID) { d_colsum2[t] = 0.f; d_colsq2[t] = 0.f; }
    int base = t * PER;
    int vals[PER];
    int s = 0;
#pragma unroll
    for (int i = 0; i < PER; i++) {
        int idx = base + i;
        vals[i] = (idx < NN) ? (d_deg[idx] + 1) : 0;   // +1 self loop (last slot)
        s += vals[i];
    }
    int lane = t & 31, w = t >> 5;
    int x = s;
#pragma unroll
    for (int off = 1; off < 32; off <<= 1) {
        int y = __shfl_up_sync(0xFFFFFFFFu, x, off);
        if (lane >= off) x += y;
    }
    if (lane == 31) wsum[w] = x;
    __syncthreads();
    if (w == 0) {
        int y = wsum[lane];
#pragma unroll
        for (int off = 1; off < 32; off <<= 1) {
            int z = __shfl_up_sync(0xFFFFFFFFu, y, off);
            if (lane >= off) y += z;
        }
        wsum[lane] = y;
    }
    __syncthreads();
    int excl = x - s + (w > 0 ? wsum[w - 1] : 0);
    int run = excl;
#pragma unroll
    for (int i = 0; i < PER; i++) {
        int idx = base + i;
        if (idx < NN) d_rowptr[idx] = run;
        run += vals[i];
    }
    if (t == 0) d_rowptr[NN] = ET;
}

// --------- edge alphas: slot assign + exp(lrelu(alpha)) + packed record --------------
__global__ void edge_alpha1(const float* __restrict__ ea, const int* __restrict__ src,
                            const int* __restrict__ dst) {
    int e = blockIdx.x * blockDim.x + threadIdx.x;
    if (e >= EE) return;
    int s = src[e], d = dst[e];
    const float4* row = (const float4*)(ea + (size_t)e * ED);
    float ec0 = 0.f, ec1 = 0.f, ec2 = 0.f, ec3 = 0.f, e2 = 0.f;
#pragma unroll
    for (int q = 0; q < 8; q++) {
        float4 v = __ldg(row + q);
        int k = q * 4;
        ec0 += v.x * d_c1[(k+0)*4+0] + v.y * d_c1[(k+1)*4+0] + v.z * d_c1[(k+2)*4+0] + v.w * d_c1[(k+3)*4+0];
        ec1 += v.x * d_c1[(k+0)*4+1] + v.y * d_c1[(k+1)*4+1] + v.z * d_c1[(k+2)*4+1] + v.w * d_c1[(k+3)*4+1];
        ec2 += v.x * d_c1[(k+0)*4+2] + v.y * d_c1[(k+1)*4+2] + v.z * d_c1[(k+2)*4+2] + v.w * d_c1[(k+3)*4+2];
        ec3 += v.x * d_c1[(k+0)*4+3] + v.y * d_c1[(k+1)*4+3] + v.z * d_c1[(k+2)*4+3] + v.w * d_c1[(k+3)*4+3];
        e2  += v.x * d_c2[k+0] + v.y * d_c2[k+1] + v.z * d_c2[k+2] + v.w * d_c2[k+3];
    }
    int p = d_rowptr[d] + atomicAdd(&d_cursor[d], 1);
    float4 a;
    a.x = __expf(lrelu(d_als1[s * 4 + 0] + d_ald1[d * 4 + 0] + ec0));
    a.y = __expf(lrelu(d_als1[s * 4 + 1] + d_ald1[d * 4 + 1] + ec1));
    a.z = __expf(lrelu(d_als1[s * 4 + 2] + d_ald1[d * 4 + 2] + ec2));
    a.w = __expf(lrelu(d_als1[s * 4 + 3] + d_ald1[d * 4 + 3] + ec3));
    d_edge[(size_t)p * 2]     = a;
    d_edge[(size_t)p * 2 + 1] = make_float4(__int_as_float(s), e2, 0.f, 0.f);
    atomicAdd(&d_ecsum[d * 4 + 0], ec0);
    atomicAdd(&d_ecsum[d * 4 + 1], ec1);
    atomicAdd(&d_ecsum[d * 4 + 2], ec2);
    atomicAdd(&d_ecsum[d * 4 + 3], ec3);
    atomicAdd(&d_ec2sum[d], e2);
}

// --------- gather layer1: warp per node, 2x unrolled inner ---------------------------
__global__ void __launch_bounds__(256) gather1w(const float* __restrict__ x) {
    int wid = threadIdx.x >> 5, lane = threadIdx.x & 31;
    int d = blockIdx.x * 8 + wid;   // NN % 8 == 0
    int r0 = d_rowptr[d], r1 = d_rowptr[d + 1];
    int LR = r1 - 1 - r0;           // real edges; slot r1-1 is self
    __shared__ __align__(16) float4 sex[8][32];
    __shared__ int ssrc[8][32];

    float inv = 1.0f / (float)(LR > 1 ? LR : 1);
    float4 es;
    es.x = __expf(lrelu(d_als1[d * 4 + 0] + d_ald1[d * 4 + 0] + d_ecsum[d * 4 + 0] * inv));
    es.y = __expf(lrelu(d_als1[d * 4 + 1] + d_ald1[d * 4 + 1] + d_ecsum[d * 4 + 1] * inv));
    es.z = __expf(lrelu(d_als1[d * 4 + 2] + d_ald1[d * 4 + 2] + d_ecsum[d * 4 + 2] * inv));
    es.w = __expf(lrelu(d_als1[d * 4 + 3] + d_ald1[d * 4 + 3] + d_ecsum[d * 4 + 3] * inv));

    float4 a0 = make_float4(0, 0, 0, 0), a1 = a0, a2 = a0, a3 = a0;
    float4 lsum = make_float4(0, 0, 0, 0);
    const float4* x4 = (const float4*)x;
    for (int c0 = r0; c0 < r0 + LR; c0 += 32) {
        int m = min(32, r0 + LR - c0);
        __syncwarp();
        if (lane < m) {
            float4 e  = d_edge[(size_t)(c0 + lane) * 2];
            float4 m2 = d_edge[(size_t)(c0 + lane) * 2 + 1];
            sex[wid][lane] = e;
            ssrc[wid][lane] = __float_as_int(m2.x);
            lsum.x += e.x; lsum.y += e.y; lsum.z += e.z; lsum.w += e.w;
        }
        __syncwarp();
        int j = 0;
        for (; j + 2 <= m; j += 2) {
            float4 xv0 = x4[(size_t)ssrc[wid][j] * 32 + lane];
            float4 xv1 = x4[(size_t)ssrc[wid][j + 1] * 32 + lane];
            float4 e0 = sex[wid][j];
            float4 e1 = sex[wid][j + 1];
            a0.x += e0.x * xv0.x; a0.y += e0.x * xv0.y; a0.z += e0.x * xv0.z; a0.w += e0.x * xv0.w;
            a1.x += e0.y * xv0.x; a1.y += e0.y * xv0.y; a1.z += e0.y * xv0.z; a1.w += e0.y * xv0.w;
            a2.x += e0.z * xv0.x; a2.y += e0.z * xv0.y; a2.z += e0.z * xv0.z; a2.w += e0.z * xv0.w;
            a3.x += e0.w * xv0.x; a3.y += e0.w * xv0.y; a3.z += e0.w * xv0.z; a3.w += e0.w * xv0.w;
            a0.x += e1.x * xv1.x; a0.y += e1.x * xv1.y; a0.z += e1.x * xv1.z; a0.w += e1.x * xv1.w;
            a1.x += e1.y * xv1.x; a1.y += e1.y * xv1.y; a1.z += e1.y * xv1.z; a1.w += e1.y * xv1.w;
            a2.x += e1.z * xv1.x; a2.y += e1.z * xv1.y; a2.z += e1.z * xv1.z; a2.w += e1.z * xv1.w;
            a3.x += e1.w * xv1.x; a3.y += e1.w * xv1.y; a3.z += e1.w * xv1.z; a3.w += e1.w * xv1.w;
        }
        if (j < m) {
            float4 xv = x4[(size_t)ssrc[wid][j] * 32 + lane];
            float4 e = sex[wid][j];
            a0.x += e.x * xv.x; a0.y += e.x * xv.y; a0.z += e.x * xv.z; a0.w += e.x * xv.w;
            a1.x += e.y * xv.x; a1.y += e.y * xv.y; a1.z += e.y * xv.z; a1.w += e.y * xv.w;
            a2.x += e.z * xv.x; a2.y += e.z * xv.y; a2.z += e.z * xv.z; a2.w += e.z * xv.w;
            a3.x += e.w * xv.x; a3.y += e.w * xv.y; a3.z += e.w * xv.z; a3.w += e.w * xv.w;
        }
    }
    // self-loop contribution
    {
        float4 xv = x4[(size_t)d * 32 + lane];
        a0.x += es.x * xv.x; a0.y += es.x * xv.y; a0.z += es.x * xv.z; a0.w += es.x * xv.w;
        a1.x += es.y * xv.x; a1.y += es.y * xv.y; a1.z += es.y * xv.z; a1.w += es.y * xv.w;
        a2.x += es.z * xv.x; a2.y += es.z * xv.y; a2.z += es.z * xv.z; a2.w += es.z * xv.w;
        a3.x += es.w * xv.x; a3.y += es.w * xv.y; a3.z += es.w * xv.z; a3.w += es.w * xv.w;
    }
#pragma unroll
    for (int off = 16; off >= 1; off >>= 1) {
        lsum.x += __shfl_xor_sync(0xFFFFFFFFu, lsum.x, off);
        lsum.y += __shfl_xor_sync(0xFFFFFFFFu, lsum.y, off);
        lsum.z += __shfl_xor_sync(0xFFFFFFFFu, lsum.z, off);
        lsum.w += __shfl_xor_sync(0xFFFFFFFFu, lsum.w, off);
    }
    lsum.x += es.x; lsum.y += es.y; lsum.z += es.z; lsum.w += es.w;
    float i0 = 1.0f / lsum.x, i1 = 1.0f / lsum.y, i2 = 1.0f / lsum.z, i3 = 1.0f / lsum.w;
    float4* tmp4 = (float4*)&d_tmp[(size_t)d * 512];
    tmp4[0 * 32 + lane] = make_float4(a0.x * i0, a0.y * i0, a0.z * i0, a0.w * i0);
    tmp4[1 * 32 + lane] = make_float4(a1.x * i1, a1.y * i1, a1.z * i1, a1.w * i1);
    tmp4[2 * 32 + lane] = make_float4(a2.x * i2, a2.y * i2, a2.z * i2, a2.w * i2);
    tmp4[3 * 32 + lane] = make_float4(a3.x * i3, a3.y * i3, a3.z * i3, a3.w * i3);
}

// ------------------- GEMM1: out1 = tmp(heads) @ W1 + b1, fused BN stats -------------
__global__ void __launch_bounds__(256) gemm1_stats(
    const float* __restrict__ A, const float* __restrict__ B,
    float* __restrict__ C, const float* __restrict__ bias) {
    const int BK = 16;
    __shared__ __align__(16) float As[BK][128 + 4];
    __shared__ __align__(16) float Bs[BK][64];
    __shared__ float reds[16][64];
    __shared__ float redq[16][64];
    int tid = threadIdx.x;
    int tx = tid & 15, ty = tid >> 4;
    int m0 = blockIdx.y * 128;
    const float* Ab = A + (size_t)blockIdx.x * 128;
    int bcol = blockIdx.x * 64;

    ull acc[4][4];
#pragma unroll
    for (int i = 0; i < 4; i++)
#pragma unroll
        for (int j = 0; j < 4; j++) acc[i][j] = 0ull;

    int ar = tid >> 1;
    int akb = (tid & 1) * 8;
    int gr_a = m0 + ar;
    int br = tid >> 4;
    int bc = (tid & 15) * 4;

    for (int k0 = 0; k0 < FIN; k0 += BK) {
        float4 a4a, a4b;
        if (gr_a < NN) {
            a4a = *(const float4*)&Ab[(size_t)gr_a * 512 + k0 + akb];
            a4b = *(const float4*)&Ab[(size_t)gr_a * 512 + k0 + akb + 4];
        } else {
            a4a = make_float4(0.f, 0.f, 0.f, 0.f);
            a4b = a4a;
        }
        As[akb + 0][ar] = a4a.x; As[akb + 1][ar] = a4a.y;
        As[akb + 2][ar] = a4a.z; As[akb + 3][ar] = a4a.w;
        As[akb + 4][ar] = a4b.x; As[akb + 5][ar] = a4b.y;
        As[akb + 6][ar] = a4b.z; As[akb + 7][ar] = a4b.w;
        *(float4*)&Bs[br][bc] = *(const float4*)&B[(size_t)(k0 + br) * C1 + bcol + bc];
        __syncthreads();
#pragma unroll
        for (int kk = 0; kk < BK; kk++) {
            ulonglong2 ap01 = *(const ulonglong2*)&As[kk][ty * 8];
            ulonglong2 ap23 = *(const ulonglong2*)&As[kk][ty * 8 + 4];
            float4 bq = *(const float4*)&Bs[kk][tx * 4];
            ull bb0 = pack2(bq.x, bq.x);
            ull bb1 = pack2(bq.y, bq.y);
            ull bb2 = pack2(bq.z, bq.z);
            ull bb3 = pack2(bq.w, bq.w);
            ull ap[4] = {ap01.x, ap01.y, ap23.x, ap23.y};
#pragma unroll
            for (int i = 0; i < 4; i++) {
                fma2(acc[i][0], ap[i], bb0);
                fma2(acc[i][1], ap[i], bb1);
                fma2(acc[i][2], ap[i], bb2);
                fma2(acc[i][3], ap[i], bb3);
            }
        }
        __syncthreads();
    }
    float4 bv = *(const float4*)&bias[bcol + tx * 4];
    float psum[4] = {0.f, 0.f, 0.f, 0.f};
    float psq[4]  = {0.f, 0.f, 0.f, 0.f};
#pragma unroll
    for (int i = 0; i < 4; i++) {
        float lo0, hi0, lo1, hi1, lo2, hi2, lo3, hi3;
        unpack2(acc[i][0], lo0, hi0);
        unpack2(acc[i][1], lo1, hi1);
        unpack2(acc[i][2], lo2, hi2);
        unpack2(acc[i][3], lo3, hi3);
        int r0 = m0 + ty * 8 + 2 * i;
        float y0 = lo0 + bv.x, y1 = lo1 + bv.y, y2 = lo2 + bv.z, y3 = lo3 + bv.w;
        float z0 = hi0 + bv.x, z1 = hi1 + bv.y, z2 = hi2 + bv.z, z3 = hi3 + bv.w;
        if (r0 < NN) {
            *(float4*)&C[(size_t)r0 * C1 + bcol + tx * 4] = make_float4(y0, y1, y2, y3);
            psum[0] += y0; psum[1] += y1; psum[2] += y2; psum[3] += y3;
            psq[0] += y0 * y0; psq[1] += y1 * y1; psq[2] += y2 * y2; psq[3] += y3 * y3;
        }
        if (r0 + 1 < NN) {
            *(float4*)&C[(size_t)(r0 + 1) * C1 + bcol + tx * 4] = make_float4(z0, z1, z2, z3);
            psum[0] += z0; psum[1] += z1; psum[2] += z2; psum[3] += z3;
            psq[0] += z0 * z0; psq[1] += z1 * z1; psq[2] += z2 * z2; psq[3] += z3 * z3;
        }
    }
#pragma unroll
    for (int c = 0; c < 4; c++) {
        reds[ty][tx * 4 + c] = psum[c];
        redq[ty][tx * 4 + c] = psq[c];
    }
    __syncthreads();
    if (tid < 64) {
        float s = 0.f, q = 0.f;
#pragma unroll
        for (int i = 0; i < 16; i++) { s += reds[i][tid]; q += redq[i][tid]; }
        atomicAdd(&d_colsum1[bcol + tid], s);
        atomicAdd(&d_colsq1[bcol + tid], q);
    }
}

// ------------------- GEMM2: xs2 = BNReLU(out1) @ W2, fused logits2 ------------------
__global__ void __launch_bounds__(256) gemm2_fused(
    const float* __restrict__ A, const float* __restrict__ B,
    float* __restrict__ C, const float* __restrict__ g1bn,
    const float* __restrict__ b1bn, const float* __restrict__ as2,
    const float* __restrict__ ad2) {
    const int BK = 16;
    __shared__ __align__(16) float As[BK][128 + 4];
    __shared__ __align__(16) float Bs[BK][64];
    __shared__ float sc[C1];
    __shared__ float sf[C1];
    int tid = threadIdx.x;
    int tx = tid & 15, ty = tid >> 4;
    int m0 = blockIdx.y * 128;

    {
        float mu = d_colsum1[tid] / (float)NN;
        float var = d_colsq1[tid] / (float)NN - mu * mu;
        float rs = rsqrtf(var + EPS) * g1bn[tid];
        sc[tid] = rs;
        sf[tid] = b1bn[tid] - mu * rs;
    }
    __syncthreads();

    ull acc[4][4];
#pragma unroll
    for (int i = 0; i < 4; i++)
#pragma unroll
        for (int j = 0; j < 4; j++) acc[i][j] = 0ull;

    int ar = tid >> 1;
    int akb = (tid & 1) * 8;
    int gr_a = m0 + ar;
    int br = tid >> 4;
    int bc = (tid & 15) * 4;

    for (int k0 = 0; k0 < C1; k0 += BK) {
        float4 a4a, a4b;
        if (gr_a < NN) {
            a4a = *(const float4*)&A[(size_t)gr_a * C1 + k0 + akb];
            a4b = *(const float4*)&A[(size_t)gr_a * C1 + k0 + akb + 4];
        } else {
            a4a = make_float4(0.f, 0.f, 0.f, 0.f);
            a4b = a4a;
        }
        int kb = k0 + akb;
        As[akb + 0][ar] = fmaxf(fmaf(a4a.x, sc[kb + 0], sf[kb + 0]), 0.f);
        As[akb + 1][ar] = fmaxf(fmaf(a4a.y, sc[kb + 1], sf[kb + 1]), 0.f);
        As[akb + 2][ar] = fmaxf(fmaf(a4a.z, sc[kb + 2], sf[kb + 2]), 0.f);
        As[akb + 3][ar] = fmaxf(fmaf(a4a.w, sc[kb + 3], sf[kb + 3]), 0.f);
        As[akb + 4][ar] = fmaxf(fmaf(a4b.x, sc[kb + 4], sf[kb + 4]), 0.f);
        As[akb + 5][ar] = fmaxf(fmaf(a4b.y, sc[kb + 5], sf[kb + 5]), 0.f);
        As[akb + 6][ar] = fmaxf(fmaf(a4b.z, sc[kb + 6], sf[kb + 6]), 0.f);
        As[akb + 7][ar] = fmaxf(fmaf(a4b.w, sc[kb + 7], sf[kb + 7]), 0.f);
        *(float4*)&Bs[br][bc] = *(const float4*)&B[(size_t)(k0 + br) * HID + bc];
        __syncthreads();
#pragma unroll
        for (int kk = 0; kk < BK; kk++) {
            ulonglong2 ap01 = *(const ulonglong2*)&As[kk][ty * 8];
            ulonglong2 ap23 = *(const ulonglong2*)&As[kk][ty * 8 + 4];
            float4 bq = *(const float4*)&Bs[kk][tx * 4];
            ull bb0 = pack2(bq.x, bq.x);
            ull bb1 = pack2(bq.y, bq.y);
            ull bb2 = pack2(bq.z, bq.z);
            ull bb3 = pack2(bq.w, bq.w);
            ull ap[4] = {ap01.x, ap01.y, ap23.x, ap23.y};
#pragma unroll
            for (int i = 0; i < 4; i++) {
                fma2(acc[i][0], ap[i], bb0);
                fma2(acc[i][1], ap[i], bb1);
                fma2(acc[i][2], ap[i], bb2);
                fma2(acc[i][3], ap[i], bb3);
            }
        }
        __syncthreads();
    }
    float4 av = *(const float4*)&as2[tx * 4];
    float4 dv = *(const float4*)&ad2[tx * 4];
    float ps8[8], pd8[8];
#pragma unroll
    for (int i = 0; i < 4; i++) {
        float lo0, hi0, lo1, hi1, lo2, hi2, lo3, hi3;
        unpack2(acc[i][0], lo0, hi0);
        unpack2(acc[i][1], lo1, hi1);
        unpack2(acc[i][2], lo2, hi2);
        unpack2(acc[i][3], lo3, hi3);
        int r0 = m0 + ty * 8 + 2 * i;
        if (r0 < NN)
            *(float4*)&C[(size_t)r0 * HID + tx * 4] = make_float4(lo0, lo1, lo2, lo3);
        if (r0 + 1 < NN)
            *(float4*)&C[(size_t)(r0 + 1) * HID + tx * 4] = make_float4(hi0, hi1, hi2, hi3);
        ps8[2 * i]     = lo0 * av.x + lo1 * av.y + lo2 * av.z + lo3 * av.w;
        ps8[2 * i + 1] = hi0 * av.x + hi1 * av.y + hi2 * av.z + hi3 * av.w;
        pd8[2 * i]     = lo0 * dv.x + lo1 * dv.y + lo2 * dv.z + lo3 * dv.w;
        pd8[2 * i + 1] = hi0 * dv.x + hi1 * dv.y + hi2 * dv.z + hi3 * dv.w;
    }
    float* red = &As[0][0];
    __syncthreads();
#pragma unroll
    for (int i = 0; i < 8; i++) red[(ty * 8 + i) * 16 + tx] = ps8[i];
    __syncthreads();
    if (tid < 128 && m0 + tid < NN) {
        float s = 0.f;
#pragma unroll
        for (int j = 0; j < 16; j++) s += red[tid * 16 + j];
        d_als2[m0 + tid] = s;
    }
    __syncthreads();
#pragma unroll
    for (int i = 0; i < 8; i++) red[(ty * 8 + i) * 16 + tx] = pd8[i];
    __syncthreads();
    if (tid < 128 && m0 + tid < NN) {
        float s = 0.f;
#pragma unroll
        for (int j = 0; j < 16; j++) s += red[tid * 16 + j];
        d_ald2[m0 + tid] = s;
    }
}

// ------- gather layer2: warp per node, 2x unrolled, fused BN2 stats ------------------
__global__ void __launch_bounds__(256) gather2w(const float* __restrict__ bias) {
    int wid = threadIdx.x >> 5, lane = threadIdx.x & 31;
    int d = blockIdx.x * 8 + wid;   // NN % 8 == 0, all warps active
    int r0 = d_rowptr[d], r1 = d_rowptr[d + 1];
    int LR = r1 - 1 - r0;
    __shared__ float sex[8][32];
    __shared__ int ssrc[8][32];
    __shared__ float s2v[8][64];
    float ald = d_ald2[d];
    float inv = 1.0f / (float)(LR > 1 ? LR : 1);
    float es = __expf(lrelu(d_als2[d] + ald + d_ec2sum[d] * inv));

    float2 acc = make_float2(0.f, 0.f);
    float lsum = 0.f;
    const float2* x2 = (const float2*)d_xs2;
    for (int c0 = r0; c0 < r0 + LR; c0 += 32) {
        int m = min(32, r0 + LR - c0);
        __syncwarp();
        if (lane < m) {
            float4 m2 = d_edge[(size_t)(c0 + lane) * 2 + 1];
            int s = __float_as_int(m2.x);
            float e = __expf(lrelu(d_als2[s] + ald + m2.y));
            sex[wid][lane] = e;
            ssrc[wid][lane] = s;
            lsum += e;
        }
        __syncwarp();
        int j = 0;
        for (; j + 2 <= m; j += 2) {
            float2 xv0 = x2[(size_t)ssrc[wid][j] * 32 + lane];
            float2 xv1 = x2[(size_t)ssrc[wid][j + 1] * 32 + lane];
            float e0 = sex[wid][j];
            float e1 = sex[wid][j + 1];
            acc.x += e0 * xv0.x; acc.y += e0 * xv0.y;
            acc.x += e1 * xv1.x; acc.y += e1 * xv1.y;
        }
        if (j < m) {
            float2 xv = x2[(size_t)ssrc[wid][j] * 32 + lane];
            float e = sex[wid][j];
            acc.x += e * xv.x;
            acc.y += e * xv.y;
        }
    }
    {
        float2 xv = x2[(size_t)d * 32 + lane];
        acc.x += es * xv.x;
        acc.y += es * xv.y;
    }
#pragma unroll
    for (int off = 16; off >= 1; off >>= 1)
        lsum += __shfl_xor_sync(0xFFFFFFFFu, lsum, off);
    lsum += es;
    float sinv = 1.0f / lsum;
    float2 bv = ((const float2*)bias)[lane];
    float y0 = acc.x * sinv + bv.x;
    float y1 = acc.y * sinv + bv.y;
    ((float2*)d_out2)[(size_t)d * 32 + lane] = make_float2(y0, y1);
    // fused BN2 stats
    s2v[wid][lane * 2]     = y0;
    s2v[wid][lane * 2 + 1] = y1;
    __syncthreads();
    int t = threadIdx.x;
    if (t < 64) {
        float s = 0.f, q = 0.f;
#pragma unroll
        for (int r = 0; r < 8; r++) {
            float v = s2v[r][t];
            s += v;
            q += v * v;
        }
        atomicAdd(&d_colsum2[t], s);
        atomicAdd(&d_colsq2[t], q);
    }
}

// ------------------- gate (applies BN2+ReLU in place) ---------------------------------
__global__ void gate_bn(const float* __restrict__ g2, const float* __restrict__ b2,
                        const float* __restrict__ Wg, const float* __restrict__ bg) {
    int n = (blockIdx.x * blockDim.x + threadIdx.x) >> 5;
    int lane = threadIdx.x & 31;
    if (n >= NN) return;
    int c0 = lane * 2, c1 = c0 + 1;
    float2 v = ((const float2*)d_out2)[(size_t)n * 32 + lane];
    float mu0 = d_colsum2[c0] / (float)NN;
    float var0 = d_colsq2[c0] / (float)NN - mu0 * mu0;
    float y0 = fmaxf((v.x - mu0) * rsqrtf(var0 + EPS) * __ldg(g2 + c0) + __ldg(b2 + c0), 0.f);
    float mu1 = d_colsum2[c1] / (float)NN;
    float var1 = d_colsq2[c1] / (float)NN - mu1 * mu1;
    float y1 = fmaxf((v.y - mu1) * rsqrtf(var1 + EPS) * __ldg(g2 + c1) + __ldg(b2 + c1), 0.f);
    ((float2*)d_out2)[(size_t)n * 32 + lane] = make_float2(y0, y1);
    float g = y0 * __ldg(Wg + c0) + y1 * __ldg(Wg + c1);
#pragma unroll
    for (int off = 16; off >= 1; off >>= 1)
        g += __shfl_xor_sync(0xFFFFFFFFu, g, off);
    if (lane == 0) d_gate[n] = g + bg[0];
}

// ------------------- pooling (256 threads; unshifted softmax) ---------------------------
__device__ __forceinline__ int lbound(const int* a, int n, int v) {
    int lo = 0, hi = n;
    while (lo < hi) {
        int mid = (lo + hi) >> 1;
        if (a[mid] < v) lo = mid + 1; else hi = mid;
    }
    return lo;
}

__global__ void __launch_bounds__(256) pool_kernel(const int* __restrict__ batch,
                                                   float* __restrict__ out) {
    int b = blockIdx.x, t = threadIdx.x;
    int c = t & 63, sub = t >> 6;
    __shared__ int slo, shi;
    __shared__ float red[256];
    __shared__ float sh_w[64];
    __shared__ float facc[4][64];
    if (t == 0) { slo = lbound(batch, NN, b); shi = lbound(batch, NN, b + 1); }
    __syncthreads();
    int lo = slo, hi = shi;
    if (hi <= lo) { if (t < 64) out[b * 64 + c] = 0.f; return; }
    float ts = 0.f;
    for (int n = lo + t; n < hi; n += 256) ts += __expf(d_gate[n]);
    red[t] = ts;
    __syncthreads();
#pragma unroll
    for (int off = 128; off >= 1; off >>= 1) {
        if (t < off) red[t] += red[t + off];
        __syncthreads();
    }
    float sinv = 1.0f / red[0];
    float acc = 0.f;
    for (int base = lo; base < hi; base += 64) {
        int mcnt = min(64, hi - base);
        __syncthreads();
        if (t < mcnt) sh_w[t] = __expf(d_gate[base + t]);
        __syncthreads();
        for (int j = sub; j < mcnt; j += 4)
            acc += sh_w[j] * d_out2[(size_t)(base + j) * 64 + c];
    }
    facc[sub][c] = acc;
    __syncthreads();
    if (t < 64) {
        float v = facc[0][t] + facc[1][t] + facc[2][t] + facc[3][t];
        out[b * 64 + t] = v * sinv;
    }
}

// ------------------- launch ----------------------------------------------------------------
static inline int gdiv(long long a, int b) { return (int)((a + b - 1) / b); }

extern "C" void kernel_launch(void* const* d_in, const int* in_sizes, int n_in,
                              void* d_out, int out_size) {
    const float* x     = (const float*)d_in[0];
    const float* ea    = (const float*)d_in[1];
    const int*   ei    = (const int*)d_in[2];
    const int*   batch = (const int*)d_in[3];
    const float* W1    = (const float*)d_in[4];
    const float* We1   = (const float*)d_in[5];
    const float* as1   = (const float*)d_in[6];
    const float* ad1   = (const float*)d_in[7];
    const float* ae1   = (const float*)d_in[8];
    const float* b1    = (const float*)d_in[9];
    const float* g1    = (const float*)d_in[10];
    const float* bb1   = (const float*)d_in[11];
    const float* W2    = (const float*)d_in[12];
    const float* We2   = (const float*)d_in[13];
    const float* as2   = (const float*)d_in[14];
    const float* ad2   = (const float*)d_in[15];
    const float* ae2   = (const float*)d_in[16];
    const float* b2    = (const float*)d_in[17];
    const float* g2    = (const float*)d_in[18];
    const float* bb2   = (const float*)d_in[19];
    const float* Wg    = (const float*)d_in[20];
    const float* bg    = (const float*)d_in[21];
    float* out = (float*)d_out;

    const int* src = ei;
    const int* dst = ei + EE;

    float* p_tmp;  cudaGetSymbolAddress((void**)&p_tmp, d_tmp);
    float* p_out1; cudaGetSymbolAddress((void**)&p_out1, d_out1);
    float* p_xs2;  cudaGetSymbolAddress((void**)&p_xs2, d_xs2);

    init_prep<<<84 + gdiv(NN * 4, 256), 256>>>(W1, as1, ad1, We1, ae1, We2, ae2);
    hist_logits<<<HBLK + gdiv(NN, 8), 256>>>(dst, x);
    scan_kernel<<<1, 1024>>>();
    edge_alpha1<<<gdiv(EE, 256), 256>>>(ea, src, dst);
    gather1w<<<gdiv(NN, 8), 256>>>(x);
    {
        dim3 g(4, gdiv(NN, 128));
        gemm1_stats<<<g, 256>>>(p_tmp, W1, p_out1, b1);
    }
    {
        dim3 g(1, gdiv(NN, 128));
        gemm2_fused<<<g, 256>>>(p_out1, W2, p_xs2, g1, bb1, as2, ad2);
    }
    gather2w<<<gdiv(NN, 8), 256>>>(b2);
    gate_bn<<<gdiv((long long)NN * 32, 256), 256>>>(g2, bb2, Wg, bg);
    pool_kernel<<<BB, 256>>>(batch, out);
}

// round 17
// speedup vs baseline: 1.2942x; 1.0311x over previous
#include <cuda_runtime.h>
#include <math_constants.h>

#define NN 30000
#define EE 480000
#define ET (EE + NN)
#define BB 64
#define FIN 128
#define HID 64
#define ED 32
#define C1 256
#define NEG 0.2f
#define EPS 1e-5f

typedef unsigned long long ull;

// ------------------- scratch -------------------------------------------------
__device__ int      d_deg[NN];
__device__ int      d_rowptr[NN + 1];
__device__ int      d_cursor[NN];
// per-edge record: [2p] = exp'd alpha (4 heads); [2p+1] = (src_bits, ec2, 0, 0)
__device__ float4   d_edge[(size_t)ET * 2];

__device__ float    d_vs1[512];
__device__ float    d_vd1[512];
__device__ float    d_c1[ED * 4];
__device__ float    d_c2[ED];
__device__ float    d_als1[NN * 4];
__device__ float    d_ald1[NN * 4];
__device__ float    d_ecsum[NN * 4];
__device__ float    d_ec2sum[NN];
__device__ float    d_tmp[(size_t)NN * 512];
__device__ float    d_out1[(size_t)NN * C1];
__device__ float    d_colsum1[C1];
__device__ float    d_colsq1[C1];
__device__ float    d_xs2[(size_t)NN * HID];
__device__ float    d_als2[NN];
__device__ float    d_ald2[NN];
__device__ float    d_out2[(size_t)NN * HID];
__device__ float    d_colsum2[HID];
__device__ float    d_colsq2[HID];
__device__ float    d_gate[NN];

// ------------------- helpers -------------------------------------------------
__device__ __forceinline__ ull pack2(float lo, float hi) {
    ull r;
    asm("mov.b64 %0, {%1, %2};" : "=l"(r) : "f"(lo), "f"(hi));
    return r;
}
__device__ __forceinline__ void unpack2(ull v, float& lo, float& hi) {
    asm("mov.b64 {%0, %1}, %2;" : "=f"(lo), "=f"(hi) : "l"(v));
}
__device__ __forceinline__ void fma2(ull& acc, ull a, ull b) {
    asm("fma.rn.f32x2 %0, %1, %2, %0;" : "+l"(acc) : "l"(a), "l"(b));
}
__device__ __forceinline__ float lrelu(float a) { return a > 0.f ? a : NEG * a; }
__device__ __forceinline__ void red_add_v4(float* addr, float a, float b, float c, float d) {
    asm volatile("red.global.add.v4.f32 [%0], {%1, %2, %3, %4};"
                 :: "l"(addr), "f"(a), "f"(b), "f"(c), "f"(d) : "memory");
}

// ---------- merged: init (blocks >= 84) + prep small vectors (blocks < 84) ---------
__global__ void __launch_bounds__(256) init_prep(
    const float* __restrict__ W1, const float* __restrict__ as1,
    const float* __restrict__ ad1,
    const float* __restrict__ We1, const float* __restrict__ ae1,
    const float* __restrict__ We2, const float* __restrict__ ae2) {
    if (blockIdx.x >= 84) {
        int i = (blockIdx.x - 84) * 256 + threadIdx.x;
        if (i < NN * 4) d_ecsum[i] = 0.f;
        if (i < NN) { d_deg[i] = 0; d_cursor[i] = 0; d_ec2sum[i] = 0.f; }
        return;
    }
    int gw = blockIdx.x * 8 + (threadIdx.x >> 5);
    int lane = threadIdx.x & 31;
    if (gw < 512) {
        int h = gw >> 7, k = gw & 127;
        const float* wrow = W1 + (size_t)k * C1 + h * HID;
        const float* arow = as1 + h * HID;
        const float* drow = ad1 + h * HID;
        float w0 = wrow[lane], w1 = wrow[lane + 32];
        float s = w0 * arow[lane] + w1 * arow[lane + 32];
        float dv = w0 * drow[lane] + w1 * drow[lane + 32];
#pragma unroll
        for (int off = 16; off >= 1; off >>= 1) {
            s += __shfl_xor_sync(0xFFFFFFFFu, s, off);
            dv += __shfl_xor_sync(0xFFFFFFFFu, dv, off);
        }
        if (lane == 0) { d_vs1[gw] = s; d_vd1[gw] = dv; }
    } else if (gw < 640) {
        int idx = gw - 512;
        int k = idx >> 2, h = idx & 3;
        const float* wrow = We1 + (size_t)k * C1 + h * HID;
        const float* arow = ae1 + h * HID;
        float s = wrow[lane] * arow[lane] + wrow[lane + 32] * arow[lane + 32];
#pragma unroll
        for (int off = 16; off >= 1; off >>= 1)
            s += __shfl_xor_sync(0xFFFFFFFFu, s, off);
        if (lane == 0) d_c1[idx] = s;
    } else if (gw < 672) {
        int k = gw - 640;
        const float* wrow = We2 + (size_t)k * HID;
        float s = wrow[lane] * ae2[lane] + wrow[lane + 32] * ae2[lane + 32];
#pragma unroll
        for (int off = 16; off >= 1; off >>= 1)
            s += __shfl_xor_sync(0xFFFFFFFFu, s, off);
        if (lane == 0) d_c2[k] = s;
    }
}

// ---------- merged: degree histogram (first HB blocks) + node logits1 -----------------
#define HBLK ((EE + 255) / 256)
__global__ void __launch_bounds__(256) hist_logits(const int* __restrict__ dst,
                                                   const float* __restrict__ x) {
    if (blockIdx.x < HBLK) {
        int e = blockIdx.x * 256 + threadIdx.x;
        if (e < EE) atomicAdd(&d_deg[dst[e]], 1);
        return;
    }
    int gw = (blockIdx.x - HBLK) * 8 + (threadIdx.x >> 5);
    int lane = threadIdx.x & 31;
    if (gw >= NN) return;
    float4 xv = ((const float4*)x)[(size_t)gw * 32 + lane];
    float r0, r1, r2, r3, q0, q1, q2, q3;
    {
        float4 v;
        v = ((const float4*)d_vs1)[0 * 32 + lane]; r0 = xv.x*v.x + xv.y*v.y + xv.z*v.z + xv.w*v.w;
        v = ((const float4*)d_vs1)[1 * 32 + lane]; r1 = xv.x*v.x + xv.y*v.y + xv.z*v.z + xv.w*v.w;
        v = ((const float4*)d_vs1)[2 * 32 + lane]; r2 = xv.x*v.x + xv.y*v.y + xv.z*v.z + xv.w*v.w;
        v = ((const float4*)d_vs1)[3 * 32 + lane]; r3 = xv.x*v.x + xv.y*v.y + xv.z*v.z + xv.w*v.w;
        v = ((const float4*)d_vd1)[0 * 32 + lane]; q0 = xv.x*v.x + xv.y*v.y + xv.z*v.z + xv.w*v.w;
        v = ((const float4*)d_vd1)[1 * 32 + lane]; q1 = xv.x*v.x + xv.y*v.y + xv.z*v.z + xv.w*v.w;
        v = ((const float4*)d_vd1)[2 * 32 + lane]; q2 = xv.x*v.x + xv.y*v.y + xv.z*v.z + xv.w*v.w;
        v = ((const float4*)d_vd1)[3 * 32 + lane]; q3 = xv.x*v.x + xv.y*v.y + xv.z*v.z + xv.w*v.w;
    }
#pragma unroll
    for (int off = 16; off >= 1; off >>= 1) {
        r0 += __shfl_xor_sync(0xFFFFFFFFu, r0, off);
        r1 += __shfl_xor_sync(0xFFFFFFFFu, r1, off);
        r2 += __shfl_xor_sync(0xFFFFFFFFu, r2, off);
        r3 += __shfl_xor_sync(0xFFFFFFFFu, r3, off);
        q0 += __shfl_xor_sync(0xFFFFFFFFu, q0, off);
        q1 += __shfl_xor_sync(0xFFFFFFFFu, q1, off);
        q2 += __shfl_xor_sync(0xFFFFFFFFu, q2, off);
        q3 += __shfl_xor_sync(0xFFFFFFFFu, q3, off);
    }
    if (lane == 0) {
        d_als1[gw * 4 + 0] = r0; d_als1[gw * 4 + 1] = r1;
        d_als1[gw * 4 + 2] = r2; d_als1[gw * 4 + 3] = r3;
        d_ald1[gw * 4 + 0] = q0; d_ald1[gw * 4 + 1] = q1;
        d_ald1[gw * 4 + 2] = q2; d_ald1[gw * 4 + 3] = q3;
    }
}

// ------------------- rowptr scan ---------------------------------------------------
__global__ void scan_kernel() {
    __shared__ int wsum[32];
    const int PER = 30;
    int t = threadIdx.x;
    if (t < C1) { d_colsum1[t] = 0.f; d_colsq1[t] = 0.f; }
    if (t < HID) { d_colsum2[t] = 0.f; d_colsq2[t] = 0.f; }
    int base = t * PER;
    int vals[PER];
    int s = 0;
#pragma unroll
    for (int i = 0; i < PER; i++) {
        int idx = base + i;
        vals[i] = (idx < NN) ? (d_deg[idx] + 1) : 0;   // +1 self loop (last slot)
        s += vals[i];
    }
    int lane = t & 31, w = t >> 5;
    int x = s;
#pragma unroll
    for (int off = 1; off < 32; off <<= 1) {
        int y = __shfl_up_sync(0xFFFFFFFFu, x, off);
        if (lane >= off) x += y;
    }
    if (lane == 31) wsum[w] = x;
    __syncthreads();
    if (w == 0) {
        int y = wsum[lane];
#pragma unroll
        for (int off = 1; off < 32; off <<= 1) {
            int z = __shfl_up_sync(0xFFFFFFFFu, y, off);
            if (lane >= off) y += z;
        }
        wsum[lane] = y;
    }
    __syncthreads();
    int excl = x - s + (w > 0 ? wsum[w - 1] : 0);
    int run = excl;
#pragma unroll
    for (int i = 0; i < PER; i++) {
        int idx = base + i;
        if (idx < NN) d_rowptr[idx] = run;
        run += vals[i];
    }
    if (t == 0) d_rowptr[NN] = ET;
}

// --------- edge alphas: vector logit loads + vector red + packed record --------------
__global__ void edge_alpha1(const float* __restrict__ ea, const int* __restrict__ src,
                            const int* __restrict__ dst) {
    int e = blockIdx.x * blockDim.x + threadIdx.x;
    if (e >= EE) return;
    int s = src[e], d = dst[e];
    const float4* row = (const float4*)(ea + (size_t)e * ED);
    float ec0 = 0.f, ec1 = 0.f, ec2 = 0.f, ec3 = 0.f, e2 = 0.f;
#pragma unroll
    for (int q = 0; q < 8; q++) {
        float4 v = __ldg(row + q);
        int k = q * 4;
        ec0 += v.x * d_c1[(k+0)*4+0] + v.y * d_c1[(k+1)*4+0] + v.z * d_c1[(k+2)*4+0] + v.w * d_c1[(k+3)*4+0];
        ec1 += v.x * d_c1[(k+0)*4+1] + v.y * d_c1[(k+1)*4+1] + v.z * d_c1[(k+2)*4+1] + v.w * d_c1[(k+3)*4+1];
        ec2 += v.x * d_c1[(k+0)*4+2] + v.y * d_c1[(k+1)*4+2] + v.z * d_c1[(k+2)*4+2] + v.w * d_c1[(k+3)*4+2];
        ec3 += v.x * d_c1[(k+0)*4+3] + v.y * d_c1[(k+1)*4+3] + v.z * d_c1[(k+2)*4+3] + v.w * d_c1[(k+3)*4+3];
        e2  += v.x * d_c2[k+0] + v.y * d_c2[k+1] + v.z * d_c2[k+2] + v.w * d_c2[k+3];
    }
    int p = d_rowptr[d] + atomicAdd(&d_cursor[d], 1);
    float4 as = __ldg((const float4*)&d_als1[s * 4]);
    float4 ad = __ldg((const float4*)&d_ald1[d * 4]);
    float4 a;
    a.x = __expf(lrelu(as.x + ad.x + ec0));
    a.y = __expf(lrelu(as.y + ad.y + ec1));
    a.z = __expf(lrelu(as.z + ad.z + ec2));
    a.w = __expf(lrelu(as.w + ad.w + ec3));
    d_edge[(size_t)p * 2]     = a;
    d_edge[(size_t)p * 2 + 1] = make_float4(__int_as_float(s), e2, 0.f, 0.f);
    red_add_v4(&d_ecsum[d * 4], ec0, ec1, ec2, ec3);
    atomicAdd(&d_ec2sum[d], e2);
}

// --------- gather layer1: warp per node, 2x unrolled inner ---------------------------
__global__ void __launch_bounds__(256) gather1w(const float* __restrict__ x) {
    int wid = threadIdx.x >> 5, lane = threadIdx.x & 31;
    int d = blockIdx.x * 8 + wid;   // NN % 8 == 0
    int r0 = d_rowptr[d], r1 = d_rowptr[d + 1];
    int LR = r1 - 1 - r0;           // real edges; slot r1-1 is self
    __shared__ __align__(16) float4 sex[8][32];
    __shared__ int ssrc[8][32];

    float inv = 1.0f / (float)(LR > 1 ? LR : 1);
    float4 es;
    es.x = __expf(lrelu(d_als1[d * 4 + 0] + d_ald1[d * 4 + 0] + d_ecsum[d * 4 + 0] * inv));
    es.y = __expf(lrelu(d_als1[d * 4 + 1] + d_ald1[d * 4 + 1] + d_ecsum[d * 4 + 1] * inv));
    es.z = __expf(lrelu(d_als1[d * 4 + 2] + d_ald1[d * 4 + 2] + d_ecsum[d * 4 + 2] * inv));
    es.w = __expf(lrelu(d_als1[d * 4 + 3] + d_ald1[d * 4 + 3] + d_ecsum[d * 4 + 3] * inv));

    float4 a0 = make_float4(0, 0, 0, 0), a1 = a0, a2 = a0, a3 = a0;
    float4 lsum = make_float4(0, 0, 0, 0);
    const float4* x4 = (const float4*)x;
    for (int c0 = r0; c0 < r0 + LR; c0 += 32) {
        int m = min(32, r0 + LR - c0);
        __syncwarp();
        if (lane < m) {
            float4 e  = d_edge[(size_t)(c0 + lane) * 2];
            float4 m2 = d_edge[(size_t)(c0 + lane) * 2 + 1];
            sex[wid][lane] = e;
            ssrc[wid][lane] = __float_as_int(m2.x);
            lsum.x += e.x; lsum.y += e.y; lsum.z += e.z; lsum.w += e.w;
        }
        __syncwarp();
        int j = 0;
        for (; j + 2 <= m; j += 2) {
            float4 xv0 = x4[(size_t)ssrc[wid][j] * 32 + lane];
            float4 xv1 = x4[(size_t)ssrc[wid][j + 1] * 32 + lane];
            float4 e0 = sex[wid][j];
            float4 e1 = sex[wid][j + 1];
            a0.x += e0.x * xv0.x; a0.y += e0.x * xv0.y; a0.z += e0.x * xv0.z; a0.w += e0.x * xv0.w;
            a1.x += e0.y * xv0.x; a1.y += e0.y * xv0.y; a1.z += e0.y * xv0.z; a1.w += e0.y * xv0.w;
            a2.x += e0.z * xv0.x; a2.y += e0.z * xv0.y; a2.z += e0.z * xv0.z; a2.w += e0.z * xv0.w;
            a3.x += e0.w * xv0.x; a3.y += e0.w * xv0.y; a3.z += e0.w * xv0.z; a3.w += e0.w * xv0.w;
            a0.x += e1.x * xv1.x; a0.y += e1.x * xv1.y; a0.z += e1.x * xv1.z; a0.w += e1.x * xv1.w;
            a1.x += e1.y * xv1.x; a1.y += e1.y * xv1.y; a1.z += e1.y * xv1.z; a1.w += e1.y * xv1.w;
            a2.x += e1.z * xv1.x; a2.y += e1.z * xv1.y; a2.z += e1.z * xv1.z; a2.w += e1.z * xv1.w;
            a3.x += e1.w * xv1.x; a3.y += e1.w * xv1.y; a3.z += e1.w * xv1.z; a3.w += e1.w * xv1.w;
        }
        if (j < m) {
            float4 xv = x4[(size_t)ssrc[wid][j] * 32 + lane];
            float4 e = sex[wid][j];
            a0.x += e.x * xv.x; a0.y += e.x * xv.y; a0.z += e.x * xv.z; a0.w += e.x * xv.w;
            a1.x += e.y * xv.x; a1.y += e.y * xv.y; a1.z += e.y * xv.z; a1.w += e.y * xv.w;
            a2.x += e.z * xv.x; a2.y += e.z * xv.y; a2.z += e.z * xv.z; a2.w += e.z * xv.w;
            a3.x += e.w * xv.x; a3.y += e.w * xv.y; a3.z += e.w * xv.z; a3.w += e.w * xv.w;
        }
    }
    // self-loop contribution
    {
        float4 xv = x4[(size_t)d * 32 + lane];
        a0.x += es.x * xv.x; a0.y += es.x * xv.y; a0.z += es.x * xv.z; a0.w += es.x * xv.w;
        a1.x += es.y * xv.x; a1.y += es.y * xv.y; a1.z += es.y * xv.z; a1.w += es.y * xv.w;
        a2.x += es.z * xv.x; a2.y += es.z * xv.y; a2.z += es.z * xv.z; a2.w += es.z * xv.w;
        a3.x += es.w * xv.x; a3.y += es.w * xv.y; a3.z += es.w * xv.z; a3.w += es.w * xv.w;
    }
#pragma unroll
    for (int off = 16; off >= 1; off >>= 1) {
        lsum.x += __shfl_xor_sync(0xFFFFFFFFu, lsum.x, off);
        lsum.y += __shfl_xor_sync(0xFFFFFFFFu, lsum.y, off);
        lsum.z += __shfl_xor_sync(0xFFFFFFFFu, lsum.z, off);
        lsum.w += __shfl_xor_sync(0xFFFFFFFFu, lsum.w, off);
    }
    lsum.x += es.x; lsum.y += es.y; lsum.z += es.z; lsum.w += es.w;
    float i0 = 1.0f / lsum.x, i1 = 1.0f / lsum.y, i2 = 1.0f / lsum.z, i3 = 1.0f / lsum.w;
    float4* tmp4 = (float4*)&d_tmp[(size_t)d * 512];
    tmp4[0 * 32 + lane] = make_float4(a0.x * i0, a0.y * i0, a0.z * i0, a0.w * i0);
    tmp4[1 * 32 + lane] = make_float4(a1.x * i1, a1.y * i1, a1.z * i1, a1.w * i1);
    tmp4[2 * 32 + lane] = make_float4(a2.x * i2, a2.y * i2, a2.z * i2, a2.w * i2);
    tmp4[3 * 32 + lane] = make_float4(a3.x * i3, a3.y * i3, a3.z * i3, a3.w * i3);
}

// ------------------- GEMM1: out1 = tmp(heads) @ W1 + b1, fused BN stats -------------
__global__ void __launch_bounds__(256) gemm1_stats(
    const float* __restrict__ A, const float* __restrict__ B,
    float* __restrict__ C, const float* __restrict__ bias) {
    const int BK = 16;
    __shared__ __align__(16) float As[BK][128 + 4];
    __shared__ __align__(16) float Bs[BK][64];
    __shared__ float reds[16][64];
    __shared__ float redq[16][64];
    int tid = threadIdx.x;
    int tx = tid & 15, ty = tid >> 4;
    int m0 = blockIdx.y * 128;
    const float* Ab = A + (size_t)blockIdx.x * 128;
    int bcol = blockIdx.x * 64;

    ull acc[4][4];
#pragma unroll
    for (int i = 0; i < 4; i++)
#pragma unroll
        for (int j = 0; j < 4; j++) acc[i][j] = 0ull;

    int ar = tid >> 1;
    int akb = (tid & 1) * 8;
    int gr_a = m0 + ar;
    int br = tid >> 4;
    int bc = (tid & 15) * 4;

    for (int k0 = 0; k0 < FIN; k0 += BK) {
        float4 a4a, a4b;
        if (gr_a < NN) {
            a4a = *(const float4*)&Ab[(size_t)gr_a * 512 + k0 + akb];
            a4b = *(const float4*)&Ab[(size_t)gr_a * 512 + k0 + akb + 4];
        } else {
            a4a = make_float4(0.f, 0.f, 0.f, 0.f);
            a4b = a4a;
        }
        As[akb + 0][ar] = a4a.x; As[akb + 1][ar] = a4a.y;
        As[akb + 2][ar] = a4a.z; As[akb + 3][ar] = a4a.w;
        As[akb + 4][ar] = a4b.x; As[akb + 5][ar] = a4b.y;
        As[akb + 6][ar] = a4b.z; As[akb + 7][ar] = a4b.w;
        *(float4*)&Bs[br][bc] = *(const float4*)&B[(size_t)(k0 + br) * C1 + bcol + bc];
        __syncthreads();
#pragma unroll
        for (int kk = 0; kk < BK; kk++) {
            ulonglong2 ap01 = *(const ulonglong2*)&As[kk][ty * 8];
            ulonglong2 ap23 = *(const ulonglong2*)&As[kk][ty * 8 + 4];
            float4 bq = *(const float4*)&Bs[kk][tx * 4];
            ull bb0 = pack2(bq.x, bq.x);
            ull bb1 = pack2(bq.y, bq.y);
            ull bb2 = pack2(bq.z, bq.z);
            ull bb3 = pack2(bq.w, bq.w);
            ull ap[4] = {ap01.x, ap01.y, ap23.x, ap23.y};
#pragma unroll
            for (int i = 0; i < 4; i++) {
                fma2(acc[i][0], ap[i], bb0);
                fma2(acc[i][1], ap[i], bb1);
                fma2(acc[i][2], ap[i], bb2);
                fma2(acc[i][3], ap[i], bb3);
            }
        }
        __syncthreads();
    }
    float4 bv = *(const float4*)&bias[bcol + tx * 4];
    float psum[4] = {0.f, 0.f, 0.f, 0.f};
    float psq[4]  = {0.f, 0.f, 0.f, 0.f};
#pragma unroll
    for (int i = 0; i < 4; i++) {
        float lo0, hi0, lo1, hi1, lo2, hi2, lo3, hi3;
        unpack2(acc[i][0], lo0, hi0);
        unpack2(acc[i][1], lo1, hi1);
        unpack2(acc[i][2], lo2, hi2);
        unpack2(acc[i][3], lo3, hi3);
        int r0 = m0 + ty * 8 + 2 * i;
        float y0 = lo0 + bv.x, y1 = lo1 + bv.y, y2 = lo2 + bv.z, y3 = lo3 + bv.w;
        float z0 = hi0 + bv.x, z1 = hi1 + bv.y, z2 = hi2 + bv.z, z3 = hi3 + bv.w;
        if (r0 < NN) {
            *(float4*)&C[(size_t)r0 * C1 + bcol + tx * 4] = make_float4(y0, y1, y2, y3);
            psum[0] += y0; psum[1] += y1; psum[2] += y2; psum[3] += y3;
            psq[0] += y0 * y0; psq[1] += y1 * y1; psq[2] += y2 * y2; psq[3] += y3 * y3;
        }
        if (r0 + 1 < NN) {
            *(float4*)&C[(size_t)(r0 + 1) * C1 + bcol + tx * 4] = make_float4(z0, z1, z2, z3);
            psum[0] += z0; psum[1] += z1; psum[2] += z2; psum[3] += z3;
            psq[0] += z0 * z0; psq[1] += z1 * z1; psq[2] += z2 * z2; psq[3] += z3 * z3;
        }
    }
#pragma unroll
    for (int c = 0; c < 4; c++) {
        reds[ty][tx * 4 + c] = psum[c];
        redq[ty][tx * 4 + c] = psq[c];
    }
    __syncthreads();
    if (tid < 64) {
        float s = 0.f, q = 0.f;
#pragma unroll
        for (int i = 0; i < 16; i++) { s += reds[i][tid]; q += redq[i][tid]; }
        atomicAdd(&d_colsum1[bcol + tid], s);
        atomicAdd(&d_colsq1[bcol + tid], q);
    }
}

// ------------------- GEMM2: xs2 = BNReLU(out1) @ W2, fused logits2 ------------------
__global__ void __launch_bounds__(256) gemm2_fused(
    const float* __restrict__ A, const float* __restrict__ B,
    float* __restrict__ C, const float* __restrict__ g1bn,
    const float* __restrict__ b1bn, const float* __restrict__ as2,
    const float* __restrict__ ad2) {
    const int BK = 16;
    __shared__ __align__(16) float As[BK][128 + 4];
    __shared__ __align__(16) float Bs[BK][64];
    __shared__ float sc[C1];
    __shared__ float sf[C1];
    int tid = threadIdx.x;
    int tx = tid & 15, ty = tid >> 4;
    int m0 = blockIdx.y * 128;

    {
        float mu = d_colsum1[tid] / (float)NN;
        float var = d_colsq1[tid] / (float)NN - mu * mu;
        float rs = rsqrtf(var + EPS) * g1bn[tid];
        sc[tid] = rs;
        sf[tid] = b1bn[tid] - mu * rs;
    }
    __syncthreads();

    ull acc[4][4];
#pragma unroll
    for (int i = 0; i < 4; i++)
#pragma unroll
        for (int j = 0; j < 4; j++) acc[i][j] = 0ull;

    int ar = tid >> 1;
    int akb = (tid & 1) * 8;
    int gr_a = m0 + ar;
    int br = tid >> 4;
    int bc = (tid & 15) * 4;

    for (int k0 = 0; k0 < C1; k0 += BK) {
        float4 a4a, a4b;
        if (gr_a < NN) {
            a4a = *(const float4*)&A[(size_t)gr_a * C1 + k0 + akb];
            a4b = *(const float4*)&A[(size_t)gr_a * C1 + k0 + akb + 4];
        } else {
            a4a = make_float4(0.f, 0.f, 0.f, 0.f);
            a4b = a4a;
        }
        int kb = k0 + akb;
        As[akb + 0][ar] = fmaxf(fmaf(a4a.x, sc[kb + 0], sf[kb + 0]), 0.f);
        As[akb + 1][ar] = fmaxf(fmaf(a4a.y, sc[kb + 1], sf[kb + 1]), 0.f);
        As[akb + 2][ar] = fmaxf(fmaf(a4a.z, sc[kb + 2], sf[kb + 2]), 0.f);
        As[akb + 3][ar] = fmaxf(fmaf(a4a.w, sc[kb + 3], sf[kb + 3]), 0.f);
        As[akb + 4][ar] = fmaxf(fmaf(a4b.x, sc[kb + 4], sf[kb + 4]), 0.f);
        As[akb + 5][ar] = fmaxf(fmaf(a4b.y, sc[kb + 5], sf[kb + 5]), 0.f);
        As[akb + 6][ar] = fmaxf(fmaf(a4b.z, sc[kb + 6], sf[kb + 6]), 0.f);
        As[akb + 7][ar] = fmaxf(fmaf(a4b.w, sc[kb + 7], sf[kb + 7]), 0.f);
        *(float4*)&Bs[br][bc] = *(const float4*)&B[(size_t)(k0 + br) * HID + bc];
        __syncthreads();
#pragma unroll
        for (int kk = 0; kk < BK; kk++) {
            ulonglong2 ap01 = *(const ulonglong2*)&As[kk][ty * 8];
            ulonglong2 ap23 = *(const ulonglong2*)&As[kk][ty * 8 + 4];
            float4 bq = *(const float4*)&Bs[kk][tx * 4];
            ull bb0 = pack2(bq.x, bq.x);
            ull bb1 = pack2(bq.y, bq.y);
            ull bb2 = pack2(bq.z, bq.z);
            ull bb3 = pack2(bq.w, bq.w);
            ull ap[4] = {ap01.x, ap01.y, ap23.x, ap23.y};
#pragma unroll
            for (int i = 0; i < 4; i++) {
                fma2(acc[i][0], ap[i], bb0);
                fma2(acc[i][1], ap[i], bb1);
                fma2(acc[i][2], ap[i], bb2);
                fma2(acc[i][3], ap[i], bb3);
            }
        }
        __syncthreads();
    }
    float4 av = *(const float4*)&as2[tx * 4];
    float4 dv = *(const float4*)&ad2[tx * 4];
    float ps8[8], pd8[8];
#pragma unroll
    for (int i = 0; i < 4; i++) {
        float lo0, hi0, lo1, hi1, lo2, hi2, lo3, hi3;
        unpack2(acc[i][0], lo0, hi0);
        unpack2(acc[i][1], lo1, hi1);
        unpack2(acc[i][2], lo2, hi2);
        unpack2(acc[i][3], lo3, hi3);
        int r0 = m0 + ty * 8 + 2 * i;
        if (r0 < NN)
            *(float4*)&C[(size_t)r0 * HID + tx * 4] = make_float4(lo0, lo1, lo2, lo3);
        if (r0 + 1 < NN)
            *(float4*)&C[(size_t)(r0 + 1) * HID + tx * 4] = make_float4(hi0, hi1, hi2, hi3);
        ps8[2 * i]     = lo0 * av.x + lo1 * av.y + lo2 * av.z + lo3 * av.w;
        ps8[2 * i + 1] = hi0 * av.x + hi1 * av.y + hi2 * av.z + hi3 * av.w;
        pd8[2 * i]     = lo0 * dv.x + lo1 * dv.y + lo2 * dv.z + lo3 * dv.w;
        pd8[2 * i + 1] = hi0 * dv.x + hi1 * dv.y + hi2 * dv.z + hi3 * dv.w;
    }
    float* red = &As[0][0];
    __syncthreads();
#pragma unroll
    for (int i = 0; i < 8; i++) red[(ty * 8 + i) * 16 + tx] = ps8[i];
    __syncthreads();
    if (tid < 128 && m0 + tid < NN) {
        float s = 0.f;
#pragma unroll
        for (int j = 0; j < 16; j++) s += red[tid * 16 + j];
        d_als2[m0 + tid] = s;
    }
    __syncthreads();
#pragma unroll
    for (int i = 0; i < 8; i++) red[(ty * 8 + i) * 16 + tx] = pd8[i];
    __syncthreads();
    if (tid < 128 && m0 + tid < NN) {
        float s = 0.f;
#pragma unroll
        for (int j = 0; j < 16; j++) s += red[tid * 16 + j];
        d_ald2[m0 + tid] = s;
    }
}

// ------- gather layer2: warp per node, 2x unrolled, fused BN2 stats ------------------
__global__ void __launch_bounds__(256) gather2w(const float* __restrict__ bias) {
    int wid = threadIdx.x >> 5, lane = threadIdx.x & 31;
    int d = blockIdx.x * 8 + wid;   // NN % 8 == 0, all warps active
    int r0 = d_rowptr[d], r1 = d_rowptr[d + 1];
    int LR = r1 - 1 - r0;
    __shared__ float sex[8][32];
    __shared__ int ssrc[8][32];
    __shared__ float s2v[8][64];
    float ald = d_ald2[d];
    float inv = 1.0f / (float)(LR > 1 ? LR : 1);
    float es = __expf(lrelu(d_als2[d] + ald + d_ec2sum[d] * inv));

    float2 acc = make_float2(0.f, 0.f);
    float lsum = 0.f;
    const float2* x2 = (const float2*)d_xs2;
    for (int c0 = r0; c0 < r0 + LR; c0 += 32) {
        int m = min(32, r0 + LR - c0);
        __syncwarp();
        if (lane < m) {
            float4 m2 = d_edge[(size_t)(c0 + lane) * 2 + 1];
            int s = __float_as_int(m2.x);
            float e = __expf(lrelu(d_als2[s] + ald + m2.y));
            sex[wid][lane] = e;
            ssrc[wid][lane] = s;
            lsum += e;
        }
        __syncwarp();
        int j = 0;
        for (; j + 2 <= m; j += 2) {
            float2 xv0 = x2[(size_t)ssrc[wid][j] * 32 + lane];
            float2 xv1 = x2[(size_t)ssrc[wid][j + 1] * 32 + lane];
            float e0 = sex[wid][j];
            float e1 = sex[wid][j + 1];
            acc.x += e0 * xv0.x; acc.y += e0 * xv0.y;
            acc.x += e1 * xv1.x; acc.y += e1 * xv1.y;
        }
        if (j < m) {
            float2 xv = x2[(size_t)ssrc[wid][j] * 32 + lane];
            float e = sex[wid][j];
            acc.x += e * xv.x;
            acc.y += e * xv.y;
        }
    }
    {
        float2 xv = x2[(size_t)d * 32 + lane];
        acc.x += es * xv.x;
        acc.y += es * xv.y;
    }
#pragma unroll
    for (int off = 16; off >= 1; off >>= 1)
        lsum += __shfl_xor_sync(0xFFFFFFFFu, lsum, off);
    lsum += es;
    float sinv = 1.0f / lsum;
    float2 bv = ((const float2*)bias)[lane];
    float y0 = acc.x * sinv + bv.x;
    float y1 = acc.y * sinv + bv.y;
    ((float2*)d_out2)[(size_t)d * 32 + lane] = make_float2(y0, y1);
    // fused BN2 stats
    s2v[wid][lane * 2]     = y0;
    s2v[wid][lane * 2 + 1] = y1;
    __syncthreads();
    int t = threadIdx.x;
    if (t < 64) {
        float s = 0.f, q = 0.f;
#pragma unroll
        for (int r = 0; r < 8; r++) {
            float v = s2v[r][t];
            s += v;
            q += v * v;
        }
        atomicAdd(&d_colsum2[t], s);
        atomicAdd(&d_colsq2[t], q);
    }
}

// ------------------- gate (applies BN2+ReLU in place) ---------------------------------
__global__ void gate_bn(const float* __restrict__ g2, const float* __restrict__ b2,
                        const float* __restrict__ Wg, const float* __restrict__ bg) {
    int n = (blockIdx.x * blockDim.x + threadIdx.x) >> 5;
    int lane = threadIdx.x & 31;
    if (n >= NN) return;
    int c0 = lane * 2, c1 = c0 + 1;
    float2 v = ((const float2*)d_out2)[(size_t)n * 32 + lane];
    float mu0 = d_colsum2[c0] / (float)NN;
    float var0 = d_colsq2[c0] / (float)NN - mu0 * mu0;
    float y0 = fmaxf((v.x - mu0) * rsqrtf(var0 + EPS) * __ldg(g2 + c0) + __ldg(b2 + c0), 0.f);
    float mu1 = d_colsum2[c1] / (float)NN;
    float var1 = d_colsq2[c1] / (float)NN - mu1 * mu1;
    float y1 = fmaxf((v.y - mu1) * rsqrtf(var1 + EPS) * __ldg(g2 + c1) + __ldg(b2 + c1), 0.f);
    ((float2*)d_out2)[(size_t)n * 32 + lane] = make_float2(y0, y1);
    float g = y0 * __ldg(Wg + c0) + y1 * __ldg(Wg + c1);
#pragma unroll
    for (int off = 16; off >= 1; off >>= 1)
        g += __shfl_xor_sync(0xFFFFFFFFu, g, off);
    if (lane == 0) d_gate[n] = g + bg[0];
}

// ------------------- pooling (256 threads; unshifted softmax) ---------------------------
__device__ __forceinline__ int lbound(const int* a, int n, int v) {
    int lo = 0, hi = n;
    while (lo < hi) {
        int mid = (lo + hi) >> 1;
        if (a[mid] < v) lo = mid + 1; else hi = mid;
    }
    return lo;
}

__global__ void __launch_bounds__(256) pool_kernel(const int* __restrict__ batch,
                                                   float* __restrict__ out) {
    int b = blockIdx.x, t = threadIdx.x;
    int c = t & 63, sub = t >> 6;
    __shared__ int slo, shi;
    __shared__ float red[256];
    __shared__ float sh_w[64];
    __shared__ float facc[4][64];
    if (t == 0) { slo = lbound(batch, NN, b); shi = lbound(batch, NN, b + 1); }
    __syncthreads();
    int lo = slo, hi = shi;
    if (hi <= lo) { if (t < 64) out[b * 64 + c] = 0.f; return; }
    float ts = 0.f;
    for (int n = lo + t; n < hi; n += 256) ts += __expf(d_gate[n]);
    red[t] = ts;
    __syncthreads();
#pragma unroll
    for (int off = 128; off >= 1; off >>= 1) {
        if (t < off) red[t] += red[t + off];
        __syncthreads();
    }
    float sinv = 1.0f / red[0];
    float acc = 0.f;
    for (int base = lo; base < hi; base += 64) {
        int mcnt = min(64, hi - base);
        __syncthreads();
        if (t < mcnt) sh_w[t] = __expf(d_gate[base + t]);
        __syncthreads();
        for (int j = sub; j < mcnt; j += 4)
            acc += sh_w[j] * d_out2[(size_t)(base + j) * 64 + c];
    }
    facc[sub][c] = acc;
    __syncthreads();
    if (t < 64) {
        float v = facc[0][t] + facc[1][t] + facc[2][t] + facc[3][t];
        out[b * 64 + t] = v * sinv;
    }
}

// ------------------- launch ----------------------------------------------------------------
static inline int gdiv(long long a, int b) { return (int)((a + b - 1) / b); }

extern "C" void kernel_launch(void* const* d_in, const int* in_sizes, int n_in,
                              void* d_out, int out_size) {
    const float* x     = (const float*)d_in[0];
    const float* ea    = (const float*)d_in[1];
    const int*   ei    = (const int*)d_in[2];
    const int*   batch = (const int*)d_in[3];
    const float* W1    = (const float*)d_in[4];
    const float* We1   = (const float*)d_in[5];
    const float* as1   = (const float*)d_in[6];
    const float* ad1   = (const float*)d_in[7];
    const float* ae1   = (const float*)d_in[8];
    const float* b1    = (const float*)d_in[9];
    const float* g1    = (const float*)d_in[10];
    const float* bb1   = (const float*)d_in[11];
    const float* W2    = (const float*)d_in[12];
    const float* We2   = (const float*)d_in[13];
    const float* as2   = (const float*)d_in[14];
    const float* ad2   = (const float*)d_in[15];
    const float* ae2   = (const float*)d_in[16];
    const float* b2    = (const float*)d_in[17];
    const float* g2    = (const float*)d_in[18];
    const float* bb2   = (const float*)d_in[19];
    const float* Wg    = (const float*)d_in[20];
    const float* bg    = (const float*)d_in[21];
    float* out = (float*)d_out;

    const int* src = ei;
    const int* dst = ei + EE;

    float* p_tmp;  cudaGetSymbolAddress((void**)&p_tmp, d_tmp);
    float* p_out1; cudaGetSymbolAddress((void**)&p_out1, d_out1);
    float* p_xs2;  cudaGetSymbolAddress((void**)&p_xs2, d_xs2);

    init_prep<<<84 + gdiv(NN * 4, 256), 256>>>(W1, as1, ad1, We1, ae1, We2, ae2);
    hist_logits<<<HBLK + gdiv(NN, 8), 256>>>(dst, x);
    scan_kernel<<<1, 1024>>>();
    edge_alpha1<<<gdiv(EE, 256), 256>>>(ea, src, dst);
    gather1w<<<gdiv(NN, 8), 256>>>(x);
    {
        dim3 g(4, gdiv(NN, 128));
        gemm1_stats<<<g, 256>>>(p_tmp, W1, p_out1, b1);
    }
    {
        dim3 g(1, gdiv(NN, 128));
        gemm2_fused<<<g, 256>>>(p_out1, W2, p_xs2, g1, bb1, as2, ad2);
    }
    gather2w<<<gdiv(NN, 8), 256>>>(b2);
    gate_bn<<<gdiv((long long)NN * 32, 256), 256>>>(g2, bb2, Wg, bg);
    pool_kernel<<<BB, 256>>>(batch, out);
}